// round 11
// baseline (speedup 1.0000x reference)
#include <cuda_runtime.h>
#include <cuda_bf16.h>
#include <cstdint>

#define NN 4096
#define CC 128
#define LL 4
#define HEADS 4
#define BN_EPS 1e-5f
#define EMAX 262144

// ---------------- scratch (static device globals; no allocation) ----------------
__device__ float g_x  [NN * CC];
__device__ float g_agg[NN * CC];
__device__ float g_ao [NN * CC];     // attention output (separate from agg!)
__device__ float g_t1 [NN * 384];
__device__ float g_t2 [NN * CC];
__device__ float g_h1 [NN * CC];
__device__ float g_h2 [NN * CC];
__device__ float g_bnsums[12 * 2 * CC];
__device__ int   g_deg[NN + 1];
__device__ int   g_cur[NN];
__device__ int   g_csr[EMAX];
__device__ __nv_bfloat16 g_qb [HEADS * NN * 32];
__device__ __nv_bfloat16 g_kb [HEADS * NN * 32];
__device__ __nv_bfloat16 g_vtb[HEADS * 32 * NN];

// concatenated hi/lo bf16 weights
#define WOFF_GIN1 0
#define WOFF_GIN2 65536
#define WOFF_AIN  131072
#define WOFF_AOUT 327680
#define WOFF_MW1  393216
#define WOFF_MW2  524288
#define WTOTAL    655360
__device__ __nv_bfloat16 g_whi[WTOTAL];
__device__ __nv_bfloat16 g_wlo[WTOTAL];

// ---------------- mma.sync helpers ----------------
__device__ __forceinline__ void mma_bf16(float* d, uint32_t a0, uint32_t a1, uint32_t a2,
                                         uint32_t a3, uint32_t b0, uint32_t b1) {
    asm volatile(
        "mma.sync.aligned.m16n8k16.row.col.f32.bf16.bf16.f32 "
        "{%0,%1,%2,%3}, {%4,%5,%6,%7}, {%8,%9}, {%0,%1,%2,%3};"
        : "+f"(d[0]), "+f"(d[1]), "+f"(d[2]), "+f"(d[3])
        : "r"(a0), "r"(a1), "r"(a2), "r"(a3), "r"(b0), "r"(b1));
}
__device__ __forceinline__ float fast_exp2(float x) {
    float y; asm("ex2.approx.ftz.f32 %0, %1;" : "=f"(y) : "f"(x)); return y;
}
__device__ __forceinline__ uint32_t pack_bf16(float lo, float hi) {
    uint32_t r; asm("cvt.rn.bf16x2.f32 %0, %1, %2;" : "=r"(r) : "f"(hi), "f"(lo)); return r;
}
__device__ __forceinline__ void split2(float x, float y, uint32_t& hi, uint32_t& lo) {
    __nv_bfloat16 hx = __float2bfloat16(x), hy = __float2bfloat16(y);
    float lx = x - __bfloat162float(hx), ly = y - __bfloat162float(hy);
    hi = pack_bf16(__bfloat162float(hx), __bfloat162float(hy));
    lo = pack_bf16(lx, ly);
}

// ---------------- misc ----------------
__global__ void copy_kernel(const float* __restrict__ a, float* __restrict__ o, int n4) {
    int i = blockIdx.x * blockDim.x + threadIdx.x;
    if (i < n4) ((float4*)o)[i] = ((const float4*)a)[i];
}

// ---------------- weight hi/lo conversion ----------------
__global__ void conv_w(const float* __restrict__ w_gin1, const float* __restrict__ w_gin2,
                       const float* __restrict__ w_ain,  const float* __restrict__ w_aout,
                       const float* __restrict__ w_m1,   const float* __restrict__ w_m2) {
    int id = blockIdx.x * 256 + threadIdx.x;
    if (id >= WTOTAL) return;
    const float* src; int off;
    if      (id < WOFF_GIN2) { src = w_gin1; off = id; }
    else if (id < WOFF_AIN)  { src = w_gin2; off = id - WOFF_GIN2; }
    else if (id < WOFF_AOUT) { src = w_ain;  off = id - WOFF_AIN; }
    else if (id < WOFF_MW1)  { src = w_aout; off = id - WOFF_AOUT; }
    else if (id < WOFF_MW2)  { src = w_m1;   off = id - WOFF_MW1; }
    else                     { src = w_m2;   off = id - WOFF_MW2; }
    float v = src[off];
    __nv_bfloat16 h = __float2bfloat16(v);
    g_whi[id] = h;
    g_wlo[id] = __float2bfloat16(v - __bfloat162float(h));
}

// ---------------- CSR build ----------------
__global__ void hist_kernel(const int* __restrict__ ei, int E) {
    int e = blockIdx.x * blockDim.x + threadIdx.x;
    if (e < E) atomicAdd(&g_deg[ei[E + e] + 1], 1);
}

__global__ void scan_kernel() {
    __shared__ int part[1024];
    int t = threadIdx.x;
    int base = t * 4;
    int x0 = g_deg[base], x1 = g_deg[base + 1], x2 = g_deg[base + 2], x3 = g_deg[base + 3];
    x1 += x0; x2 += x1; x3 += x2;
    part[t] = x3;
    __syncthreads();
    for (int off = 1; off < 1024; off <<= 1) {
        int v = (t >= off) ? part[t - off] : 0;
        __syncthreads();
        part[t] += v;
        __syncthreads();
    }
    int add = (t > 0) ? part[t - 1] : 0;
    int v0 = x0 + add, v1 = x1 + add, v2 = x2 + add, v3 = x3 + add;
    g_deg[base] = v0; g_deg[base + 1] = v1; g_deg[base + 2] = v2; g_deg[base + 3] = v3;
    g_cur[base] = v0; g_cur[base + 1] = v1; g_cur[base + 2] = v2; g_cur[base + 3] = v3;
    __syncthreads();
    if (t == 0) g_deg[NN] += g_deg[NN - 1];
}

__global__ void fill_kernel(const int* __restrict__ ei, int E) {
    int e = blockIdx.x * blockDim.x + threadIdx.x;
    if (e >= E) return;
    int s = ei[e], d = ei[E + e];
    int pos = atomicAdd(&g_cur[d], 1);
    g_csr[pos] = s;
}

// ---------------- GIN gather body ----------------
__device__ __forceinline__ void gather_body(const float* __restrict__ x,
                                            float* __restrict__ agg, int blk) {
    int wg = (blk * 256 + threadIdx.x) >> 5;
    int lane = threadIdx.x & 31;
    if (wg >= NN) return;
    int beg = g_deg[wg], end = g_deg[wg + 1];
    float4 acc = *(const float4*)&x[(long)wg * CC + lane * 4];
    for (int j = beg; j < end; j++) {
        int s = g_csr[j];
        float4 v = *(const float4*)&x[(long)s * CC + lane * 4];
        acc.x += v.x; acc.y += v.y; acc.z += v.z; acc.w += v.w;
    }
    *(float4*)&agg[(long)wg * CC + lane * 4] = acc;
}

// ---------------- tensor-core GEMM body (hi/lo split, register-prefetch) ----------------
// LMODE 0: A fp32 plain. LMODE 2: A = aff1(A)+aff2(A2); writes hout (bx==0).
// EMODE 0: store. 1: relu store. 2: qkv scatter. 3: w=v+xres, store w, col-sum reduce.
#define AST 40
#define GEMM_SM_BYTES (4 * 64 * AST * 2 + 4 * 128 * 4)   // 22528
template <int LMODE, int EMODE>
__device__ __forceinline__ void gemm_body(char* smraw, int bx, int by,
        const float* __restrict__ A, const float* __restrict__ A2,
        const __nv_bfloat16* __restrict__ Bh, const __nv_bfloat16* __restrict__ Bl,
        const float* __restrict__ bias, float* __restrict__ C,
        __nv_bfloat16* __restrict__ qb, __nv_bfloat16* __restrict__ kbuf,
        __nv_bfloat16* __restrict__ vtb,
        const float* __restrict__ xres, float* __restrict__ sums_out,
        const float* __restrict__ s1, const float* __restrict__ g1, const float* __restrict__ b1,
        const float* __restrict__ s2, const float* __restrict__ g2, const float* __restrict__ b2,
        float* __restrict__ hout, int M, int N, int K) {
    uint16_t* Ahs = (uint16_t*)smraw;
    uint16_t* Als = Ahs + 64 * AST;
    uint16_t* Bhs = Als + 64 * AST;
    uint16_t* Bls = Bhs + 64 * AST;
    float* csc1 = (float*)(Bls + 64 * AST);
    float* cof1 = csc1 + 128;
    float* csc2 = cof1 + 128;
    float* cof2 = csc2 + 128;

    const int tid = threadIdx.x;
    const int warp = tid >> 5, lane = tid & 31;
    const int gid = lane >> 2, tig = lane & 3;
    const int wm = warp >> 1, wn = warp & 1;
    const int bm = by * 64, bn = bx * 64;
    float acc[4][4] = {};

    if (LMODE == 2) {
        int c = tid & 127;
        const float* ss = (tid < 128) ? s1 : s2;
        const float* gg = (tid < 128) ? g1 : g2;
        const float* bb2 = (tid < 128) ? b1 : b2;
        float mean = ss[c] * (1.f / NN);
        float var  = ss[CC + c] * (1.f / NN) - mean * mean;
        float sc   = rsqrtf(var + BN_EPS) * gg[c];
        float off  = bb2[c] - mean * sc;
        if (tid < 128) { csc1[c] = sc; cof1[c] = off; }
        else           { csc2[c] = sc; cof2[c] = off; }
        __syncthreads();
    }

    const int nch = K >> 5;
    const int j0 = tid * 2, j1 = tid * 2 + 1;
    const int ar0 = j0 >> 3, ac0 = j0 & 7;
    const int ar1 = j1 >> 3, ac1 = j1 & 7;
    const int brow = tid >> 2, bseg = tid & 3;

    float4 va0, va1, wa0, wa1;
    uint4 vbh, vbl;

    va0 = *(const float4*)&A[(long)(bm + ar0) * K + ac0 * 4];
    va1 = *(const float4*)&A[(long)(bm + ar1) * K + ac1 * 4];
    if (LMODE == 2) {
        wa0 = *(const float4*)&A2[(long)(bm + ar0) * K + ac0 * 4];
        wa1 = *(const float4*)&A2[(long)(bm + ar1) * K + ac1 * 4];
    }
    vbh = *(const uint4*)&Bh[(long)(bn + brow) * K + bseg * 8];
    vbl = *(const uint4*)&Bl[(long)(bn + brow) * K + bseg * 8];

    for (int c = 0; c < nch; c++) {
        const int k0 = c * 32;
        {
            float4 v = va0;
            int cbase = k0 + ac0 * 4;
            if (LMODE == 2) {
                v.x = v.x * csc1[cbase]     + cof1[cbase]     + wa0.x * csc2[cbase]     + cof2[cbase];
                v.y = v.y * csc1[cbase + 1] + cof1[cbase + 1] + wa0.y * csc2[cbase + 1] + cof2[cbase + 1];
                v.z = v.z * csc1[cbase + 2] + cof1[cbase + 2] + wa0.z * csc2[cbase + 2] + cof2[cbase + 2];
                v.w = v.w * csc1[cbase + 3] + cof1[cbase + 3] + wa0.w * csc2[cbase + 3] + cof2[cbase + 3];
                if (bx == 0)
                    *(float4*)&hout[(long)(bm + ar0) * K + cbase] = v;
            }
            uint32_t h0, l0, h1, l1;
            split2(v.x, v.y, h0, l0);
            split2(v.z, v.w, h1, l1);
            uint32_t* ph = (uint32_t*)&Ahs[ar0 * AST + ac0 * 4];
            uint32_t* pl = (uint32_t*)&Als[ar0 * AST + ac0 * 4];
            ph[0] = h0; ph[1] = h1;
            pl[0] = l0; pl[1] = l1;
        }
        {
            float4 v = va1;
            int cbase = k0 + ac1 * 4;
            if (LMODE == 2) {
                v.x = v.x * csc1[cbase]     + cof1[cbase]     + wa1.x * csc2[cbase]     + cof2[cbase];
                v.y = v.y * csc1[cbase + 1] + cof1[cbase + 1] + wa1.y * csc2[cbase + 1] + cof2[cbase + 1];
                v.z = v.z * csc1[cbase + 2] + cof1[cbase + 2] + wa1.z * csc2[cbase + 2] + cof2[cbase + 2];
                v.w = v.w * csc1[cbase + 3] + cof1[cbase + 3] + wa1.w * csc2[cbase + 3] + cof2[cbase + 3];
                if (bx == 0)
                    *(float4*)&hout[(long)(bm + ar1) * K + cbase] = v;
            }
            uint32_t h0, l0, h1, l1;
            split2(v.x, v.y, h0, l0);
            split2(v.z, v.w, h1, l1);
            uint32_t* ph = (uint32_t*)&Ahs[ar1 * AST + ac1 * 4];
            uint32_t* pl = (uint32_t*)&Als[ar1 * AST + ac1 * 4];
            ph[0] = h0; ph[1] = h1;
            pl[0] = l0; pl[1] = l1;
        }
        *(uint4*)&Bhs[brow * AST + bseg * 8] = vbh;
        *(uint4*)&Bls[brow * AST + bseg * 8] = vbl;
        __syncthreads();

        if (c + 1 < nch) {
            const int kn = (c + 1) * 32;
            va0 = *(const float4*)&A[(long)(bm + ar0) * K + kn + ac0 * 4];
            va1 = *(const float4*)&A[(long)(bm + ar1) * K + kn + ac1 * 4];
            if (LMODE == 2) {
                wa0 = *(const float4*)&A2[(long)(bm + ar0) * K + kn + ac0 * 4];
                wa1 = *(const float4*)&A2[(long)(bm + ar1) * K + kn + ac1 * 4];
            }
            vbh = *(const uint4*)&Bh[(long)(bn + brow) * K + kn + bseg * 8];
            vbl = *(const uint4*)&Bl[(long)(bn + brow) * K + kn + bseg * 8];
        }

#pragma unroll
        for (int ks = 0; ks < 2; ks++) {
            int kk = ks * 16 + tig * 2;
            int r = wm * 16;
            uint32_t ah0 = *(const uint32_t*)&Ahs[(r + gid    ) * AST + kk    ];
            uint32_t ah1 = *(const uint32_t*)&Ahs[(r + gid + 8) * AST + kk    ];
            uint32_t ah2 = *(const uint32_t*)&Ahs[(r + gid    ) * AST + kk + 8];
            uint32_t ah3 = *(const uint32_t*)&Ahs[(r + gid + 8) * AST + kk + 8];
            uint32_t al0 = *(const uint32_t*)&Als[(r + gid    ) * AST + kk    ];
            uint32_t al1 = *(const uint32_t*)&Als[(r + gid + 8) * AST + kk    ];
            uint32_t al2 = *(const uint32_t*)&Als[(r + gid    ) * AST + kk + 8];
            uint32_t al3 = *(const uint32_t*)&Als[(r + gid + 8) * AST + kk + 8];
#pragma unroll
            for (int nb = 0; nb < 4; nb++) {
                int nr = wn * 32 + nb * 8 + gid;
                uint32_t bh0 = *(const uint32_t*)&Bhs[nr * AST + kk    ];
                uint32_t bh1 = *(const uint32_t*)&Bhs[nr * AST + kk + 8];
                uint32_t bl0 = *(const uint32_t*)&Bls[nr * AST + kk    ];
                uint32_t bl1 = *(const uint32_t*)&Bls[nr * AST + kk + 8];
                mma_bf16(acc[nb], ah0, ah1, ah2, ah3, bh0, bh1);
                mma_bf16(acc[nb], ah0, ah1, ah2, ah3, bl0, bl1);
                mma_bf16(acc[nb], al0, al1, al2, al3, bh0, bh1);
            }
        }
        __syncthreads();
    }

    const int rowA = bm + wm * 16 + gid, rowB = rowA + 8;
#pragma unroll
    for (int nb = 0; nb < 4; nb++) {
        int col = bn + wn * 32 + nb * 8 + tig * 2;
        if (col >= N) continue;
        float b0 = bias[col], b1v = bias[col + 1];
        float v0 = acc[nb][0] + b0, v1 = acc[nb][1] + b1v;
        float v2 = acc[nb][2] + b0, v3 = acc[nb][3] + b1v;
        if (EMODE == 1) {
            v0 = fmaxf(v0, 0.f); v1 = fmaxf(v1, 0.f);
            v2 = fmaxf(v2, 0.f); v3 = fmaxf(v3, 0.f);
        }
        if (EMODE == 2) {
            int sec = col >> 7, hh = (col & 127) >> 5, d = col & 31;
            if (sec == 0) {
                *(uint32_t*)&qb[((hh << 12) + rowA) * 32 + d] = pack_bf16(v0, v1);
                *(uint32_t*)&qb[((hh << 12) + rowB) * 32 + d] = pack_bf16(v2, v3);
            } else if (sec == 1) {
                *(uint32_t*)&kbuf[((hh << 12) + rowA) * 32 + d] = pack_bf16(v0, v1);
                *(uint32_t*)&kbuf[((hh << 12) + rowB) * 32 + d] = pack_bf16(v2, v3);
            } else {
                vtb[((hh * 32 + d    ) << 12) + rowA] = __float2bfloat16(v0);
                vtb[((hh * 32 + d + 1) << 12) + rowA] = __float2bfloat16(v1);
                vtb[((hh * 32 + d    ) << 12) + rowB] = __float2bfloat16(v2);
                vtb[((hh * 32 + d + 1) << 12) + rowB] = __float2bfloat16(v3);
            }
        } else if (EMODE == 3) {
            float2 xA = *(const float2*)&xres[(long)rowA * N + col];
            float2 xB = *(const float2*)&xres[(long)rowB * N + col];
            float w0 = v0 + xA.x, w1 = v1 + xA.y;
            float w2 = v2 + xB.x, w3 = v3 + xB.y;
            *(float2*)&C[(long)rowA * N + col] = make_float2(w0, w1);
            *(float2*)&C[(long)rowB * N + col] = make_float2(w2, w3);
            float cs0 = w0 + w2, cs1 = w1 + w3;
            float cq0 = w0 * w0 + w2 * w2, cq1 = w1 * w1 + w3 * w3;
#pragma unroll
            for (int mk = 4; mk < 32; mk <<= 1) {
                cs0 += __shfl_xor_sync(0xFFFFFFFF, cs0, mk);
                cs1 += __shfl_xor_sync(0xFFFFFFFF, cs1, mk);
                cq0 += __shfl_xor_sync(0xFFFFFFFF, cq0, mk);
                cq1 += __shfl_xor_sync(0xFFFFFFFF, cq1, mk);
            }
            if (gid == 0) {
                atomicAdd(&sums_out[col], cs0);
                atomicAdd(&sums_out[CC + col], cq0);
                atomicAdd(&sums_out[col + 1], cs1);
                atomicAdd(&sums_out[CC + col + 1], cq1);
            }
        } else {
            *(float2*)&C[(long)rowA * N + col] = make_float2(v0, v1);
            *(float2*)&C[(long)rowB * N + col] = make_float2(v2, v3);
        }
    }
}

// ---------------- attention body ----------------
#define EXP2_SCALE 0.25503480f
#define QK_STRIDE 40
#define VT_STRIDE 136
#define ATTN_SM_BYTES ((128 * QK_STRIDE + 128 * QK_STRIDE + 32 * VT_STRIDE) * 2)  // 29184

__device__ __forceinline__ void attn_body(char* smraw, int qt, int h,
        const __nv_bfloat16* __restrict__ qb, const __nv_bfloat16* __restrict__ kb,
        const __nv_bfloat16* __restrict__ vtb, float* __restrict__ out) {
    uint16_t* Qs  = (uint16_t*)smraw;
    uint16_t* Ks  = Qs + 128 * QK_STRIDE;
    uint16_t* Vts = Ks + 128 * QK_STRIDE;

    const int tid = threadIdx.x;
    const int wid = tid >> 5, lane = tid & 31;
    const int gid = lane >> 2, tig = lane & 3;
    const int qbase = qt * 128;
    const int r0 = wid * 16;

    const uint16_t* Qg = (const uint16_t*)(qb + ((long)h * NN + qbase) * 32);
#pragma unroll
    for (int it = 0; it < 2; it++) {
        int i = tid + it * 256;
        int row = i >> 2, seg = i & 3;
        *(uint4*)&Qs[row * QK_STRIDE + seg * 8] = *(const uint4*)&Qg[row * 32 + seg * 8];
    }
    __syncthreads();

    uint32_t aq[2][4];
#pragma unroll
    for (int t = 0; t < 2; t++) {
        int k = t * 16 + tig * 2;
        aq[t][0] = *(const uint32_t*)&Qs[(r0 + gid    ) * QK_STRIDE + k    ];
        aq[t][1] = *(const uint32_t*)&Qs[(r0 + gid + 8) * QK_STRIDE + k    ];
        aq[t][2] = *(const uint32_t*)&Qs[(r0 + gid    ) * QK_STRIDE + k + 8];
        aq[t][3] = *(const uint32_t*)&Qs[(r0 + gid + 8) * QK_STRIDE + k + 8];
    }

    float oacc[4][4] = {};
    float rs0 = 0.f, rs1 = 0.f;

    for (int kt = 0; kt < NN / 128; kt++) {
        const int kb0 = kt * 128;
        __syncthreads();
        const uint16_t* Kg = (const uint16_t*)(kb + ((long)h * NN + kb0) * 32);
#pragma unroll
        for (int it = 0; it < 2; it++) {
            int i = tid + it * 256;
            int row = i >> 2, seg = i & 3;
            *(uint4*)&Ks[row * QK_STRIDE + seg * 8] = *(const uint4*)&Kg[row * 32 + seg * 8];
        }
        const uint16_t* Vg = (const uint16_t*)(vtb + ((long)h * 32) * NN + kb0);
#pragma unroll
        for (int it = 0; it < 2; it++) {
            int i = tid + it * 256;
            int d = i >> 4, seg = i & 15;
            *(uint4*)&Vts[d * VT_STRIDE + seg * 8] = *(const uint4*)&Vg[(long)d * NN + seg * 8];
        }
        __syncthreads();

        float sacc[16][4];
#pragma unroll
        for (int j = 0; j < 16; j++) { sacc[j][0] = sacc[j][1] = sacc[j][2] = sacc[j][3] = 0.f; }
#pragma unroll
        for (int j = 0; j < 16; j++) {
#pragma unroll
            for (int t = 0; t < 2; t++) {
                int k = t * 16 + tig * 2;
                uint32_t b0 = *(const uint32_t*)&Ks[(8 * j + gid) * QK_STRIDE + k    ];
                uint32_t b1 = *(const uint32_t*)&Ks[(8 * j + gid) * QK_STRIDE + k + 8];
                mma_bf16(sacc[j], aq[t][0], aq[t][1], aq[t][2], aq[t][3], b0, b1);
            }
        }

        uint32_t pf[16][2];
#pragma unroll
        for (int j = 0; j < 16; j++) {
            float p0 = fast_exp2(sacc[j][0] * EXP2_SCALE);
            float p1 = fast_exp2(sacc[j][1] * EXP2_SCALE);
            float p2 = fast_exp2(sacc[j][2] * EXP2_SCALE);
            float p3 = fast_exp2(sacc[j][3] * EXP2_SCALE);
            rs0 += p0 + p1;
            rs1 += p2 + p3;
            pf[j][0] = pack_bf16(p0, p1);
            pf[j][1] = pack_bf16(p2, p3);
        }

#pragma unroll
        for (int t = 0; t < 8; t++) {
            uint32_t a0 = pf[2 * t][0], a1 = pf[2 * t][1];
            uint32_t a2 = pf[2 * t + 1][0], a3 = pf[2 * t + 1][1];
            int k = t * 16 + tig * 2;
#pragma unroll
            for (int n = 0; n < 4; n++) {
                uint32_t b0 = *(const uint32_t*)&Vts[(8 * n + gid) * VT_STRIDE + k    ];
                uint32_t b1 = *(const uint32_t*)&Vts[(8 * n + gid) * VT_STRIDE + k + 8];
                mma_bf16(oacc[n], a0, a1, a2, a3, b0, b1);
            }
        }
    }

    rs0 += __shfl_xor_sync(0xFFFFFFFF, rs0, 1);
    rs0 += __shfl_xor_sync(0xFFFFFFFF, rs0, 2);
    rs1 += __shfl_xor_sync(0xFFFFFFFF, rs1, 1);
    rs1 += __shfl_xor_sync(0xFFFFFFFF, rs1, 2);
    float inv0 = 1.f / rs0, inv1 = 1.f / rs1;

    int rowA = qbase + r0 + gid, rowB = rowA + 8;
    float* poA = out + (long)rowA * CC + h * 32 + tig * 2;
    float* poB = out + (long)rowB * CC + h * 32 + tig * 2;
#pragma unroll
    for (int n = 0; n < 4; n++) {
        *(float2*)(poA + n * 8) = make_float2(oacc[n][0] * inv0, oacc[n][1] * inv0);
        *(float2*)(poB + n * 8) = make_float2(oacc[n][2] * inv1, oacc[n][3] * inv1);
    }
}

// ---------------- fused branch kernels ----------------
// A: gather (512 blocks) || qkv gemm (384 blocks)
__global__ __launch_bounds__(256) void k_gather_qkv(const float* __restrict__ x,
        float* __restrict__ agg,
        const __nv_bfloat16* __restrict__ Bh, const __nv_bfloat16* __restrict__ Bl,
        const float* __restrict__ aib,
        __nv_bfloat16* __restrict__ qb, __nv_bfloat16* __restrict__ kbuf,
        __nv_bfloat16* __restrict__ vtb) {
    __shared__ __align__(16) char sm[GEMM_SM_BYTES];
    int b = blockIdx.x;
    if (b < 512) {
        gather_body(x, agg, b);
    } else {
        int i = b - 512;
        gemm_body<0, 2>(sm, i % 6, i / 6, x, nullptr, Bh, Bl, aib, nullptr,
                        qb, kbuf, vtb, nullptr, nullptr,
                        nullptr, nullptr, nullptr, nullptr, nullptr, nullptr,
                        nullptr, NN, 3 * CC, CC);
    }
}

// B: gin1 relu gemm (128 blocks) || attention (128 blocks)
__global__ __launch_bounds__(256) void k_gin1_attn(const float* __restrict__ agg,
        const __nv_bfloat16* __restrict__ G1h, const __nv_bfloat16* __restrict__ G1l,
        const float* __restrict__ gb1, float* __restrict__ t1,
        const __nv_bfloat16* __restrict__ qb, const __nv_bfloat16* __restrict__ kb,
        const __nv_bfloat16* __restrict__ vtb, float* __restrict__ ao) {
    __shared__ __align__(16) char sm[ATTN_SM_BYTES];
    int b = blockIdx.x;
    if (b < 128) {
        gemm_body<0, 1>(sm, b & 1, b >> 1, agg, nullptr, G1h, G1l, gb1, t1,
                        nullptr, nullptr, nullptr, nullptr, nullptr,
                        nullptr, nullptr, nullptr, nullptr, nullptr, nullptr,
                        nullptr, NN, CC, CC);
    } else {
        int i = b - 128;
        attn_body(sm, i & 31, i >> 5, qb, kb, vtb, ao);
    }
}

// C: gin2 gemm E3 (128 blocks) || attn-out gemm E3 (128 blocks)
__global__ __launch_bounds__(256) void k_gin2_aout(const float* __restrict__ t1,
        const __nv_bfloat16* __restrict__ G2h, const __nv_bfloat16* __restrict__ G2l,
        const float* __restrict__ gb2, float* __restrict__ h1,
        const float* __restrict__ ao,
        const __nv_bfloat16* __restrict__ AOh, const __nv_bfloat16* __restrict__ AOl,
        const float* __restrict__ aob, float* __restrict__ h2,
        const float* __restrict__ x, float* __restrict__ s1, float* __restrict__ s2) {
    __shared__ __align__(16) char sm[GEMM_SM_BYTES];
    int b = blockIdx.x;
    if (b < 128) {
        gemm_body<0, 3>(sm, b & 1, b >> 1, t1, nullptr, G2h, G2l, gb2, h1,
                        nullptr, nullptr, nullptr, x, s1,
                        nullptr, nullptr, nullptr, nullptr, nullptr, nullptr,
                        nullptr, NN, CC, CC);
    } else {
        int i = b - 128;
        gemm_body<0, 3>(sm, i & 1, i >> 1, ao, nullptr, AOh, AOl, aob, h2,
                        nullptr, nullptr, nullptr, x, s2,
                        nullptr, nullptr, nullptr, nullptr, nullptr, nullptr,
                        nullptr, NN, CC, CC);
    }
}

// standalone gemm wrapper (mlp1 / mlp2)
template <int LMODE, int EMODE>
__global__ __launch_bounds__(256) void gemm_tc(const float* __restrict__ A,
        const float* __restrict__ A2,
        const __nv_bfloat16* __restrict__ Bh, const __nv_bfloat16* __restrict__ Bl,
        const float* __restrict__ bias, float* __restrict__ C,
        const float* __restrict__ xres, float* __restrict__ sums_out,
        const float* __restrict__ s1, const float* __restrict__ g1, const float* __restrict__ b1,
        const float* __restrict__ s2, const float* __restrict__ g2, const float* __restrict__ b2,
        float* __restrict__ hout, int M, int N, int K) {
    __shared__ __align__(16) char sm[GEMM_SM_BYTES];
    gemm_body<LMODE, EMODE>(sm, blockIdx.x, blockIdx.y, A, A2, Bh, Bl, bias, C,
                            nullptr, nullptr, nullptr, xres, sums_out,
                            s1, g1, b1, s2, g2, b2, hout, M, N, K);
}

// ---------------- BN affine apply: x = aff(u) ----------------
__global__ __launch_bounds__(256) void bn_affine(const float* __restrict__ u,
        const float* __restrict__ sums, const float* __restrict__ g,
        const float* __restrict__ b, float* __restrict__ out) {
    int i = blockIdx.x * 256 + threadIdx.x;
    if (i >= NN * 32) return;
    int c4 = i & 31;
    float4 v = ((const float4*)u)[i];
    float o[4] = {v.x, v.y, v.z, v.w};
#pragma unroll
    for (int k = 0; k < 4; k++) {
        int c = c4 * 4 + k;
        float mean = sums[c] * (1.f / NN);
        float var  = sums[CC + c] * (1.f / NN) - mean * mean;
        float sc   = rsqrtf(var + BN_EPS) * g[c];
        o[k] = (o[k] - mean) * sc + b[c];
    }
    ((float4*)out)[i] = make_float4(o[0], o[1], o[2], o[3]);
}

// ---------------- head MLP: warp-per-node, low smem ----------------
__global__ __launch_bounds__(256) void head_warp(const float* __restrict__ x,
        const float* __restrict__ w1, const float* __restrict__ b1,
        const float* __restrict__ w2, const float* __restrict__ b2,
        const float* __restrict__ w3, const float* __restrict__ b3,
        float* __restrict__ out) {
    __shared__ float y1s[8][64];
    __shared__ float y2s[8][32];
    int tid = threadIdx.x;
    int wid = tid >> 5, lane = tid & 31;
    int n = blockIdx.x * 8 + wid;

    float4 xv = *(const float4*)&x[(long)n * 128 + lane * 4];

    for (int o = 0; o < 64; o++) {
        float4 wv = *(const float4*)&w1[o * 128 + lane * 4];
        float p = xv.x * wv.x + xv.y * wv.y + xv.z * wv.z + xv.w * wv.w;
#pragma unroll
        for (int mk = 16; mk > 0; mk >>= 1) p += __shfl_xor_sync(0xFFFFFFFF, p, mk);
        if (lane == 0) y1s[wid][o] = fmaxf(p + b1[o], 0.f);
    }
    __syncwarp();
    float ya = y1s[wid][lane * 2], yb = y1s[wid][lane * 2 + 1];
    for (int o = 0; o < 32; o++) {
        float2 wv = *(const float2*)&w2[o * 64 + lane * 2];
        float p = ya * wv.x + yb * wv.y;
#pragma unroll
        for (int mk = 16; mk > 0; mk >>= 1) p += __shfl_xor_sync(0xFFFFFFFF, p, mk);
        if (lane == 0) y2s[wid][o] = fmaxf(p + b2[o], 0.f);
    }
    __syncwarp();
    float p = y2s[wid][lane] * w3[lane];
#pragma unroll
    for (int mk = 16; mk > 0; mk >>= 1) p += __shfl_xor_sync(0xFFFFFFFF, p, mk);
    if (lane == 0) out[n] = p + b3[0];
}

// ---------------- host orchestration ----------------
static __nv_bfloat16 *s_whi, *s_wlo;

extern "C" void kernel_launch(void* const* d_in, const int* in_sizes, int n_in,
                              void* d_out, int out_size) {
    const float* x_in      = (const float*)d_in[0];
    const int*   edge      = (const int*)  d_in[1];
    const float* gin_w1    = (const float*)d_in[2];
    const float* gin_b1    = (const float*)d_in[3];
    const float* gin_w2    = (const float*)d_in[4];
    const float* gin_b2    = (const float*)d_in[5];
    const float* attn_in_w = (const float*)d_in[6];
    const float* attn_in_b = (const float*)d_in[7];
    const float* attn_o_w  = (const float*)d_in[8];
    const float* attn_o_b  = (const float*)d_in[9];
    const float* n1_g = (const float*)d_in[10];
    const float* n1_b = (const float*)d_in[11];
    const float* n2_g = (const float*)d_in[12];
    const float* n2_b = (const float*)d_in[13];
    const float* n3_g = (const float*)d_in[14];
    const float* n3_b = (const float*)d_in[15];
    const float* mlp_w1 = (const float*)d_in[16];
    const float* mlp_b1 = (const float*)d_in[17];
    const float* mlp_w2 = (const float*)d_in[18];
    const float* mlp_b2 = (const float*)d_in[19];
    const float* hw1 = (const float*)d_in[20];
    const float* hb1 = (const float*)d_in[21];
    const float* hw2 = (const float*)d_in[22];
    const float* hb2 = (const float*)d_in[23];
    const float* hw3 = (const float*)d_in[24];
    const float* hb3 = (const float*)d_in[25];
    float* out = (float*)d_out;

    int E = in_sizes[1] / 2;

    float *p_x, *p_agg, *p_ao, *p_t1, *p_t2, *p_h1, *p_h2, *p_sums;
    int *p_deg;
    __nv_bfloat16 *p_qb, *p_kb, *p_vtb;
    cudaGetSymbolAddress((void**)&p_x,  g_x);
    cudaGetSymbolAddress((void**)&p_agg, g_agg);
    cudaGetSymbolAddress((void**)&p_ao, g_ao);
    cudaGetSymbolAddress((void**)&p_t1, g_t1);
    cudaGetSymbolAddress((void**)&p_t2, g_t2);
    cudaGetSymbolAddress((void**)&p_h1, g_h1);
    cudaGetSymbolAddress((void**)&p_h2, g_h2);
    cudaGetSymbolAddress((void**)&p_sums, g_bnsums);
    cudaGetSymbolAddress((void**)&p_deg, g_deg);
    cudaGetSymbolAddress((void**)&p_qb, g_qb);
    cudaGetSymbolAddress((void**)&p_kb, g_kb);
    cudaGetSymbolAddress((void**)&p_vtb, g_vtb);
    cudaGetSymbolAddress((void**)&s_whi, g_whi);
    cudaGetSymbolAddress((void**)&s_wlo, g_wlo);

    const int NC4 = NN * CC / 4;

    conv_w<<<(WTOTAL + 255) / 256, 256>>>(gin_w1, gin_w2, attn_in_w, attn_o_w, mlp_w1, mlp_w2);
    cudaMemsetAsync(p_sums, 0, 12 * 2 * CC * sizeof(float));
    cudaMemsetAsync(p_deg, 0, (NN + 1) * sizeof(int));
    hist_kernel<<<(E + 255) / 256, 256>>>(edge, E);
    scan_kernel<<<1, 1024>>>();
    fill_kernel<<<(E + 255) / 256, 256>>>(edge, E);
    copy_kernel<<<(NC4 + 255) / 256, 256>>>(x_in, p_x, NC4);

    for (int i = 0; i < LL; i++) {
        const float* gb1 = gin_b1 + (long)i * CC;
        const float* gb2 = gin_b2 + (long)i * CC;
        const float* aib = attn_in_b + (long)i * 3 * CC;
        const float* aob = attn_o_b + (long)i * CC;
        const float* mb1 = mlp_b1 + (long)i * 2 * CC;
        const float* mb2 = mlp_b2 + (long)i * CC;
        float* s1 = p_sums + (3 * i + 0) * 2 * CC;
        float* s2 = p_sums + (3 * i + 1) * 2 * CC;
        float* s3 = p_sums + (3 * i + 2) * 2 * CC;

        // A: gather || qkv
        k_gather_qkv<<<512 + 384, 256>>>(p_x, p_agg,
            s_whi + WOFF_AIN + i * 3 * CC * CC, s_wlo + WOFF_AIN + i * 3 * CC * CC,
            aib, p_qb, p_kb, p_vtb);
        // B: gin1 || attention
        k_gin1_attn<<<256, 256>>>(p_agg,
            s_whi + WOFF_GIN1 + i * CC * CC, s_wlo + WOFF_GIN1 + i * CC * CC, gb1, p_t1,
            p_qb, p_kb, p_vtb, p_ao);
        // C: gin2(E3,s1) || aout(E3,s2)
        k_gin2_aout<<<256, 256>>>(p_t1,
            s_whi + WOFF_GIN2 + i * CC * CC, s_wlo + WOFF_GIN2 + i * CC * CC, gb2, p_h1,
            p_ao, s_whi + WOFF_AOUT + i * CC * CC, s_wlo + WOFF_AOUT + i * CC * CC,
            aob, p_h2, p_x, s1, s2);

        // MLP: A = aff1(h1') + aff2(h2') (= h), write h, relu gemm
        gemm_tc<2, 1><<<dim3(4, 64), 256>>>(p_h1, p_h2,
            s_whi + WOFF_MW1 + i * 2 * CC * CC, s_wlo + WOFF_MW1 + i * 2 * CC * CC, mb1, p_t1,
            nullptr, nullptr,
            s1, n1_g + i * CC, n1_b + i * CC, s2, n2_g + i * CC, n2_b + i * CC,
            p_t2, NN, 2 * CC, CC);
        gemm_tc<0, 3><<<dim3(2, 64), 256>>>(p_t1, nullptr,
            s_whi + WOFF_MW2 + i * 2 * CC * CC, s_wlo + WOFF_MW2 + i * 2 * CC * CC, mb2, p_agg,
            p_t2, s3,
            nullptr, nullptr, nullptr, nullptr, nullptr, nullptr,
            nullptr, NN, CC, 2 * CC);
        bn_affine<<<NN * 32 / 256, 256>>>(p_agg, s3, n3_g + i * CC, n3_b + i * CC, p_x);
    }

    // ---- head ----
    head_warp<<<NN / 8, 256>>>(p_x, hw1, hb1, hw2, hb2, hw3, hb3, out);
}

// round 13
// speedup vs baseline: 1.2062x; 1.2062x over previous
#include <cuda_runtime.h>
#include <cuda_bf16.h>
#include <cstdint>

#define NN 4096
#define CC 128
#define LL 4
#define HEADS 4
#define BN_EPS 1e-5f
#define EMAX 262144

// ---------------- scratch (static device globals; no allocation) ----------------
__device__ float g_x  [NN * CC];
__device__ float g_agg[NN * CC];
__device__ float g_t1 [NN * 384];
__device__ float g_t2 [NN * CC];
__device__ float g_h1 [NN * CC];
__device__ float g_h2 [NN * CC];
__device__ float g_bnsums[12 * 2 * CC];
__device__ int   g_deg[NN + 1];
__device__ int   g_cur[NN];
__device__ int   g_csr[EMAX];
__device__ __nv_bfloat16 g_qb [HEADS * NN * 32];
__device__ __nv_bfloat16 g_kb [HEADS * NN * 32];
__device__ __nv_bfloat16 g_vtb[HEADS * 32 * NN];

// concatenated hi/lo bf16 weights
#define WOFF_GIN1 0
#define WOFF_GIN2 65536
#define WOFF_AIN  131072
#define WOFF_AOUT 327680
#define WOFF_MW1  393216
#define WOFF_MW2  524288
#define WTOTAL    655360
__device__ __nv_bfloat16 g_whi[WTOTAL];
__device__ __nv_bfloat16 g_wlo[WTOTAL];

// ---------------- mma.sync / ptx helpers ----------------
__device__ __forceinline__ void mma_bf16(float* d, uint32_t a0, uint32_t a1, uint32_t a2,
                                         uint32_t a3, uint32_t b0, uint32_t b1) {
    asm volatile(
        "mma.sync.aligned.m16n8k16.row.col.f32.bf16.bf16.f32 "
        "{%0,%1,%2,%3}, {%4,%5,%6,%7}, {%8,%9}, {%0,%1,%2,%3};"
        : "+f"(d[0]), "+f"(d[1]), "+f"(d[2]), "+f"(d[3])
        : "r"(a0), "r"(a1), "r"(a2), "r"(a3), "r"(b0), "r"(b1));
}
__device__ __forceinline__ float fast_exp2(float x) {
    float y; asm("ex2.approx.ftz.f32 %0, %1;" : "=f"(y) : "f"(x)); return y;
}
__device__ __forceinline__ uint32_t pack_bf16(float lo, float hi) {
    uint32_t r; asm("cvt.rn.bf16x2.f32 %0, %1, %2;" : "=r"(r) : "f"(hi), "f"(lo)); return r;
}
__device__ __forceinline__ void split2(float x, float y, uint32_t& hi, uint32_t& lo) {
    __nv_bfloat16 hx = __float2bfloat16(x), hy = __float2bfloat16(y);
    float lx = x - __bfloat162float(hx), ly = y - __bfloat162float(hy);
    hi = pack_bf16(__bfloat162float(hx), __bfloat162float(hy));
    lo = pack_bf16(lx, ly);
}
__device__ __forceinline__ uint32_t smem_u32(const void* p) {
    return (uint32_t)__cvta_generic_to_shared(p);
}
#define CP16(dst_u32, src) \
    asm volatile("cp.async.cg.shared.global [%0], [%1], 16;" :: "r"(dst_u32), "l"(src))
#define CP_COMMIT() asm volatile("cp.async.commit_group;")
#define CP_WAIT1()  asm volatile("cp.async.wait_group 1;")
#define CP_WAIT0()  asm volatile("cp.async.wait_group 0;")

// ---------------- weight hi/lo conversion ----------------
__global__ void conv_w(const float* __restrict__ w_gin1, const float* __restrict__ w_gin2,
                       const float* __restrict__ w_ain,  const float* __restrict__ w_aout,
                       const float* __restrict__ w_m1,   const float* __restrict__ w_m2) {
    int id = blockIdx.x * 256 + threadIdx.x;
    if (id >= WTOTAL) return;
    const float* src; int off;
    if      (id < WOFF_GIN2) { src = w_gin1; off = id; }
    else if (id < WOFF_AIN)  { src = w_gin2; off = id - WOFF_GIN2; }
    else if (id < WOFF_AOUT) { src = w_ain;  off = id - WOFF_AIN; }
    else if (id < WOFF_MW1)  { src = w_aout; off = id - WOFF_AOUT; }
    else if (id < WOFF_MW2)  { src = w_m1;   off = id - WOFF_MW1; }
    else                     { src = w_m2;   off = id - WOFF_MW2; }
    float v = src[off];
    __nv_bfloat16 h = __float2bfloat16(v);
    g_whi[id] = h;
    g_wlo[id] = __float2bfloat16(v - __bfloat162float(h));
}

// ---------------- CSR build ----------------
__global__ void hist_kernel(const int* __restrict__ ei, int E) {
    int e = blockIdx.x * blockDim.x + threadIdx.x;
    if (e < E) atomicAdd(&g_deg[ei[E + e] + 1], 1);
}

__global__ void scan_kernel() {
    __shared__ int part[1024];
    int t = threadIdx.x;
    int base = t * 4;
    int x0 = g_deg[base], x1 = g_deg[base + 1], x2 = g_deg[base + 2], x3 = g_deg[base + 3];
    x1 += x0; x2 += x1; x3 += x2;
    part[t] = x3;
    __syncthreads();
    for (int off = 1; off < 1024; off <<= 1) {
        int v = (t >= off) ? part[t - off] : 0;
        __syncthreads();
        part[t] += v;
        __syncthreads();
    }
    int add = (t > 0) ? part[t - 1] : 0;
    int v0 = x0 + add, v1 = x1 + add, v2 = x2 + add, v3 = x3 + add;
    g_deg[base] = v0; g_deg[base + 1] = v1; g_deg[base + 2] = v2; g_deg[base + 3] = v3;
    g_cur[base] = v0; g_cur[base + 1] = v1; g_cur[base + 2] = v2; g_cur[base + 3] = v3;
    __syncthreads();
    if (t == 0) g_deg[NN] += g_deg[NN - 1];
}

__global__ void fill_kernel(const int* __restrict__ ei, int E) {
    int e = blockIdx.x * blockDim.x + threadIdx.x;
    if (e >= E) return;
    int s = ei[e], d = ei[E + e];
    int pos = atomicAdd(&g_cur[d], 1);
    g_csr[pos] = s;
}

// ---------------- GIN gather ----------------
__global__ __launch_bounds__(256) void gather_kernel(const float* __restrict__ x,
                                                     float* __restrict__ agg) {
    int wg = (blockIdx.x * 256 + threadIdx.x) >> 5;
    int lane = threadIdx.x & 31;
    if (wg >= NN) return;
    int beg = g_deg[wg], end = g_deg[wg + 1];
    float4 acc = *(const float4*)&x[(long)wg * CC + lane * 4];
    for (int j = beg; j < end; j++) {
        int s = g_csr[j];
        float4 v = *(const float4*)&x[(long)s * CC + lane * 4];
        acc.x += v.x; acc.y += v.y; acc.z += v.z; acc.w += v.w;
    }
    *(float4*)&agg[(long)wg * CC + lane * 4] = acc;
}

// ---------------- tensor-core GEMM (hi/lo split, register-prefetch) — R10 proven ------
#define AST 40
template <int LMODE, int EMODE>
__global__ __launch_bounds__(256) void gemm_tc(const float* __restrict__ A,
        const float* __restrict__ A2,
        const __nv_bfloat16* __restrict__ Bh, const __nv_bfloat16* __restrict__ Bl,
        const float* __restrict__ bias, float* __restrict__ C,
        __nv_bfloat16* __restrict__ qb, __nv_bfloat16* __restrict__ kbuf,
        __nv_bfloat16* __restrict__ vtb,
        const float* __restrict__ xres, float* __restrict__ sums_out,
        const float* __restrict__ s1, const float* __restrict__ g1, const float* __restrict__ b1,
        const float* __restrict__ s2, const float* __restrict__ g2, const float* __restrict__ b2,
        float* __restrict__ hout, int M, int N, int K) {
    __shared__ uint16_t Ahs[64 * AST], Als[64 * AST];
    __shared__ uint16_t Bhs[64 * AST], Bls[64 * AST];
    __shared__ float csc1[128], cof1[128], csc2[128], cof2[128];
    const int tid = threadIdx.x;
    const int warp = tid >> 5, lane = tid & 31;
    const int gid = lane >> 2, tig = lane & 3;
    const int wm = warp >> 1, wn = warp & 1;
    const int bm = blockIdx.y * 64, bn = blockIdx.x * 64;
    float acc[4][4] = {};

    if (LMODE == 2) {
        int c = tid & 127;
        const float* ss = (tid < 128) ? s1 : s2;
        const float* gg = (tid < 128) ? g1 : g2;
        const float* bb2 = (tid < 128) ? b1 : b2;
        float mean = ss[c] * (1.f / NN);
        float var  = ss[CC + c] * (1.f / NN) - mean * mean;
        float sc   = rsqrtf(var + BN_EPS) * gg[c];
        float off  = bb2[c] - mean * sc;
        if (tid < 128) { csc1[c] = sc; cof1[c] = off; }
        else           { csc2[c] = sc; cof2[c] = off; }
        __syncthreads();
    }

    const int nch = K >> 5;
    const int j0 = tid * 2, j1 = tid * 2 + 1;
    const int ar0 = j0 >> 3, ac0 = j0 & 7;
    const int ar1 = j1 >> 3, ac1 = j1 & 7;
    const int brow = tid >> 2, bseg = tid & 3;

    float4 va0, va1, wa0, wa1;
    uint4 vbh, vbl;

    va0 = *(const float4*)&A[(long)(bm + ar0) * K + ac0 * 4];
    va1 = *(const float4*)&A[(long)(bm + ar1) * K + ac1 * 4];
    if (LMODE == 2) {
        wa0 = *(const float4*)&A2[(long)(bm + ar0) * K + ac0 * 4];
        wa1 = *(const float4*)&A2[(long)(bm + ar1) * K + ac1 * 4];
    }
    vbh = *(const uint4*)&Bh[(long)(bn + brow) * K + bseg * 8];
    vbl = *(const uint4*)&Bl[(long)(bn + brow) * K + bseg * 8];

    for (int c = 0; c < nch; c++) {
        const int k0 = c * 32;
        {
            float4 v = va0;
            int cbase = k0 + ac0 * 4;
            if (LMODE == 2) {
                v.x = v.x * csc1[cbase]     + cof1[cbase]     + wa0.x * csc2[cbase]     + cof2[cbase];
                v.y = v.y * csc1[cbase + 1] + cof1[cbase + 1] + wa0.y * csc2[cbase + 1] + cof2[cbase + 1];
                v.z = v.z * csc1[cbase + 2] + cof1[cbase + 2] + wa0.z * csc2[cbase + 2] + cof2[cbase + 2];
                v.w = v.w * csc1[cbase + 3] + cof1[cbase + 3] + wa0.w * csc2[cbase + 3] + cof2[cbase + 3];
                if (blockIdx.x == 0)
                    *(float4*)&hout[(long)(bm + ar0) * K + cbase] = v;
            }
            uint32_t h0, l0, h1, l1;
            split2(v.x, v.y, h0, l0);
            split2(v.z, v.w, h1, l1);
            uint32_t* ph = (uint32_t*)&Ahs[ar0 * AST + ac0 * 4];
            uint32_t* pl = (uint32_t*)&Als[ar0 * AST + ac0 * 4];
            ph[0] = h0; ph[1] = h1;
            pl[0] = l0; pl[1] = l1;
        }
        {
            float4 v = va1;
            int cbase = k0 + ac1 * 4;
            if (LMODE == 2) {
                v.x = v.x * csc1[cbase]     + cof1[cbase]     + wa1.x * csc2[cbase]     + cof2[cbase];
                v.y = v.y * csc1[cbase + 1] + cof1[cbase + 1] + wa1.y * csc2[cbase + 1] + cof2[cbase + 1];
                v.z = v.z * csc1[cbase + 2] + cof1[cbase + 2] + wa1.z * csc2[cbase + 2] + cof2[cbase + 2];
                v.w = v.w * csc1[cbase + 3] + cof1[cbase + 3] + wa1.w * csc2[cbase + 3] + cof2[cbase + 3];
                if (blockIdx.x == 0)
                    *(float4*)&hout[(long)(bm + ar1) * K + cbase] = v;
            }
            uint32_t h0, l0, h1, l1;
            split2(v.x, v.y, h0, l0);
            split2(v.z, v.w, h1, l1);
            uint32_t* ph = (uint32_t*)&Ahs[ar1 * AST + ac1 * 4];
            uint32_t* pl = (uint32_t*)&Als[ar1 * AST + ac1 * 4];
            ph[0] = h0; ph[1] = h1;
            pl[0] = l0; pl[1] = l1;
        }
        *(uint4*)&Bhs[brow * AST + bseg * 8] = vbh;
        *(uint4*)&Bls[brow * AST + bseg * 8] = vbl;
        __syncthreads();

        if (c + 1 < nch) {
            const int kn = (c + 1) * 32;
            va0 = *(const float4*)&A[(long)(bm + ar0) * K + kn + ac0 * 4];
            va1 = *(const float4*)&A[(long)(bm + ar1) * K + kn + ac1 * 4];
            if (LMODE == 2) {
                wa0 = *(const float4*)&A2[(long)(bm + ar0) * K + kn + ac0 * 4];
                wa1 = *(const float4*)&A2[(long)(bm + ar1) * K + kn + ac1 * 4];
            }
            vbh = *(const uint4*)&Bh[(long)(bn + brow) * K + kn + bseg * 8];
            vbl = *(const uint4*)&Bl[(long)(bn + brow) * K + kn + bseg * 8];
        }

#pragma unroll
        for (int ks = 0; ks < 2; ks++) {
            int kk = ks * 16 + tig * 2;
            int r = wm * 16;
            uint32_t ah0 = *(const uint32_t*)&Ahs[(r + gid    ) * AST + kk    ];
            uint32_t ah1 = *(const uint32_t*)&Ahs[(r + gid + 8) * AST + kk    ];
            uint32_t ah2 = *(const uint32_t*)&Ahs[(r + gid    ) * AST + kk + 8];
            uint32_t ah3 = *(const uint32_t*)&Ahs[(r + gid + 8) * AST + kk + 8];
            uint32_t al0 = *(const uint32_t*)&Als[(r + gid    ) * AST + kk    ];
            uint32_t al1 = *(const uint32_t*)&Als[(r + gid + 8) * AST + kk    ];
            uint32_t al2 = *(const uint32_t*)&Als[(r + gid    ) * AST + kk + 8];
            uint32_t al3 = *(const uint32_t*)&Als[(r + gid + 8) * AST + kk + 8];
#pragma unroll
            for (int nb = 0; nb < 4; nb++) {
                int nr = wn * 32 + nb * 8 + gid;
                uint32_t bh0 = *(const uint32_t*)&Bhs[nr * AST + kk    ];
                uint32_t bh1 = *(const uint32_t*)&Bhs[nr * AST + kk + 8];
                uint32_t bl0 = *(const uint32_t*)&Bls[nr * AST + kk    ];
                uint32_t bl1 = *(const uint32_t*)&Bls[nr * AST + kk + 8];
                mma_bf16(acc[nb], ah0, ah1, ah2, ah3, bh0, bh1);
                mma_bf16(acc[nb], ah0, ah1, ah2, ah3, bl0, bl1);
                mma_bf16(acc[nb], al0, al1, al2, al3, bh0, bh1);
            }
        }
        __syncthreads();
    }

    const int rowA = bm + wm * 16 + gid, rowB = rowA + 8;
#pragma unroll
    for (int nb = 0; nb < 4; nb++) {
        int col = bn + wn * 32 + nb * 8 + tig * 2;
        if (col >= N) continue;
        float b0 = bias[col], b1v = bias[col + 1];
        float v0 = acc[nb][0] + b0, v1 = acc[nb][1] + b1v;
        float v2 = acc[nb][2] + b0, v3 = acc[nb][3] + b1v;
        if (EMODE == 1) {
            v0 = fmaxf(v0, 0.f); v1 = fmaxf(v1, 0.f);
            v2 = fmaxf(v2, 0.f); v3 = fmaxf(v3, 0.f);
        }
        if (EMODE == 2) {
            int sec = col >> 7, hh = (col & 127) >> 5, d = col & 31;
            if (sec == 0) {
                *(uint32_t*)&qb[((hh << 12) + rowA) * 32 + d] = pack_bf16(v0, v1);
                *(uint32_t*)&qb[((hh << 12) + rowB) * 32 + d] = pack_bf16(v2, v3);
            } else if (sec == 1) {
                *(uint32_t*)&kbuf[((hh << 12) + rowA) * 32 + d] = pack_bf16(v0, v1);
                *(uint32_t*)&kbuf[((hh << 12) + rowB) * 32 + d] = pack_bf16(v2, v3);
            } else {
                vtb[((hh * 32 + d    ) << 12) + rowA] = __float2bfloat16(v0);
                vtb[((hh * 32 + d + 1) << 12) + rowA] = __float2bfloat16(v1);
                vtb[((hh * 32 + d    ) << 12) + rowB] = __float2bfloat16(v2);
                vtb[((hh * 32 + d + 1) << 12) + rowB] = __float2bfloat16(v3);
            }
        } else if (EMODE == 3) {
            float2 xA = *(const float2*)&xres[(long)rowA * N + col];
            float2 xB = *(const float2*)&xres[(long)rowB * N + col];
            float w0 = v0 + xA.x, w1 = v1 + xA.y;
            float w2 = v2 + xB.x, w3 = v3 + xB.y;
            *(float2*)&C[(long)rowA * N + col] = make_float2(w0, w1);
            *(float2*)&C[(long)rowB * N + col] = make_float2(w2, w3);
            float cs0 = w0 + w2, cs1 = w1 + w3;
            float cq0 = w0 * w0 + w2 * w2, cq1 = w1 * w1 + w3 * w3;
#pragma unroll
            for (int mk = 4; mk < 32; mk <<= 1) {
                cs0 += __shfl_xor_sync(0xFFFFFFFF, cs0, mk);
                cs1 += __shfl_xor_sync(0xFFFFFFFF, cs1, mk);
                cq0 += __shfl_xor_sync(0xFFFFFFFF, cq0, mk);
                cq1 += __shfl_xor_sync(0xFFFFFFFF, cq1, mk);
            }
            if (gid == 0) {
                atomicAdd(&sums_out[col], cs0);
                atomicAdd(&sums_out[CC + col], cq0);
                atomicAdd(&sums_out[col + 1], cs1);
                atomicAdd(&sums_out[CC + col + 1], cq1);
            }
        } else {
            *(float2*)&C[(long)rowA * N + col] = make_float2(v0, v1);
            *(float2*)&C[(long)rowB * N + col] = make_float2(v2, v3);
        }
    }
}

// ---------------- BN affine apply ----------------
__global__ __launch_bounds__(256) void bn_affine(const float* __restrict__ u,
        const float* __restrict__ sums, const float* __restrict__ g,
        const float* __restrict__ b, float* __restrict__ out) {
    int i = blockIdx.x * 256 + threadIdx.x;
    if (i >= NN * 32) return;
    int c4 = i & 31;
    float4 v = ((const float4*)u)[i];
    float o[4] = {v.x, v.y, v.z, v.w};
#pragma unroll
    for (int k = 0; k < 4; k++) {
        int c = c4 * 4 + k;
        float mean = sums[c] * (1.f / NN);
        float var  = sums[CC + c] * (1.f / NN) - mean * mean;
        float sc   = rsqrtf(var + BN_EPS) * g[c];
        o[k] = (o[k] - mean) * sc + b[c];
    }
    ((float4*)out)[i] = make_float4(o[0], o[1], o[2], o[3]);
}

// ---------------- mma.sync flash attention (BQ=128, cp.async double-buffered K/V) ----
#define EXP2_SCALE 0.25503480f
#define QK_STRIDE 40
#define VT_STRIDE 136

__global__ __launch_bounds__(256, 1) void mma_attn(const __nv_bfloat16* __restrict__ qb,
        const __nv_bfloat16* __restrict__ kb, const __nv_bfloat16* __restrict__ vtb,
        float* __restrict__ out) {
    __shared__ uint16_t Qs[128 * QK_STRIDE];
    __shared__ uint16_t Ks[2][128 * QK_STRIDE];
    __shared__ uint16_t Vts[2][32 * VT_STRIDE];

    const int tid = threadIdx.x;
    const int wid = tid >> 5, lane = tid & 31;
    const int gid = lane >> 2, tig = lane & 3;
    const int h = blockIdx.y;
    const int qbase = blockIdx.x * 128;
    const int r0 = wid * 16;

    const uint16_t* Qg = (const uint16_t*)(qb + ((long)h * NN + qbase) * 32);
#pragma unroll
    for (int it = 0; it < 2; it++) {
        int i = tid + it * 256;
        int row = i >> 2, seg = i & 3;
        *(uint4*)&Qs[row * QK_STRIDE + seg * 8] = *(const uint4*)&Qg[row * 32 + seg * 8];
    }

    // prefetch K/V tile into stage st via cp.async
    auto pre_kv = [&](int st, int kb0) {
        const uint16_t* Kg = (const uint16_t*)(kb + ((long)h * NN + kb0) * 32);
#pragma unroll
        for (int it = 0; it < 2; it++) {
            int i = tid + it * 256;
            int row = i >> 2, seg = i & 3;
            CP16(smem_u32(&Ks[st][row * QK_STRIDE + seg * 8]), &Kg[row * 32 + seg * 8]);
        }
        const uint16_t* Vg = (const uint16_t*)(vtb + ((long)h * 32) * NN + kb0);
#pragma unroll
        for (int it = 0; it < 2; it++) {
            int i = tid + it * 256;
            int d = i >> 4, seg = i & 15;
            CP16(smem_u32(&Vts[st][d * VT_STRIDE + seg * 8]), &Vg[(long)d * NN + seg * 8]);
        }
    };

    pre_kv(0, 0);
    CP_COMMIT();
    __syncthreads();

    uint32_t aq[2][4];
#pragma unroll
    for (int t = 0; t < 2; t++) {
        int k = t * 16 + tig * 2;
        aq[t][0] = *(const uint32_t*)&Qs[(r0 + gid    ) * QK_STRIDE + k    ];
        aq[t][1] = *(const uint32_t*)&Qs[(r0 + gid + 8) * QK_STRIDE + k    ];
        aq[t][2] = *(const uint32_t*)&Qs[(r0 + gid    ) * QK_STRIDE + k + 8];
        aq[t][3] = *(const uint32_t*)&Qs[(r0 + gid + 8) * QK_STRIDE + k + 8];
    }

    float oacc[4][4] = {};
    float rs0 = 0.f, rs1 = 0.f;

    for (int kt = 0; kt < NN / 128; kt++) {
        const int st = kt & 1;
        if (kt + 1 < NN / 128) {
            pre_kv(st ^ 1, (kt + 1) * 128);
            CP_COMMIT();
            CP_WAIT1();
        } else {
            CP_WAIT0();
        }
        __syncthreads();

        float sacc[16][4];
#pragma unroll
        for (int j = 0; j < 16; j++) { sacc[j][0] = sacc[j][1] = sacc[j][2] = sacc[j][3] = 0.f; }
#pragma unroll
        for (int j = 0; j < 16; j++) {
#pragma unroll
            for (int t = 0; t < 2; t++) {
                int k = t * 16 + tig * 2;
                uint32_t b0 = *(const uint32_t*)&Ks[st][(8 * j + gid) * QK_STRIDE + k    ];
                uint32_t b1 = *(const uint32_t*)&Ks[st][(8 * j + gid) * QK_STRIDE + k + 8];
                mma_bf16(sacc[j], aq[t][0], aq[t][1], aq[t][2], aq[t][3], b0, b1);
            }
        }

        uint32_t pf[16][2];
#pragma unroll
        for (int j = 0; j < 16; j++) {
            float p0 = fast_exp2(sacc[j][0] * EXP2_SCALE);
            float p1 = fast_exp2(sacc[j][1] * EXP2_SCALE);
            float p2 = fast_exp2(sacc[j][2] * EXP2_SCALE);
            float p3 = fast_exp2(sacc[j][3] * EXP2_SCALE);
            rs0 += p0 + p1;
            rs1 += p2 + p3;
            pf[j][0] = pack_bf16(p0, p1);
            pf[j][1] = pack_bf16(p2, p3);
        }

#pragma unroll
        for (int t = 0; t < 8; t++) {
            uint32_t a0 = pf[2 * t][0], a1 = pf[2 * t][1];
            uint32_t a2 = pf[2 * t + 1][0], a3 = pf[2 * t + 1][1];
            int k = t * 16 + tig * 2;
#pragma unroll
            for (int n = 0; n < 4; n++) {
                uint32_t b0 = *(const uint32_t*)&Vts[st][(8 * n + gid) * VT_STRIDE + k    ];
                uint32_t b1 = *(const uint32_t*)&Vts[st][(8 * n + gid) * VT_STRIDE + k + 8];
                mma_bf16(oacc[n], a0, a1, a2, a3, b0, b1);
            }
        }
        __syncthreads();   // all reads of stage st done before kt+2 prefetch overwrites it
    }

    rs0 += __shfl_xor_sync(0xFFFFFFFF, rs0, 1);
    rs0 += __shfl_xor_sync(0xFFFFFFFF, rs0, 2);
    rs1 += __shfl_xor_sync(0xFFFFFFFF, rs1, 1);
    rs1 += __shfl_xor_sync(0xFFFFFFFF, rs1, 2);
    float inv0 = 1.f / rs0, inv1 = 1.f / rs1;

    int rowA = qbase + r0 + gid, rowB = rowA + 8;
    float* poA = out + (long)rowA * CC + h * 32 + tig * 2;
    float* poB = out + (long)rowB * CC + h * 32 + tig * 2;
#pragma unroll
    for (int n = 0; n < 4; n++) {
        *(float2*)(poA + n * 8) = make_float2(oacc[n][0] * inv0, oacc[n][1] * inv0);
        *(float2*)(poB + n * 8) = make_float2(oacc[n][2] * inv1, oacc[n][3] * inv1);
    }
}

// ---------------- head MLP: warp-per-node, low smem ----------------
__global__ __launch_bounds__(256) void head_warp(const float* __restrict__ x,
        const float* __restrict__ w1, const float* __restrict__ b1,
        const float* __restrict__ w2, const float* __restrict__ b2,
        const float* __restrict__ w3, const float* __restrict__ b3,
        float* __restrict__ out) {
    __shared__ float y1s[8][64];
    __shared__ float y2s[8][32];
    int tid = threadIdx.x;
    int wid = tid >> 5, lane = tid & 31;
    int n = blockIdx.x * 8 + wid;

    float4 xv = *(const float4*)&x[(long)n * 128 + lane * 4];

    for (int o = 0; o < 64; o++) {
        float4 wv = *(const float4*)&w1[o * 128 + lane * 4];
        float p = xv.x * wv.x + xv.y * wv.y + xv.z * wv.z + xv.w * wv.w;
#pragma unroll
        for (int mk = 16; mk > 0; mk >>= 1) p += __shfl_xor_sync(0xFFFFFFFF, p, mk);
        if (lane == 0) y1s[wid][o] = fmaxf(p + b1[o], 0.f);
    }
    __syncwarp();
    float ya = y1s[wid][lane * 2], yb = y1s[wid][lane * 2 + 1];
    for (int o = 0; o < 32; o++) {
        float2 wv = *(const float2*)&w2[o * 64 + lane * 2];
        float p = ya * wv.x + yb * wv.y;
#pragma unroll
        for (int mk = 16; mk > 0; mk >>= 1) p += __shfl_xor_sync(0xFFFFFFFF, p, mk);
        if (lane == 0) y2s[wid][o] = fmaxf(p + b2[o], 0.f);
    }
    __syncwarp();
    float p = y2s[wid][lane] * w3[lane];
#pragma unroll
    for (int mk = 16; mk > 0; mk >>= 1) p += __shfl_xor_sync(0xFFFFFFFF, p, mk);
    if (lane == 0) out[n] = p + b3[0];
}

// ---------------- host orchestration ----------------
static __nv_bfloat16 *s_whi, *s_wlo;

extern "C" void kernel_launch(void* const* d_in, const int* in_sizes, int n_in,
                              void* d_out, int out_size) {
    const float* x_in      = (const float*)d_in[0];
    const int*   edge      = (const int*)  d_in[1];
    const float* gin_w1    = (const float*)d_in[2];
    const float* gin_b1    = (const float*)d_in[3];
    const float* gin_w2    = (const float*)d_in[4];
    const float* gin_b2    = (const float*)d_in[5];
    const float* attn_in_w = (const float*)d_in[6];
    const float* attn_in_b = (const float*)d_in[7];
    const float* attn_o_w  = (const float*)d_in[8];
    const float* attn_o_b  = (const float*)d_in[9];
    const float* n1_g = (const float*)d_in[10];
    const float* n1_b = (const float*)d_in[11];
    const float* n2_g = (const float*)d_in[12];
    const float* n2_b = (const float*)d_in[13];
    const float* n3_g = (const float*)d_in[14];
    const float* n3_b = (const float*)d_in[15];
    const float* mlp_w1 = (const float*)d_in[16];
    const float* mlp_b1 = (const float*)d_in[17];
    const float* mlp_w2 = (const float*)d_in[18];
    const float* mlp_b2 = (const float*)d_in[19];
    const float* hw1 = (const float*)d_in[20];
    const float* hb1 = (const float*)d_in[21];
    const float* hw2 = (const float*)d_in[22];
    const float* hb2 = (const float*)d_in[23];
    const float* hw3 = (const float*)d_in[24];
    const float* hb3 = (const float*)d_in[25];
    float* out = (float*)d_out;

    int E = in_sizes[1] / 2;

    float *p_x, *p_agg, *p_t1, *p_t2, *p_h1, *p_h2, *p_sums;
    int *p_deg;
    __nv_bfloat16 *p_qb, *p_kb, *p_vtb;
    cudaGetSymbolAddress((void**)&p_x,  g_x);
    cudaGetSymbolAddress((void**)&p_agg, g_agg);
    cudaGetSymbolAddress((void**)&p_t1, g_t1);
    cudaGetSymbolAddress((void**)&p_t2, g_t2);
    cudaGetSymbolAddress((void**)&p_h1, g_h1);
    cudaGetSymbolAddress((void**)&p_h2, g_h2);
    cudaGetSymbolAddress((void**)&p_sums, g_bnsums);
    cudaGetSymbolAddress((void**)&p_deg, g_deg);
    cudaGetSymbolAddress((void**)&p_qb, g_qb);
    cudaGetSymbolAddress((void**)&p_kb, g_kb);
    cudaGetSymbolAddress((void**)&p_vtb, g_vtb);
    cudaGetSymbolAddress((void**)&s_whi, g_whi);
    cudaGetSymbolAddress((void**)&s_wlo, g_wlo);

    conv_w<<<(WTOTAL + 255) / 256, 256>>>(gin_w1, gin_w2, attn_in_w, attn_o_w, mlp_w1, mlp_w2);
    cudaMemsetAsync(p_sums, 0, 12 * 2 * CC * sizeof(float));
    cudaMemsetAsync(p_deg, 0, (NN + 1) * sizeof(int));
    hist_kernel<<<(E + 255) / 256, 256>>>(edge, E);
    scan_kernel<<<1, 1024>>>();
    fill_kernel<<<(E + 255) / 256, 256>>>(edge, E);

    for (int i = 0; i < LL; i++) {
        const float* xcur = (i == 0) ? x_in : p_x;   // layer 0 reads input directly
        const float* gb1 = gin_b1 + (long)i * CC;
        const float* gb2 = gin_b2 + (long)i * CC;
        const float* aib = attn_in_b + (long)i * 3 * CC;
        const float* aob = attn_o_b + (long)i * CC;
        const float* mb1 = mlp_b1 + (long)i * 2 * CC;
        const float* mb2 = mlp_b2 + (long)i * CC;
        float* s1 = p_sums + (3 * i + 0) * 2 * CC;
        float* s2 = p_sums + (3 * i + 1) * 2 * CC;
        float* s3 = p_sums + (3 * i + 2) * 2 * CC;

        // ---- GIN branch ----
        gather_kernel<<<NN / 8, 256>>>(xcur, p_agg);
        gemm_tc<0, 1><<<dim3(2, 64), 256>>>(p_agg, nullptr,
            s_whi + WOFF_GIN1 + i * CC * CC, s_wlo + WOFF_GIN1 + i * CC * CC, gb1, p_t1,
            nullptr, nullptr, nullptr, nullptr, nullptr,
            nullptr, nullptr, nullptr, nullptr, nullptr, nullptr, nullptr, NN, CC, CC);
        gemm_tc<0, 3><<<dim3(2, 64), 256>>>(p_t1, nullptr,
            s_whi + WOFF_GIN2 + i * CC * CC, s_wlo + WOFF_GIN2 + i * CC * CC, gb2, p_h1,
            nullptr, nullptr, nullptr, xcur, s1,
            nullptr, nullptr, nullptr, nullptr, nullptr, nullptr, nullptr, NN, CC, CC);

        // ---- attention branch ----
        gemm_tc<0, 2><<<dim3(6, 64), 256>>>(xcur, nullptr,
            s_whi + WOFF_AIN + i * 3 * CC * CC, s_wlo + WOFF_AIN + i * 3 * CC * CC, aib, nullptr,
            p_qb, p_kb, p_vtb, nullptr, nullptr,
            nullptr, nullptr, nullptr, nullptr, nullptr, nullptr, nullptr, NN, 3 * CC, CC);
        mma_attn<<<dim3(NN / 128, HEADS), 256>>>(p_qb, p_kb, p_vtb, p_agg);
        gemm_tc<0, 3><<<dim3(2, 64), 256>>>(p_agg, nullptr,
            s_whi + WOFF_AOUT + i * CC * CC, s_wlo + WOFF_AOUT + i * CC * CC, aob, p_h2,
            nullptr, nullptr, nullptr, xcur, s2,
            nullptr, nullptr, nullptr, nullptr, nullptr, nullptr, nullptr, NN, CC, CC);

        // ---- MLP ----
        gemm_tc<2, 1><<<dim3(4, 64), 256>>>(p_h1, p_h2,
            s_whi + WOFF_MW1 + i * 2 * CC * CC, s_wlo + WOFF_MW1 + i * 2 * CC * CC, mb1, p_t1,
            nullptr, nullptr, nullptr, nullptr, nullptr,
            s1, n1_g + i * CC, n1_b + i * CC, s2, n2_g + i * CC, n2_b + i * CC,
            p_t2, NN, 2 * CC, CC);
        gemm_tc<0, 3><<<dim3(2, 64), 256>>>(p_t1, nullptr,
            s_whi + WOFF_MW2 + i * 2 * CC * CC, s_wlo + WOFF_MW2 + i * 2 * CC * CC, mb2, p_agg,
            nullptr, nullptr, nullptr, p_t2, s3,
            nullptr, nullptr, nullptr, nullptr, nullptr, nullptr, nullptr, NN, CC, 2 * CC);
        bn_affine<<<NN * 32 / 256, 256>>>(p_agg, s3, n3_g + i * CC, n3_b + i * CC, p_x);
    }

    // ---- head ----
    head_warp<<<NN / 8, 256>>>(p_x, hw1, hb1, hw2, hb2, hw3, hb3, out);
}

// round 14
// speedup vs baseline: 1.3037x; 1.0809x over previous
#include <cuda_runtime.h>
#include <cuda_bf16.h>
#include <cstdint>

#define NN 4096
#define CC 128
#define LL 4
#define HEADS 4
#define BN_EPS 1e-5f
#define EMAX 262144

// ---------------- scratch (static device globals; no allocation) ----------------
__device__ float g_x  [NN * CC];
__device__ float g_agg[NN * CC];
__device__ float g_t1 [NN * 384];
__device__ float g_t2 [NN * CC];
__device__ float g_h1 [NN * CC];
__device__ float g_h2 [NN * CC];
__device__ float g_bnsums[12 * 2 * CC];
__device__ int   g_deg[NN + 1];
__device__ int   g_cur[NN];
__device__ int   g_csr[EMAX];
__device__ __nv_bfloat16 g_qb [HEADS * NN * 32];
__device__ __nv_bfloat16 g_kb [HEADS * NN * 32];
__device__ __nv_bfloat16 g_vtb[HEADS * 32 * NN];

// concatenated hi/lo bf16 weights
#define WOFF_GIN1 0
#define WOFF_GIN2 65536
#define WOFF_AIN  131072
#define WOFF_AOUT 327680
#define WOFF_MW1  393216
#define WOFF_MW2  524288
#define WTOTAL    655360
__device__ __nv_bfloat16 g_whi[WTOTAL];
__device__ __nv_bfloat16 g_wlo[WTOTAL];

// ---------------- mma.sync / ptx helpers ----------------
__device__ __forceinline__ void mma_bf16(float* d, uint32_t a0, uint32_t a1, uint32_t a2,
                                         uint32_t a3, uint32_t b0, uint32_t b1) {
    asm volatile(
        "mma.sync.aligned.m16n8k16.row.col.f32.bf16.bf16.f32 "
        "{%0,%1,%2,%3}, {%4,%5,%6,%7}, {%8,%9}, {%0,%1,%2,%3};"
        : "+f"(d[0]), "+f"(d[1]), "+f"(d[2]), "+f"(d[3])
        : "r"(a0), "r"(a1), "r"(a2), "r"(a3), "r"(b0), "r"(b1));
}
__device__ __forceinline__ float fast_exp2(float x) {
    float y; asm("ex2.approx.ftz.f32 %0, %1;" : "=f"(y) : "f"(x)); return y;
}
__device__ __forceinline__ uint32_t pack_bf16(float lo, float hi) {
    uint32_t r; asm("cvt.rn.bf16x2.f32 %0, %1, %2;" : "=r"(r) : "f"(hi), "f"(lo)); return r;
}
__device__ __forceinline__ void split2(float x, float y, uint32_t& hi, uint32_t& lo) {
    __nv_bfloat16 hx = __float2bfloat16(x), hy = __float2bfloat16(y);
    float lx = x - __bfloat162float(hx), ly = y - __bfloat162float(hy);
    hi = pack_bf16(__bfloat162float(hx), __bfloat162float(hy));
    lo = pack_bf16(lx, ly);
}
__device__ __forceinline__ uint32_t smem_u32(const void* p) {
    return (uint32_t)__cvta_generic_to_shared(p);
}
#define CP16(dst_u32, src) \
    asm volatile("cp.async.cg.shared.global [%0], [%1], 16;" :: "r"(dst_u32), "l"(src))
#define CP_COMMIT() asm volatile("cp.async.commit_group;")
#define CP_WAIT1()  asm volatile("cp.async.wait_group 1;")
#define CP_WAIT0()  asm volatile("cp.async.wait_group 0;")

// ---------------- weight hi/lo conversion ----------------
__global__ void conv_w(const float* __restrict__ w_gin1, const float* __restrict__ w_gin2,
                       const float* __restrict__ w_ain,  const float* __restrict__ w_aout,
                       const float* __restrict__ w_m1,   const float* __restrict__ w_m2) {
    int id = blockIdx.x * 256 + threadIdx.x;
    if (id >= WTOTAL) return;
    const float* src; int off;
    if      (id < WOFF_GIN2) { src = w_gin1; off = id; }
    else if (id < WOFF_AIN)  { src = w_gin2; off = id - WOFF_GIN2; }
    else if (id < WOFF_AOUT) { src = w_ain;  off = id - WOFF_AIN; }
    else if (id < WOFF_MW1)  { src = w_aout; off = id - WOFF_AOUT; }
    else if (id < WOFF_MW2)  { src = w_m1;   off = id - WOFF_MW1; }
    else                     { src = w_m2;   off = id - WOFF_MW2; }
    float v = src[off];
    __nv_bfloat16 h = __float2bfloat16(v);
    g_whi[id] = h;
    g_wlo[id] = __float2bfloat16(v - __bfloat162float(h));
}

// ---------------- CSR build ----------------
__global__ void hist_kernel(const int* __restrict__ ei, int E) {
    int e = blockIdx.x * blockDim.x + threadIdx.x;
    if (e < E) atomicAdd(&g_deg[ei[E + e] + 1], 1);
}

__global__ void scan_kernel() {
    __shared__ int part[1024];
    int t = threadIdx.x;
    int base = t * 4;
    int x0 = g_deg[base], x1 = g_deg[base + 1], x2 = g_deg[base + 2], x3 = g_deg[base + 3];
    x1 += x0; x2 += x1; x3 += x2;
    part[t] = x3;
    __syncthreads();
    for (int off = 1; off < 1024; off <<= 1) {
        int v = (t >= off) ? part[t - off] : 0;
        __syncthreads();
        part[t] += v;
        __syncthreads();
    }
    int add = (t > 0) ? part[t - 1] : 0;
    int v0 = x0 + add, v1 = x1 + add, v2 = x2 + add, v3 = x3 + add;
    g_deg[base] = v0; g_deg[base + 1] = v1; g_deg[base + 2] = v2; g_deg[base + 3] = v3;
    g_cur[base] = v0; g_cur[base + 1] = v1; g_cur[base + 2] = v2; g_cur[base + 3] = v3;
    __syncthreads();
    if (t == 0) g_deg[NN] += g_deg[NN - 1];
}

__global__ void fill_kernel(const int* __restrict__ ei, int E) {
    int e = blockIdx.x * blockDim.x + threadIdx.x;
    if (e >= E) return;
    int s = ei[e], d = ei[E + e];
    int pos = atomicAdd(&g_cur[d], 1);
    g_csr[pos] = s;
}

// ---------------- GIN gather ----------------
__global__ __launch_bounds__(256) void gather_kernel(const float* __restrict__ x,
                                                     float* __restrict__ agg) {
    int wg = (blockIdx.x * 256 + threadIdx.x) >> 5;
    int lane = threadIdx.x & 31;
    if (wg >= NN) return;
    int beg = g_deg[wg], end = g_deg[wg + 1];
    float4 acc = *(const float4*)&x[(long)wg * CC + lane * 4];
    for (int j = beg; j < end; j++) {
        int s = g_csr[j];
        float4 v = *(const float4*)&x[(long)s * CC + lane * 4];
        acc.x += v.x; acc.y += v.y; acc.z += v.z; acc.w += v.w;
    }
    *(float4*)&agg[(long)wg * CC + lane * 4] = acc;
}

// ---------------- tensor-core GEMM (hi/lo split, register-prefetch) — R13 proven ------
#define AST 40
template <int LMODE, int EMODE>
__global__ __launch_bounds__(256) void gemm_tc(const float* __restrict__ A,
        const float* __restrict__ A2,
        const __nv_bfloat16* __restrict__ Bh, const __nv_bfloat16* __restrict__ Bl,
        const float* __restrict__ bias, float* __restrict__ C,
        __nv_bfloat16* __restrict__ qb, __nv_bfloat16* __restrict__ kbuf,
        __nv_bfloat16* __restrict__ vtb,
        const float* __restrict__ xres, float* __restrict__ sums_out,
        const float* __restrict__ s1, const float* __restrict__ g1, const float* __restrict__ b1,
        const float* __restrict__ s2, const float* __restrict__ g2, const float* __restrict__ b2,
        float* __restrict__ hout, int M, int N, int K) {
    __shared__ uint16_t Ahs[64 * AST], Als[64 * AST];
    __shared__ uint16_t Bhs[64 * AST], Bls[64 * AST];
    __shared__ float csc1[128], cof1[128], csc2[128], cof2[128];
    const int tid = threadIdx.x;
    const int warp = tid >> 5, lane = tid & 31;
    const int gid = lane >> 2, tig = lane & 3;
    const int wm = warp >> 1, wn = warp & 1;
    const int bm = blockIdx.y * 64, bn = blockIdx.x * 64;
    float acc[4][4] = {};

    if (LMODE == 2) {
        int c = tid & 127;
        const float* ss = (tid < 128) ? s1 : s2;
        const float* gg = (tid < 128) ? g1 : g2;
        const float* bb2 = (tid < 128) ? b1 : b2;
        float mean = ss[c] * (1.f / NN);
        float var  = ss[CC + c] * (1.f / NN) - mean * mean;
        float sc   = rsqrtf(var + BN_EPS) * gg[c];
        float off  = bb2[c] - mean * sc;
        if (tid < 128) { csc1[c] = sc; cof1[c] = off; }
        else           { csc2[c] = sc; cof2[c] = off; }
        __syncthreads();
    }

    const int nch = K >> 5;
    const int j0 = tid * 2, j1 = tid * 2 + 1;
    const int ar0 = j0 >> 3, ac0 = j0 & 7;
    const int ar1 = j1 >> 3, ac1 = j1 & 7;
    const int brow = tid >> 2, bseg = tid & 3;

    float4 va0, va1, wa0, wa1;
    uint4 vbh, vbl;

    va0 = *(const float4*)&A[(long)(bm + ar0) * K + ac0 * 4];
    va1 = *(const float4*)&A[(long)(bm + ar1) * K + ac1 * 4];
    if (LMODE == 2) {
        wa0 = *(const float4*)&A2[(long)(bm + ar0) * K + ac0 * 4];
        wa1 = *(const float4*)&A2[(long)(bm + ar1) * K + ac1 * 4];
    }
    vbh = *(const uint4*)&Bh[(long)(bn + brow) * K + bseg * 8];
    vbl = *(const uint4*)&Bl[(long)(bn + brow) * K + bseg * 8];

    for (int c = 0; c < nch; c++) {
        const int k0 = c * 32;
        {
            float4 v = va0;
            int cbase = k0 + ac0 * 4;
            if (LMODE == 2) {
                v.x = v.x * csc1[cbase]     + cof1[cbase]     + wa0.x * csc2[cbase]     + cof2[cbase];
                v.y = v.y * csc1[cbase + 1] + cof1[cbase + 1] + wa0.y * csc2[cbase + 1] + cof2[cbase + 1];
                v.z = v.z * csc1[cbase + 2] + cof1[cbase + 2] + wa0.z * csc2[cbase + 2] + cof2[cbase + 2];
                v.w = v.w * csc1[cbase + 3] + cof1[cbase + 3] + wa0.w * csc2[cbase + 3] + cof2[cbase + 3];
                if (blockIdx.x == 0)
                    *(float4*)&hout[(long)(bm + ar0) * K + cbase] = v;
            }
            uint32_t h0, l0, h1, l1;
            split2(v.x, v.y, h0, l0);
            split2(v.z, v.w, h1, l1);
            uint32_t* ph = (uint32_t*)&Ahs[ar0 * AST + ac0 * 4];
            uint32_t* pl = (uint32_t*)&Als[ar0 * AST + ac0 * 4];
            ph[0] = h0; ph[1] = h1;
            pl[0] = l0; pl[1] = l1;
        }
        {
            float4 v = va1;
            int cbase = k0 + ac1 * 4;
            if (LMODE == 2) {
                v.x = v.x * csc1[cbase]     + cof1[cbase]     + wa1.x * csc2[cbase]     + cof2[cbase];
                v.y = v.y * csc1[cbase + 1] + cof1[cbase + 1] + wa1.y * csc2[cbase + 1] + cof2[cbase + 1];
                v.z = v.z * csc1[cbase + 2] + cof1[cbase + 2] + wa1.z * csc2[cbase + 2] + cof2[cbase + 2];
                v.w = v.w * csc1[cbase + 3] + cof1[cbase + 3] + wa1.w * csc2[cbase + 3] + cof2[cbase + 3];
                if (blockIdx.x == 0)
                    *(float4*)&hout[(long)(bm + ar1) * K + cbase] = v;
            }
            uint32_t h0, l0, h1, l1;
            split2(v.x, v.y, h0, l0);
            split2(v.z, v.w, h1, l1);
            uint32_t* ph = (uint32_t*)&Ahs[ar1 * AST + ac1 * 4];
            uint32_t* pl = (uint32_t*)&Als[ar1 * AST + ac1 * 4];
            ph[0] = h0; ph[1] = h1;
            pl[0] = l0; pl[1] = l1;
        }
        *(uint4*)&Bhs[brow * AST + bseg * 8] = vbh;
        *(uint4*)&Bls[brow * AST + bseg * 8] = vbl;
        __syncthreads();

        if (c + 1 < nch) {
            const int kn = (c + 1) * 32;
            va0 = *(const float4*)&A[(long)(bm + ar0) * K + kn + ac0 * 4];
            va1 = *(const float4*)&A[(long)(bm + ar1) * K + kn + ac1 * 4];
            if (LMODE == 2) {
                wa0 = *(const float4*)&A2[(long)(bm + ar0) * K + kn + ac0 * 4];
                wa1 = *(const float4*)&A2[(long)(bm + ar1) * K + kn + ac1 * 4];
            }
            vbh = *(const uint4*)&Bh[(long)(bn + brow) * K + kn + bseg * 8];
            vbl = *(const uint4*)&Bl[(long)(bn + brow) * K + kn + bseg * 8];
        }

#pragma unroll
        for (int ks = 0; ks < 2; ks++) {
            int kk = ks * 16 + tig * 2;
            int r = wm * 16;
            uint32_t ah0 = *(const uint32_t*)&Ahs[(r + gid    ) * AST + kk    ];
            uint32_t ah1 = *(const uint32_t*)&Ahs[(r + gid + 8) * AST + kk    ];
            uint32_t ah2 = *(const uint32_t*)&Ahs[(r + gid    ) * AST + kk + 8];
            uint32_t ah3 = *(const uint32_t*)&Ahs[(r + gid + 8) * AST + kk + 8];
            uint32_t al0 = *(const uint32_t*)&Als[(r + gid    ) * AST + kk    ];
            uint32_t al1 = *(const uint32_t*)&Als[(r + gid + 8) * AST + kk    ];
            uint32_t al2 = *(const uint32_t*)&Als[(r + gid    ) * AST + kk + 8];
            uint32_t al3 = *(const uint32_t*)&Als[(r + gid + 8) * AST + kk + 8];
#pragma unroll
            for (int nb = 0; nb < 4; nb++) {
                int nr = wn * 32 + nb * 8 + gid;
                uint32_t bh0 = *(const uint32_t*)&Bhs[nr * AST + kk    ];
                uint32_t bh1 = *(const uint32_t*)&Bhs[nr * AST + kk + 8];
                uint32_t bl0 = *(const uint32_t*)&Bls[nr * AST + kk    ];
                uint32_t bl1 = *(const uint32_t*)&Bls[nr * AST + kk + 8];
                mma_bf16(acc[nb], ah0, ah1, ah2, ah3, bh0, bh1);
                mma_bf16(acc[nb], ah0, ah1, ah2, ah3, bl0, bl1);
                mma_bf16(acc[nb], al0, al1, al2, al3, bh0, bh1);
            }
        }
        __syncthreads();
    }

    const int rowA = bm + wm * 16 + gid, rowB = rowA + 8;
#pragma unroll
    for (int nb = 0; nb < 4; nb++) {
        int col = bn + wn * 32 + nb * 8 + tig * 2;
        if (col >= N) continue;
        float b0 = bias[col], b1v = bias[col + 1];
        float v0 = acc[nb][0] + b0, v1 = acc[nb][1] + b1v;
        float v2 = acc[nb][2] + b0, v3 = acc[nb][3] + b1v;
        if (EMODE == 1) {
            v0 = fmaxf(v0, 0.f); v1 = fmaxf(v1, 0.f);
            v2 = fmaxf(v2, 0.f); v3 = fmaxf(v3, 0.f);
        }
        if (EMODE == 2) {
            int sec = col >> 7, hh = (col & 127) >> 5, d = col & 31;
            if (sec == 0) {
                *(uint32_t*)&qb[((hh << 12) + rowA) * 32 + d] = pack_bf16(v0, v1);
                *(uint32_t*)&qb[((hh << 12) + rowB) * 32 + d] = pack_bf16(v2, v3);
            } else if (sec == 1) {
                *(uint32_t*)&kbuf[((hh << 12) + rowA) * 32 + d] = pack_bf16(v0, v1);
                *(uint32_t*)&kbuf[((hh << 12) + rowB) * 32 + d] = pack_bf16(v2, v3);
            } else {
                vtb[((hh * 32 + d    ) << 12) + rowA] = __float2bfloat16(v0);
                vtb[((hh * 32 + d + 1) << 12) + rowA] = __float2bfloat16(v1);
                vtb[((hh * 32 + d    ) << 12) + rowB] = __float2bfloat16(v2);
                vtb[((hh * 32 + d + 1) << 12) + rowB] = __float2bfloat16(v3);
            }
        } else if (EMODE == 3) {
            float2 xA = *(const float2*)&xres[(long)rowA * N + col];
            float2 xB = *(const float2*)&xres[(long)rowB * N + col];
            float w0 = v0 + xA.x, w1 = v1 + xA.y;
            float w2 = v2 + xB.x, w3 = v3 + xB.y;
            *(float2*)&C[(long)rowA * N + col] = make_float2(w0, w1);
            *(float2*)&C[(long)rowB * N + col] = make_float2(w2, w3);
            float cs0 = w0 + w2, cs1 = w1 + w3;
            float cq0 = w0 * w0 + w2 * w2, cq1 = w1 * w1 + w3 * w3;
#pragma unroll
            for (int mk = 4; mk < 32; mk <<= 1) {
                cs0 += __shfl_xor_sync(0xFFFFFFFF, cs0, mk);
                cs1 += __shfl_xor_sync(0xFFFFFFFF, cs1, mk);
                cq0 += __shfl_xor_sync(0xFFFFFFFF, cq0, mk);
                cq1 += __shfl_xor_sync(0xFFFFFFFF, cq1, mk);
            }
            if (gid == 0) {
                atomicAdd(&sums_out[col], cs0);
                atomicAdd(&sums_out[CC + col], cq0);
                atomicAdd(&sums_out[col + 1], cs1);
                atomicAdd(&sums_out[CC + col + 1], cq1);
            }
        } else {
            *(float2*)&C[(long)rowA * N + col] = make_float2(v0, v1);
            *(float2*)&C[(long)rowB * N + col] = make_float2(v2, v3);
        }
    }
}

// ---------------- dual EMODE-3 GEMM: gin2 (blocks 0..127) || aout (blocks 128..255) ----
// Identical body to gemm_tc<0,3> with M=NN, N=K=CC (nch=4). Pointer set chosen by range.
__global__ __launch_bounds__(256) void gemm_dual_e3(
        const float* __restrict__ A_a, const __nv_bfloat16* __restrict__ Bh_a,
        const __nv_bfloat16* __restrict__ Bl_a, const float* __restrict__ bias_a,
        float* __restrict__ C_a, float* __restrict__ sums_a,
        const float* __restrict__ A_b, const __nv_bfloat16* __restrict__ Bh_b,
        const __nv_bfloat16* __restrict__ Bl_b, const float* __restrict__ bias_b,
        float* __restrict__ C_b, float* __restrict__ sums_b,
        const float* __restrict__ xres) {
    __shared__ uint16_t Ahs[64 * AST], Als[64 * AST];
    __shared__ uint16_t Bhs[64 * AST], Bls[64 * AST];

    const int half = (blockIdx.x >= 128);
    const int lb = blockIdx.x & 127;
    const float* A = half ? A_b : A_a;
    const __nv_bfloat16* Bh = half ? Bh_b : Bh_a;
    const __nv_bfloat16* Bl = half ? Bl_b : Bl_a;
    const float* bias = half ? bias_b : bias_a;
    float* C = half ? C_b : C_a;
    float* sums_out = half ? sums_b : sums_a;

    const int tid = threadIdx.x;
    const int warp = tid >> 5, lane = tid & 31;
    const int gid = lane >> 2, tig = lane & 3;
    const int wm = warp >> 1, wn = warp & 1;
    const int bm = (lb >> 1) * 64, bn = (lb & 1) * 64;
    const int K = CC, N = CC;
    float acc[4][4] = {};

    const int j0 = tid * 2, j1 = tid * 2 + 1;
    const int ar0 = j0 >> 3, ac0 = j0 & 7;
    const int ar1 = j1 >> 3, ac1 = j1 & 7;
    const int brow = tid >> 2, bseg = tid & 3;

    float4 va0, va1;
    uint4 vbh, vbl;
    va0 = *(const float4*)&A[(long)(bm + ar0) * K + ac0 * 4];
    va1 = *(const float4*)&A[(long)(bm + ar1) * K + ac1 * 4];
    vbh = *(const uint4*)&Bh[(long)(bn + brow) * K + bseg * 8];
    vbl = *(const uint4*)&Bl[(long)(bn + brow) * K + bseg * 8];

#pragma unroll
    for (int c = 0; c < 4; c++) {
        {
            float4 v = va0;
            uint32_t h0, l0, h1, l1;
            split2(v.x, v.y, h0, l0);
            split2(v.z, v.w, h1, l1);
            uint32_t* ph = (uint32_t*)&Ahs[ar0 * AST + ac0 * 4];
            uint32_t* pl = (uint32_t*)&Als[ar0 * AST + ac0 * 4];
            ph[0] = h0; ph[1] = h1;
            pl[0] = l0; pl[1] = l1;
        }
        {
            float4 v = va1;
            uint32_t h0, l0, h1, l1;
            split2(v.x, v.y, h0, l0);
            split2(v.z, v.w, h1, l1);
            uint32_t* ph = (uint32_t*)&Ahs[ar1 * AST + ac1 * 4];
            uint32_t* pl = (uint32_t*)&Als[ar1 * AST + ac1 * 4];
            ph[0] = h0; ph[1] = h1;
            pl[0] = l0; pl[1] = l1;
        }
        *(uint4*)&Bhs[brow * AST + bseg * 8] = vbh;
        *(uint4*)&Bls[brow * AST + bseg * 8] = vbl;
        __syncthreads();

        if (c + 1 < 4) {
            const int kn = (c + 1) * 32;
            va0 = *(const float4*)&A[(long)(bm + ar0) * K + kn + ac0 * 4];
            va1 = *(const float4*)&A[(long)(bm + ar1) * K + kn + ac1 * 4];
            vbh = *(const uint4*)&Bh[(long)(bn + brow) * K + kn + bseg * 8];
            vbl = *(const uint4*)&Bl[(long)(bn + brow) * K + kn + bseg * 8];
        }

#pragma unroll
        for (int ks = 0; ks < 2; ks++) {
            int kk = ks * 16 + tig * 2;
            int r = wm * 16;
            uint32_t ah0 = *(const uint32_t*)&Ahs[(r + gid    ) * AST + kk    ];
            uint32_t ah1 = *(const uint32_t*)&Ahs[(r + gid + 8) * AST + kk    ];
            uint32_t ah2 = *(const uint32_t*)&Ahs[(r + gid    ) * AST + kk + 8];
            uint32_t ah3 = *(const uint32_t*)&Ahs[(r + gid + 8) * AST + kk + 8];
            uint32_t al0 = *(const uint32_t*)&Als[(r + gid    ) * AST + kk    ];
            uint32_t al1 = *(const uint32_t*)&Als[(r + gid + 8) * AST + kk    ];
            uint32_t al2 = *(const uint32_t*)&Als[(r + gid    ) * AST + kk + 8];
            uint32_t al3 = *(const uint32_t*)&Als[(r + gid + 8) * AST + kk + 8];
#pragma unroll
            for (int nb = 0; nb < 4; nb++) {
                int nr = wn * 32 + nb * 8 + gid;
                uint32_t bh0 = *(const uint32_t*)&Bhs[nr * AST + kk    ];
                uint32_t bh1 = *(const uint32_t*)&Bhs[nr * AST + kk + 8];
                uint32_t bl0 = *(const uint32_t*)&Bls[nr * AST + kk    ];
                uint32_t bl1 = *(const uint32_t*)&Bls[nr * AST + kk + 8];
                mma_bf16(acc[nb], ah0, ah1, ah2, ah3, bh0, bh1);
                mma_bf16(acc[nb], ah0, ah1, ah2, ah3, bl0, bl1);
                mma_bf16(acc[nb], al0, al1, al2, al3, bh0, bh1);
            }
        }
        __syncthreads();
    }

    const int rowA = bm + wm * 16 + gid, rowB = rowA + 8;
#pragma unroll
    for (int nb = 0; nb < 4; nb++) {
        int col = bn + wn * 32 + nb * 8 + tig * 2;
        float b0 = bias[col], b1v = bias[col + 1];
        float v0 = acc[nb][0] + b0, v1 = acc[nb][1] + b1v;
        float v2 = acc[nb][2] + b0, v3 = acc[nb][3] + b1v;
        float2 xA = *(const float2*)&xres[(long)rowA * N + col];
        float2 xB = *(const float2*)&xres[(long)rowB * N + col];
        float w0 = v0 + xA.x, w1 = v1 + xA.y;
        float w2 = v2 + xB.x, w3 = v3 + xB.y;
        *(float2*)&C[(long)rowA * N + col] = make_float2(w0, w1);
        *(float2*)&C[(long)rowB * N + col] = make_float2(w2, w3);
        float cs0 = w0 + w2, cs1 = w1 + w3;
        float cq0 = w0 * w0 + w2 * w2, cq1 = w1 * w1 + w3 * w3;
#pragma unroll
        for (int mk = 4; mk < 32; mk <<= 1) {
            cs0 += __shfl_xor_sync(0xFFFFFFFF, cs0, mk);
            cs1 += __shfl_xor_sync(0xFFFFFFFF, cs1, mk);
            cq0 += __shfl_xor_sync(0xFFFFFFFF, cq0, mk);
            cq1 += __shfl_xor_sync(0xFFFFFFFF, cq1, mk);
        }
        if (gid == 0) {
            atomicAdd(&sums_out[col], cs0);
            atomicAdd(&sums_out[CC + col], cq0);
            atomicAdd(&sums_out[col + 1], cs1);
            atomicAdd(&sums_out[CC + col + 1], cq1);
        }
    }
}

// ---------------- BN affine apply ----------------
__global__ __launch_bounds__(256) void bn_affine(const float* __restrict__ u,
        const float* __restrict__ sums, const float* __restrict__ g,
        const float* __restrict__ b, float* __restrict__ out) {
    int i = blockIdx.x * 256 + threadIdx.x;
    if (i >= NN * 32) return;
    int c4 = i & 31;
    float4 v = ((const float4*)u)[i];
    float o[4] = {v.x, v.y, v.z, v.w};
#pragma unroll
    for (int k = 0; k < 4; k++) {
        int c = c4 * 4 + k;
        float mean = sums[c] * (1.f / NN);
        float var  = sums[CC + c] * (1.f / NN) - mean * mean;
        float sc   = rsqrtf(var + BN_EPS) * g[c];
        o[k] = (o[k] - mean) * sc + b[c];
    }
    ((float4*)out)[i] = make_float4(o[0], o[1], o[2], o[3]);
}

// ---------------- mma.sync flash attention (BQ=128, cp.async double-buffered K/V) ----
#define EXP2_SCALE 0.25503480f
#define QK_STRIDE 40
#define VT_STRIDE 136

__global__ __launch_bounds__(256, 1) void mma_attn(const __nv_bfloat16* __restrict__ qb,
        const __nv_bfloat16* __restrict__ kb, const __nv_bfloat16* __restrict__ vtb,
        float* __restrict__ out) {
    __shared__ uint16_t Qs[128 * QK_STRIDE];
    __shared__ uint16_t Ks[2][128 * QK_STRIDE];
    __shared__ uint16_t Vts[2][32 * VT_STRIDE];

    const int tid = threadIdx.x;
    const int wid = tid >> 5, lane = tid & 31;
    const int gid = lane >> 2, tig = lane & 3;
    const int h = blockIdx.y;
    const int qbase = blockIdx.x * 128;
    const int r0 = wid * 16;

    const uint16_t* Qg = (const uint16_t*)(qb + ((long)h * NN + qbase) * 32);
#pragma unroll
    for (int it = 0; it < 2; it++) {
        int i = tid + it * 256;
        int row = i >> 2, seg = i & 3;
        *(uint4*)&Qs[row * QK_STRIDE + seg * 8] = *(const uint4*)&Qg[row * 32 + seg * 8];
    }

    auto pre_kv = [&](int st, int kb0) {
        const uint16_t* Kg = (const uint16_t*)(kb + ((long)h * NN + kb0) * 32);
#pragma unroll
        for (int it = 0; it < 2; it++) {
            int i = tid + it * 256;
            int row = i >> 2, seg = i & 3;
            CP16(smem_u32(&Ks[st][row * QK_STRIDE + seg * 8]), &Kg[row * 32 + seg * 8]);
        }
        const uint16_t* Vg = (const uint16_t*)(vtb + ((long)h * 32) * NN + kb0);
#pragma unroll
        for (int it = 0; it < 2; it++) {
            int i = tid + it * 256;
            int d = i >> 4, seg = i & 15;
            CP16(smem_u32(&Vts[st][d * VT_STRIDE + seg * 8]), &Vg[(long)d * NN + seg * 8]);
        }
    };

    pre_kv(0, 0);
    CP_COMMIT();
    __syncthreads();

    uint32_t aq[2][4];
#pragma unroll
    for (int t = 0; t < 2; t++) {
        int k = t * 16 + tig * 2;
        aq[t][0] = *(const uint32_t*)&Qs[(r0 + gid    ) * QK_STRIDE + k    ];
        aq[t][1] = *(const uint32_t*)&Qs[(r0 + gid + 8) * QK_STRIDE + k    ];
        aq[t][2] = *(const uint32_t*)&Qs[(r0 + gid    ) * QK_STRIDE + k + 8];
        aq[t][3] = *(const uint32_t*)&Qs[(r0 + gid + 8) * QK_STRIDE + k + 8];
    }

    float oacc[4][4] = {};
    float rs0 = 0.f, rs1 = 0.f;

    for (int kt = 0; kt < NN / 128; kt++) {
        const int st = kt & 1;
        if (kt + 1 < NN / 128) {
            pre_kv(st ^ 1, (kt + 1) * 128);
            CP_COMMIT();
            CP_WAIT1();
        } else {
            CP_WAIT0();
        }
        __syncthreads();

        float sacc[16][4];
#pragma unroll
        for (int j = 0; j < 16; j++) { sacc[j][0] = sacc[j][1] = sacc[j][2] = sacc[j][3] = 0.f; }
#pragma unroll
        for (int j = 0; j < 16; j++) {
#pragma unroll
            for (int t = 0; t < 2; t++) {
                int k = t * 16 + tig * 2;
                uint32_t b0 = *(const uint32_t*)&Ks[st][(8 * j + gid) * QK_STRIDE + k    ];
                uint32_t b1 = *(const uint32_t*)&Ks[st][(8 * j + gid) * QK_STRIDE + k + 8];
                mma_bf16(sacc[j], aq[t][0], aq[t][1], aq[t][2], aq[t][3], b0, b1);
            }
        }

        uint32_t pf[16][2];
#pragma unroll
        for (int j = 0; j < 16; j++) {
            float p0 = fast_exp2(sacc[j][0] * EXP2_SCALE);
            float p1 = fast_exp2(sacc[j][1] * EXP2_SCALE);
            float p2 = fast_exp2(sacc[j][2] * EXP2_SCALE);
            float p3 = fast_exp2(sacc[j][3] * EXP2_SCALE);
            rs0 += p0 + p1;
            rs1 += p2 + p3;
            pf[j][0] = pack_bf16(p0, p1);
            pf[j][1] = pack_bf16(p2, p3);
        }

#pragma unroll
        for (int t = 0; t < 8; t++) {
            uint32_t a0 = pf[2 * t][0], a1 = pf[2 * t][1];
            uint32_t a2 = pf[2 * t + 1][0], a3 = pf[2 * t + 1][1];
            int k = t * 16 + tig * 2;
#pragma unroll
            for (int n = 0; n < 4; n++) {
                uint32_t b0 = *(const uint32_t*)&Vts[st][(8 * n + gid) * VT_STRIDE + k    ];
                uint32_t b1 = *(const uint32_t*)&Vts[st][(8 * n + gid) * VT_STRIDE + k + 8];
                mma_bf16(oacc[n], a0, a1, a2, a3, b0, b1);
            }
        }
        __syncthreads();
    }

    rs0 += __shfl_xor_sync(0xFFFFFFFF, rs0, 1);
    rs0 += __shfl_xor_sync(0xFFFFFFFF, rs0, 2);
    rs1 += __shfl_xor_sync(0xFFFFFFFF, rs1, 1);
    rs1 += __shfl_xor_sync(0xFFFFFFFF, rs1, 2);
    float inv0 = 1.f / rs0, inv1 = 1.f / rs1;

    int rowA = qbase + r0 + gid, rowB = rowA + 8;
    float* poA = out + (long)rowA * CC + h * 32 + tig * 2;
    float* poB = out + (long)rowB * CC + h * 32 + tig * 2;
#pragma unroll
    for (int n = 0; n < 4; n++) {
        *(float2*)(poA + n * 8) = make_float2(oacc[n][0] * inv0, oacc[n][1] * inv0);
        *(float2*)(poB + n * 8) = make_float2(oacc[n][2] * inv1, oacc[n][3] * inv1);
    }
}

// ---------------- head MLP: warp-per-node, low smem ----------------
__global__ __launch_bounds__(256) void head_warp(const float* __restrict__ x,
        const float* __restrict__ w1, const float* __restrict__ b1,
        const float* __restrict__ w2, const float* __restrict__ b2,
        const float* __restrict__ w3, const float* __restrict__ b3,
        float* __restrict__ out) {
    __shared__ float y1s[8][64];
    __shared__ float y2s[8][32];
    int tid = threadIdx.x;
    int wid = tid >> 5, lane = tid & 31;
    int n = blockIdx.x * 8 + wid;

    float4 xv = *(const float4*)&x[(long)n * 128 + lane * 4];

    for (int o = 0; o < 64; o++) {
        float4 wv = *(const float4*)&w1[o * 128 + lane * 4];
        float p = xv.x * wv.x + xv.y * wv.y + xv.z * wv.z + xv.w * wv.w;
#pragma unroll
        for (int mk = 16; mk > 0; mk >>= 1) p += __shfl_xor_sync(0xFFFFFFFF, p, mk);
        if (lane == 0) y1s[wid][o] = fmaxf(p + b1[o], 0.f);
    }
    __syncwarp();
    float ya = y1s[wid][lane * 2], yb = y1s[wid][lane * 2 + 1];
    for (int o = 0; o < 32; o++) {
        float2 wv = *(const float2*)&w2[o * 64 + lane * 2];
        float p = ya * wv.x + yb * wv.y;
#pragma unroll
        for (int mk = 16; mk > 0; mk >>= 1) p += __shfl_xor_sync(0xFFFFFFFF, p, mk);
        if (lane == 0) y2s[wid][o] = fmaxf(p + b2[o], 0.f);
    }
    __syncwarp();
    float p = y2s[wid][lane] * w3[lane];
#pragma unroll
    for (int mk = 16; mk > 0; mk >>= 1) p += __shfl_xor_sync(0xFFFFFFFF, p, mk);
    if (lane == 0) out[n] = p + b3[0];
}

// ---------------- host orchestration ----------------
static __nv_bfloat16 *s_whi, *s_wlo;

extern "C" void kernel_launch(void* const* d_in, const int* in_sizes, int n_in,
                              void* d_out, int out_size) {
    const float* x_in      = (const float*)d_in[0];
    const int*   edge      = (const int*)  d_in[1];
    const float* gin_w1    = (const float*)d_in[2];
    const float* gin_b1    = (const float*)d_in[3];
    const float* gin_w2    = (const float*)d_in[4];
    const float* gin_b2    = (const float*)d_in[5];
    const float* attn_in_w = (const float*)d_in[6];
    const float* attn_in_b = (const float*)d_in[7];
    const float* attn_o_w  = (const float*)d_in[8];
    const float* attn_o_b  = (const float*)d_in[9];
    const float* n1_g = (const float*)d_in[10];
    const float* n1_b = (const float*)d_in[11];
    const float* n2_g = (const float*)d_in[12];
    const float* n2_b = (const float*)d_in[13];
    const float* n3_g = (const float*)d_in[14];
    const float* n3_b = (const float*)d_in[15];
    const float* mlp_w1 = (const float*)d_in[16];
    const float* mlp_b1 = (const float*)d_in[17];
    const float* mlp_w2 = (const float*)d_in[18];
    const float* mlp_b2 = (const float*)d_in[19];
    const float* hw1 = (const float*)d_in[20];
    const float* hb1 = (const float*)d_in[21];
    const float* hw2 = (const float*)d_in[22];
    const float* hb2 = (const float*)d_in[23];
    const float* hw3 = (const float*)d_in[24];
    const float* hb3 = (const float*)d_in[25];
    float* out = (float*)d_out;

    int E = in_sizes[1] / 2;

    float *p_x, *p_agg, *p_t1, *p_t2, *p_h1, *p_h2, *p_sums;
    int *p_deg;
    __nv_bfloat16 *p_qb, *p_kb, *p_vtb;
    cudaGetSymbolAddress((void**)&p_x,  g_x);
    cudaGetSymbolAddress((void**)&p_agg, g_agg);
    cudaGetSymbolAddress((void**)&p_t1, g_t1);
    cudaGetSymbolAddress((void**)&p_t2, g_t2);
    cudaGetSymbolAddress((void**)&p_h1, g_h1);
    cudaGetSymbolAddress((void**)&p_h2, g_h2);
    cudaGetSymbolAddress((void**)&p_sums, g_bnsums);
    cudaGetSymbolAddress((void**)&p_deg, g_deg);
    cudaGetSymbolAddress((void**)&p_qb, g_qb);
    cudaGetSymbolAddress((void**)&p_kb, g_kb);
    cudaGetSymbolAddress((void**)&p_vtb, g_vtb);
    cudaGetSymbolAddress((void**)&s_whi, g_whi);
    cudaGetSymbolAddress((void**)&s_wlo, g_wlo);

    conv_w<<<(WTOTAL + 255) / 256, 256>>>(gin_w1, gin_w2, attn_in_w, attn_o_w, mlp_w1, mlp_w2);
    cudaMemsetAsync(p_sums, 0, 12 * 2 * CC * sizeof(float));
    cudaMemsetAsync(p_deg, 0, (NN + 1) * sizeof(int));
    hist_kernel<<<(E + 255) / 256, 256>>>(edge, E);
    scan_kernel<<<1, 1024>>>();
    fill_kernel<<<(E + 255) / 256, 256>>>(edge, E);

    for (int i = 0; i < LL; i++) {
        const float* xcur = (i == 0) ? x_in : p_x;
        const float* gb1 = gin_b1 + (long)i * CC;
        const float* gb2 = gin_b2 + (long)i * CC;
        const float* aib = attn_in_b + (long)i * 3 * CC;
        const float* aob = attn_o_b + (long)i * CC;
        const float* mb1 = mlp_b1 + (long)i * 2 * CC;
        const float* mb2 = mlp_b2 + (long)i * CC;
        float* s1 = p_sums + (3 * i + 0) * 2 * CC;
        float* s2 = p_sums + (3 * i + 1) * 2 * CC;
        float* s3 = p_sums + (3 * i + 2) * 2 * CC;

        // ---- gather + qkv + gin1 + attention ----
        gather_kernel<<<NN / 8, 256>>>(xcur, p_agg);
        gemm_tc<0, 2><<<dim3(6, 64), 256>>>(xcur, nullptr,
            s_whi + WOFF_AIN + i * 3 * CC * CC, s_wlo + WOFF_AIN + i * 3 * CC * CC, aib, nullptr,
            p_qb, p_kb, p_vtb, nullptr, nullptr,
            nullptr, nullptr, nullptr, nullptr, nullptr, nullptr, nullptr, NN, 3 * CC, CC);
        gemm_tc<0, 1><<<dim3(2, 64), 256>>>(p_agg, nullptr,
            s_whi + WOFF_GIN1 + i * CC * CC, s_wlo + WOFF_GIN1 + i * CC * CC, gb1, p_t1,
            nullptr, nullptr, nullptr, nullptr, nullptr,
            nullptr, nullptr, nullptr, nullptr, nullptr, nullptr, nullptr, NN, CC, CC);
        mma_attn<<<dim3(NN / 128, HEADS), 256>>>(p_qb, p_kb, p_vtb, p_agg);

        // ---- fused gin2 (t1->h1,s1) || aout (agg->h2,s2) ----
        gemm_dual_e3<<<256, 256>>>(
            p_t1, s_whi + WOFF_GIN2 + i * CC * CC, s_wlo + WOFF_GIN2 + i * CC * CC, gb2, p_h1, s1,
            p_agg, s_whi + WOFF_AOUT + i * CC * CC, s_wlo + WOFF_AOUT + i * CC * CC, aob, p_h2, s2,
            xcur);

        // ---- MLP ----
        gemm_tc<2, 1><<<dim3(4, 64), 256>>>(p_h1, p_h2,
            s_whi + WOFF_MW1 + i * 2 * CC * CC, s_wlo + WOFF_MW1 + i * 2 * CC * CC, mb1, p_t1,
            nullptr, nullptr, nullptr, nullptr, nullptr,
            s1, n1_g + i * CC, n1_b + i * CC, s2, n2_g + i * CC, n2_b + i * CC,
            p_t2, NN, 2 * CC, CC);
        gemm_tc<0, 3><<<dim3(2, 64), 256>>>(p_t1, nullptr,
            s_whi + WOFF_MW2 + i * 2 * CC * CC, s_wlo + WOFF_MW2 + i * 2 * CC * CC, mb2, p_agg,
            nullptr, nullptr, nullptr, p_t2, s3,
            nullptr, nullptr, nullptr, nullptr, nullptr, nullptr, nullptr, NN, CC, 2 * CC);
        bn_affine<<<NN * 32 / 256, 256>>>(p_agg, s3, n3_g + i * CC, n3_b + i * CC, p_x);
    }

    // ---- head ----
    head_warp<<<NN / 8, 256>>>(p_x, hw1, hb1, hw2, hb2, hw3, hb3, out);
}

// round 15
// speedup vs baseline: 1.3514x; 1.0366x over previous
#include <cuda_runtime.h>
#include <cuda_bf16.h>
#include <cstdint>

#define NN 4096
#define CC 128
#define LL 4
#define HEADS 4
#define BN_EPS 1e-5f
#define EMAX 262144

// ---------------- scratch (static device globals; no allocation) ----------------
__device__ float g_x  [NN * CC];
__device__ float g_agg[NN * CC];
__device__ float g_t1 [NN * 384];
__device__ float g_t2 [NN * CC];
__device__ float g_h1 [NN * CC];
__device__ float g_h2 [NN * CC];
__device__ float g_bnsums[12 * 2 * CC];
__device__ int   g_deg[NN + 1];
__device__ int   g_cur[NN];
__device__ int   g_csr[EMAX];
__device__ __nv_bfloat16 g_qb [HEADS * NN * 32];
__device__ __nv_bfloat16 g_kb [HEADS * NN * 32];
__device__ __nv_bfloat16 g_vtb[HEADS * 32 * NN];

// concatenated hi/lo bf16 weights
#define WOFF_GIN1 0
#define WOFF_GIN2 65536
#define WOFF_AIN  131072
#define WOFF_AOUT 327680
#define WOFF_MW1  393216
#define WOFF_MW2  524288
#define WTOTAL    655360
__device__ __nv_bfloat16 g_whi[WTOTAL];
__device__ __nv_bfloat16 g_wlo[WTOTAL];

// ---------------- mma.sync / ptx helpers ----------------
__device__ __forceinline__ void mma_bf16(float* d, uint32_t a0, uint32_t a1, uint32_t a2,
                                         uint32_t a3, uint32_t b0, uint32_t b1) {
    asm volatile(
        "mma.sync.aligned.m16n8k16.row.col.f32.bf16.bf16.f32 "
        "{%0,%1,%2,%3}, {%4,%5,%6,%7}, {%8,%9}, {%0,%1,%2,%3};"
        : "+f"(d[0]), "+f"(d[1]), "+f"(d[2]), "+f"(d[3])
        : "r"(a0), "r"(a1), "r"(a2), "r"(a3), "r"(b0), "r"(b1));
}
__device__ __forceinline__ float fast_exp2(float x) {
    float y; asm("ex2.approx.ftz.f32 %0, %1;" : "=f"(y) : "f"(x)); return y;
}
__device__ __forceinline__ uint32_t pack_bf16(float lo, float hi) {
    uint32_t r; asm("cvt.rn.bf16x2.f32 %0, %1, %2;" : "=r"(r) : "f"(hi), "f"(lo)); return r;
}
__device__ __forceinline__ void split2(float x, float y, uint32_t& hi, uint32_t& lo) {
    __nv_bfloat16 hx = __float2bfloat16(x), hy = __float2bfloat16(y);
    float lx = x - __bfloat162float(hx), ly = y - __bfloat162float(hy);
    hi = pack_bf16(__bfloat162float(hx), __bfloat162float(hy));
    lo = pack_bf16(lx, ly);
}
__device__ __forceinline__ uint32_t smem_u32(const void* p) {
    return (uint32_t)__cvta_generic_to_shared(p);
}
#define CP16(dst_u32, src) \
    asm volatile("cp.async.cg.shared.global [%0], [%1], 16;" :: "r"(dst_u32), "l"(src))
#define CP_COMMIT() asm volatile("cp.async.commit_group;")
#define CP_WAIT1()  asm volatile("cp.async.wait_group 1;")
#define CP_WAIT0()  asm volatile("cp.async.wait_group 0;")

// ---------------- weight hi/lo conversion ----------------
__global__ void conv_w(const float* __restrict__ w_gin1, const float* __restrict__ w_gin2,
                       const float* __restrict__ w_ain,  const float* __restrict__ w_aout,
                       const float* __restrict__ w_m1,   const float* __restrict__ w_m2) {
    int id = blockIdx.x * 256 + threadIdx.x;
    if (id >= WTOTAL) return;
    const float* src; int off;
    if      (id < WOFF_GIN2) { src = w_gin1; off = id; }
    else if (id < WOFF_AIN)  { src = w_gin2; off = id - WOFF_GIN2; }
    else if (id < WOFF_AOUT) { src = w_ain;  off = id - WOFF_AIN; }
    else if (id < WOFF_MW1)  { src = w_aout; off = id - WOFF_AOUT; }
    else if (id < WOFF_MW2)  { src = w_m1;   off = id - WOFF_MW1; }
    else                     { src = w_m2;   off = id - WOFF_MW2; }
    float v = src[off];
    __nv_bfloat16 h = __float2bfloat16(v);
    g_whi[id] = h;
    g_wlo[id] = __float2bfloat16(v - __bfloat162float(h));
}

// ---------------- CSR build ----------------
__global__ void hist_kernel(const int* __restrict__ ei, int E) {
    int e = blockIdx.x * blockDim.x + threadIdx.x;
    if (e < E) atomicAdd(&g_deg[ei[E + e] + 1], 1);
}

__global__ void scan_kernel() {
    __shared__ int part[1024];
    int t = threadIdx.x;
    int base = t * 4;
    int x0 = g_deg[base], x1 = g_deg[base + 1], x2 = g_deg[base + 2], x3 = g_deg[base + 3];
    x1 += x0; x2 += x1; x3 += x2;
    part[t] = x3;
    __syncthreads();
    for (int off = 1; off < 1024; off <<= 1) {
        int v = (t >= off) ? part[t - off] : 0;
        __syncthreads();
        part[t] += v;
        __syncthreads();
    }
    int add = (t > 0) ? part[t - 1] : 0;
    int v0 = x0 + add, v1 = x1 + add, v2 = x2 + add, v3 = x3 + add;
    g_deg[base] = v0; g_deg[base + 1] = v1; g_deg[base + 2] = v2; g_deg[base + 3] = v3;
    g_cur[base] = v0; g_cur[base + 1] = v1; g_cur[base + 2] = v2; g_cur[base + 3] = v3;
    __syncthreads();
    if (t == 0) g_deg[NN] += g_deg[NN - 1];
}

__global__ void fill_kernel(const int* __restrict__ ei, int E) {
    int e = blockIdx.x * blockDim.x + threadIdx.x;
    if (e >= E) return;
    int s = ei[e], d = ei[E + e];
    int pos = atomicAdd(&g_cur[d], 1);
    g_csr[pos] = s;
}

// ---------------- GIN gather ----------------
__global__ __launch_bounds__(256) void gather_kernel(const float* __restrict__ x,
                                                     float* __restrict__ agg) {
    int wg = (blockIdx.x * 256 + threadIdx.x) >> 5;
    int lane = threadIdx.x & 31;
    if (wg >= NN) return;
    int beg = g_deg[wg], end = g_deg[wg + 1];
    float4 acc = *(const float4*)&x[(long)wg * CC + lane * 4];
    for (int j = beg; j < end; j++) {
        int s = g_csr[j];
        float4 v = *(const float4*)&x[(long)s * CC + lane * 4];
        acc.x += v.x; acc.y += v.y; acc.z += v.z; acc.w += v.w;
    }
    *(float4*)&agg[(long)wg * CC + lane * 4] = acc;
}

// ---------------- tensor-core GEMM (hi/lo split, register-prefetch) — R13 proven ------
#define AST 40
template <int LMODE, int EMODE>
__global__ __launch_bounds__(256) void gemm_tc(const float* __restrict__ A,
        const float* __restrict__ A2,
        const __nv_bfloat16* __restrict__ Bh, const __nv_bfloat16* __restrict__ Bl,
        const float* __restrict__ bias, float* __restrict__ C,
        __nv_bfloat16* __restrict__ qb, __nv_bfloat16* __restrict__ kbuf,
        __nv_bfloat16* __restrict__ vtb,
        const float* __restrict__ xres, float* __restrict__ sums_out,
        const float* __restrict__ s1, const float* __restrict__ g1, const float* __restrict__ b1,
        const float* __restrict__ s2, const float* __restrict__ g2, const float* __restrict__ b2,
        float* __restrict__ hout, int M, int N, int K) {
    __shared__ uint16_t Ahs[64 * AST], Als[64 * AST];
    __shared__ uint16_t Bhs[64 * AST], Bls[64 * AST];
    __shared__ float csc1[128], cof1[128], csc2[128], cof2[128];
    const int tid = threadIdx.x;
    const int warp = tid >> 5, lane = tid & 31;
    const int gid = lane >> 2, tig = lane & 3;
    const int wm = warp >> 1, wn = warp & 1;
    const int bm = blockIdx.y * 64, bn = blockIdx.x * 64;
    float acc[4][4] = {};

    if (LMODE == 2) {
        int c = tid & 127;
        const float* ss = (tid < 128) ? s1 : s2;
        const float* gg = (tid < 128) ? g1 : g2;
        const float* bb2 = (tid < 128) ? b1 : b2;
        float mean = ss[c] * (1.f / NN);
        float var  = ss[CC + c] * (1.f / NN) - mean * mean;
        float sc   = rsqrtf(var + BN_EPS) * gg[c];
        float off  = bb2[c] - mean * sc;
        if (tid < 128) { csc1[c] = sc; cof1[c] = off; }
        else           { csc2[c] = sc; cof2[c] = off; }
        __syncthreads();
    }

    const int nch = K >> 5;
    const int j0 = tid * 2, j1 = tid * 2 + 1;
    const int ar0 = j0 >> 3, ac0 = j0 & 7;
    const int ar1 = j1 >> 3, ac1 = j1 & 7;
    const int brow = tid >> 2, bseg = tid & 3;

    float4 va0, va1, wa0, wa1;
    uint4 vbh, vbl;

    va0 = *(const float4*)&A[(long)(bm + ar0) * K + ac0 * 4];
    va1 = *(const float4*)&A[(long)(bm + ar1) * K + ac1 * 4];
    if (LMODE == 2) {
        wa0 = *(const float4*)&A2[(long)(bm + ar0) * K + ac0 * 4];
        wa1 = *(const float4*)&A2[(long)(bm + ar1) * K + ac1 * 4];
    }
    vbh = *(const uint4*)&Bh[(long)(bn + brow) * K + bseg * 8];
    vbl = *(const uint4*)&Bl[(long)(bn + brow) * K + bseg * 8];

    for (int c = 0; c < nch; c++) {
        const int k0 = c * 32;
        {
            float4 v = va0;
            int cbase = k0 + ac0 * 4;
            if (LMODE == 2) {
                v.x = v.x * csc1[cbase]     + cof1[cbase]     + wa0.x * csc2[cbase]     + cof2[cbase];
                v.y = v.y * csc1[cbase + 1] + cof1[cbase + 1] + wa0.y * csc2[cbase + 1] + cof2[cbase + 1];
                v.z = v.z * csc1[cbase + 2] + cof1[cbase + 2] + wa0.z * csc2[cbase + 2] + cof2[cbase + 2];
                v.w = v.w * csc1[cbase + 3] + cof1[cbase + 3] + wa0.w * csc2[cbase + 3] + cof2[cbase + 3];
                if (blockIdx.x == 0)
                    *(float4*)&hout[(long)(bm + ar0) * K + cbase] = v;
            }
            uint32_t h0, l0, h1, l1;
            split2(v.x, v.y, h0, l0);
            split2(v.z, v.w, h1, l1);
            uint32_t* ph = (uint32_t*)&Ahs[ar0 * AST + ac0 * 4];
            uint32_t* pl = (uint32_t*)&Als[ar0 * AST + ac0 * 4];
            ph[0] = h0; ph[1] = h1;
            pl[0] = l0; pl[1] = l1;
        }
        {
            float4 v = va1;
            int cbase = k0 + ac1 * 4;
            if (LMODE == 2) {
                v.x = v.x * csc1[cbase]     + cof1[cbase]     + wa1.x * csc2[cbase]     + cof2[cbase];
                v.y = v.y * csc1[cbase + 1] + cof1[cbase + 1] + wa1.y * csc2[cbase + 1] + cof2[cbase + 1];
                v.z = v.z * csc1[cbase + 2] + cof1[cbase + 2] + wa1.z * csc2[cbase + 2] + cof2[cbase + 2];
                v.w = v.w * csc1[cbase + 3] + cof1[cbase + 3] + wa1.w * csc2[cbase + 3] + cof2[cbase + 3];
                if (blockIdx.x == 0)
                    *(float4*)&hout[(long)(bm + ar1) * K + cbase] = v;
            }
            uint32_t h0, l0, h1, l1;
            split2(v.x, v.y, h0, l0);
            split2(v.z, v.w, h1, l1);
            uint32_t* ph = (uint32_t*)&Ahs[ar1 * AST + ac1 * 4];
            uint32_t* pl = (uint32_t*)&Als[ar1 * AST + ac1 * 4];
            ph[0] = h0; ph[1] = h1;
            pl[0] = l0; pl[1] = l1;
        }
        *(uint4*)&Bhs[brow * AST + bseg * 8] = vbh;
        *(uint4*)&Bls[brow * AST + bseg * 8] = vbl;
        __syncthreads();

        if (c + 1 < nch) {
            const int kn = (c + 1) * 32;
            va0 = *(const float4*)&A[(long)(bm + ar0) * K + kn + ac0 * 4];
            va1 = *(const float4*)&A[(long)(bm + ar1) * K + kn + ac1 * 4];
            if (LMODE == 2) {
                wa0 = *(const float4*)&A2[(long)(bm + ar0) * K + kn + ac0 * 4];
                wa1 = *(const float4*)&A2[(long)(bm + ar1) * K + kn + ac1 * 4];
            }
            vbh = *(const uint4*)&Bh[(long)(bn + brow) * K + kn + bseg * 8];
            vbl = *(const uint4*)&Bl[(long)(bn + brow) * K + kn + bseg * 8];
        }

#pragma unroll
        for (int ks = 0; ks < 2; ks++) {
            int kk = ks * 16 + tig * 2;
            int r = wm * 16;
            uint32_t ah0 = *(const uint32_t*)&Ahs[(r + gid    ) * AST + kk    ];
            uint32_t ah1 = *(const uint32_t*)&Ahs[(r + gid + 8) * AST + kk    ];
            uint32_t ah2 = *(const uint32_t*)&Ahs[(r + gid    ) * AST + kk + 8];
            uint32_t ah3 = *(const uint32_t*)&Ahs[(r + gid + 8) * AST + kk + 8];
            uint32_t al0 = *(const uint32_t*)&Als[(r + gid    ) * AST + kk    ];
            uint32_t al1 = *(const uint32_t*)&Als[(r + gid + 8) * AST + kk    ];
            uint32_t al2 = *(const uint32_t*)&Als[(r + gid    ) * AST + kk + 8];
            uint32_t al3 = *(const uint32_t*)&Als[(r + gid + 8) * AST + kk + 8];
#pragma unroll
            for (int nb = 0; nb < 4; nb++) {
                int nr = wn * 32 + nb * 8 + gid;
                uint32_t bh0 = *(const uint32_t*)&Bhs[nr * AST + kk    ];
                uint32_t bh1 = *(const uint32_t*)&Bhs[nr * AST + kk + 8];
                uint32_t bl0 = *(const uint32_t*)&Bls[nr * AST + kk    ];
                uint32_t bl1 = *(const uint32_t*)&Bls[nr * AST + kk + 8];
                mma_bf16(acc[nb], ah0, ah1, ah2, ah3, bh0, bh1);
                mma_bf16(acc[nb], ah0, ah1, ah2, ah3, bl0, bl1);
                mma_bf16(acc[nb], al0, al1, al2, al3, bh0, bh1);
            }
        }
        __syncthreads();
    }

    const int rowA = bm + wm * 16 + gid, rowB = rowA + 8;
#pragma unroll
    for (int nb = 0; nb < 4; nb++) {
        int col = bn + wn * 32 + nb * 8 + tig * 2;
        if (col >= N) continue;
        float b0 = bias[col], b1v = bias[col + 1];
        float v0 = acc[nb][0] + b0, v1 = acc[nb][1] + b1v;
        float v2 = acc[nb][2] + b0, v3 = acc[nb][3] + b1v;
        if (EMODE == 1) {
            v0 = fmaxf(v0, 0.f); v1 = fmaxf(v1, 0.f);
            v2 = fmaxf(v2, 0.f); v3 = fmaxf(v3, 0.f);
        }
        if (EMODE == 2) {
            int sec = col >> 7, hh = (col & 127) >> 5, d = col & 31;
            if (sec == 0) {
                *(uint32_t*)&qb[((hh << 12) + rowA) * 32 + d] = pack_bf16(v0, v1);
                *(uint32_t*)&qb[((hh << 12) + rowB) * 32 + d] = pack_bf16(v2, v3);
            } else if (sec == 1) {
                *(uint32_t*)&kbuf[((hh << 12) + rowA) * 32 + d] = pack_bf16(v0, v1);
                *(uint32_t*)&kbuf[((hh << 12) + rowB) * 32 + d] = pack_bf16(v2, v3);
            } else {
                vtb[((hh * 32 + d    ) << 12) + rowA] = __float2bfloat16(v0);
                vtb[((hh * 32 + d + 1) << 12) + rowA] = __float2bfloat16(v1);
                vtb[((hh * 32 + d    ) << 12) + rowB] = __float2bfloat16(v2);
                vtb[((hh * 32 + d + 1) << 12) + rowB] = __float2bfloat16(v3);
            }
        } else if (EMODE == 3) {
            float2 xA = *(const float2*)&xres[(long)rowA * N + col];
            float2 xB = *(const float2*)&xres[(long)rowB * N + col];
            float w0 = v0 + xA.x, w1 = v1 + xA.y;
            float w2 = v2 + xB.x, w3 = v3 + xB.y;
            *(float2*)&C[(long)rowA * N + col] = make_float2(w0, w1);
            *(float2*)&C[(long)rowB * N + col] = make_float2(w2, w3);
            float cs0 = w0 + w2, cs1 = w1 + w3;
            float cq0 = w0 * w0 + w2 * w2, cq1 = w1 * w1 + w3 * w3;
#pragma unroll
            for (int mk = 4; mk < 32; mk <<= 1) {
                cs0 += __shfl_xor_sync(0xFFFFFFFF, cs0, mk);
                cs1 += __shfl_xor_sync(0xFFFFFFFF, cs1, mk);
                cq0 += __shfl_xor_sync(0xFFFFFFFF, cq0, mk);
                cq1 += __shfl_xor_sync(0xFFFFFFFF, cq1, mk);
            }
            if (gid == 0) {
                atomicAdd(&sums_out[col], cs0);
                atomicAdd(&sums_out[CC + col], cq0);
                atomicAdd(&sums_out[col + 1], cs1);
                atomicAdd(&sums_out[CC + col + 1], cq1);
            }
        } else {
            *(float2*)&C[(long)rowA * N + col] = make_float2(v0, v1);
            *(float2*)&C[(long)rowB * N + col] = make_float2(v2, v3);
        }
    }
}

// ---------------- fused qkv (blocks 0..383, EMODE2) || gin1 (blocks 384..511, EMODE1) --
// Both LMODE 0, K=128 (nch=4). Body identical to gemm_tc; pointer/epilogue by block range.
__global__ __launch_bounds__(256) void gemm_qkv_gin1(
        const float* __restrict__ xcur,
        const __nv_bfloat16* __restrict__ Bh_q, const __nv_bfloat16* __restrict__ Bl_q,
        const float* __restrict__ aib,
        __nv_bfloat16* __restrict__ qb, __nv_bfloat16* __restrict__ kbuf,
        __nv_bfloat16* __restrict__ vtb,
        const float* __restrict__ agg,
        const __nv_bfloat16* __restrict__ Bh_g, const __nv_bfloat16* __restrict__ Bl_g,
        const float* __restrict__ gb1, float* __restrict__ t1) {
    __shared__ uint16_t Ahs[64 * AST], Als[64 * AST];
    __shared__ uint16_t Bhs[64 * AST], Bls[64 * AST];

    const bool isq = (blockIdx.x < 384);
    int bx, by;
    const float* A;
    const __nv_bfloat16 *Bh, *Bl;
    const float* bias;
    int N;
    if (isq) {
        bx = blockIdx.x % 6; by = blockIdx.x / 6;
        A = xcur; Bh = Bh_q; Bl = Bl_q; bias = aib; N = 384;
    } else {
        int lb = blockIdx.x - 384;
        bx = lb & 1; by = lb >> 1;
        A = agg; Bh = Bh_g; Bl = Bl_g; bias = gb1; N = 128;
    }
    const int K = CC;
    const int tid = threadIdx.x;
    const int warp = tid >> 5, lane = tid & 31;
    const int gid = lane >> 2, tig = lane & 3;
    const int wm = warp >> 1, wn = warp & 1;
    const int bm = by * 64, bn = bx * 64;
    float acc[4][4] = {};

    const int j0 = tid * 2, j1 = tid * 2 + 1;
    const int ar0 = j0 >> 3, ac0 = j0 & 7;
    const int ar1 = j1 >> 3, ac1 = j1 & 7;
    const int brow = tid >> 2, bseg = tid & 3;

    float4 va0, va1;
    uint4 vbh, vbl;
    va0 = *(const float4*)&A[(long)(bm + ar0) * K + ac0 * 4];
    va1 = *(const float4*)&A[(long)(bm + ar1) * K + ac1 * 4];
    vbh = *(const uint4*)&Bh[(long)(bn + brow) * K + bseg * 8];
    vbl = *(const uint4*)&Bl[(long)(bn + brow) * K + bseg * 8];

#pragma unroll
    for (int c = 0; c < 4; c++) {
        {
            float4 v = va0;
            uint32_t h0, l0, h1, l1;
            split2(v.x, v.y, h0, l0);
            split2(v.z, v.w, h1, l1);
            uint32_t* ph = (uint32_t*)&Ahs[ar0 * AST + ac0 * 4];
            uint32_t* pl = (uint32_t*)&Als[ar0 * AST + ac0 * 4];
            ph[0] = h0; ph[1] = h1;
            pl[0] = l0; pl[1] = l1;
        }
        {
            float4 v = va1;
            uint32_t h0, l0, h1, l1;
            split2(v.x, v.y, h0, l0);
            split2(v.z, v.w, h1, l1);
            uint32_t* ph = (uint32_t*)&Ahs[ar1 * AST + ac1 * 4];
            uint32_t* pl = (uint32_t*)&Als[ar1 * AST + ac1 * 4];
            ph[0] = h0; ph[1] = h1;
            pl[0] = l0; pl[1] = l1;
        }
        *(uint4*)&Bhs[brow * AST + bseg * 8] = vbh;
        *(uint4*)&Bls[brow * AST + bseg * 8] = vbl;
        __syncthreads();

        if (c + 1 < 4) {
            const int kn = (c + 1) * 32;
            va0 = *(const float4*)&A[(long)(bm + ar0) * K + kn + ac0 * 4];
            va1 = *(const float4*)&A[(long)(bm + ar1) * K + kn + ac1 * 4];
            vbh = *(const uint4*)&Bh[(long)(bn + brow) * K + kn + bseg * 8];
            vbl = *(const uint4*)&Bl[(long)(bn + brow) * K + kn + bseg * 8];
        }

#pragma unroll
        for (int ks = 0; ks < 2; ks++) {
            int kk = ks * 16 + tig * 2;
            int r = wm * 16;
            uint32_t ah0 = *(const uint32_t*)&Ahs[(r + gid    ) * AST + kk    ];
            uint32_t ah1 = *(const uint32_t*)&Ahs[(r + gid + 8) * AST + kk    ];
            uint32_t ah2 = *(const uint32_t*)&Ahs[(r + gid    ) * AST + kk + 8];
            uint32_t ah3 = *(const uint32_t*)&Ahs[(r + gid + 8) * AST + kk + 8];
            uint32_t al0 = *(const uint32_t*)&Als[(r + gid    ) * AST + kk    ];
            uint32_t al1 = *(const uint32_t*)&Als[(r + gid + 8) * AST + kk    ];
            uint32_t al2 = *(const uint32_t*)&Als[(r + gid    ) * AST + kk + 8];
            uint32_t al3 = *(const uint32_t*)&Als[(r + gid + 8) * AST + kk + 8];
#pragma unroll
            for (int nb = 0; nb < 4; nb++) {
                int nr = wn * 32 + nb * 8 + gid;
                uint32_t bh0 = *(const uint32_t*)&Bhs[nr * AST + kk    ];
                uint32_t bh1 = *(const uint32_t*)&Bhs[nr * AST + kk + 8];
                uint32_t bl0 = *(const uint32_t*)&Bls[nr * AST + kk    ];
                uint32_t bl1 = *(const uint32_t*)&Bls[nr * AST + kk + 8];
                mma_bf16(acc[nb], ah0, ah1, ah2, ah3, bh0, bh1);
                mma_bf16(acc[nb], ah0, ah1, ah2, ah3, bl0, bl1);
                mma_bf16(acc[nb], al0, al1, al2, al3, bh0, bh1);
            }
        }
        __syncthreads();
    }

    const int rowA = bm + wm * 16 + gid, rowB = rowA + 8;
#pragma unroll
    for (int nb = 0; nb < 4; nb++) {
        int col = bn + wn * 32 + nb * 8 + tig * 2;
        float b0 = bias[col], b1v = bias[col + 1];
        float v0 = acc[nb][0] + b0, v1 = acc[nb][1] + b1v;
        float v2 = acc[nb][2] + b0, v3 = acc[nb][3] + b1v;
        if (isq) {
            int sec = col >> 7, hh = (col & 127) >> 5, d = col & 31;
            if (sec == 0) {
                *(uint32_t*)&qb[((hh << 12) + rowA) * 32 + d] = pack_bf16(v0, v1);
                *(uint32_t*)&qb[((hh << 12) + rowB) * 32 + d] = pack_bf16(v2, v3);
            } else if (sec == 1) {
                *(uint32_t*)&kbuf[((hh << 12) + rowA) * 32 + d] = pack_bf16(v0, v1);
                *(uint32_t*)&kbuf[((hh << 12) + rowB) * 32 + d] = pack_bf16(v2, v3);
            } else {
                vtb[((hh * 32 + d    ) << 12) + rowA] = __float2bfloat16(v0);
                vtb[((hh * 32 + d + 1) << 12) + rowA] = __float2bfloat16(v1);
                vtb[((hh * 32 + d    ) << 12) + rowB] = __float2bfloat16(v2);
                vtb[((hh * 32 + d + 1) << 12) + rowB] = __float2bfloat16(v3);
            }
        } else {
            v0 = fmaxf(v0, 0.f); v1 = fmaxf(v1, 0.f);
            v2 = fmaxf(v2, 0.f); v3 = fmaxf(v3, 0.f);
            *(float2*)&t1[(long)rowA * 128 + col] = make_float2(v0, v1);
            *(float2*)&t1[(long)rowB * 128 + col] = make_float2(v2, v3);
        }
    }
}

// ---------------- dual EMODE-3 GEMM (R14 proven) ----------------
__global__ __launch_bounds__(256) void gemm_dual_e3(
        const float* __restrict__ A_a, const __nv_bfloat16* __restrict__ Bh_a,
        const __nv_bfloat16* __restrict__ Bl_a, const float* __restrict__ bias_a,
        float* __restrict__ C_a, float* __restrict__ sums_a,
        const float* __restrict__ A_b, const __nv_bfloat16* __restrict__ Bh_b,
        const __nv_bfloat16* __restrict__ Bl_b, const float* __restrict__ bias_b,
        float* __restrict__ C_b, float* __restrict__ sums_b,
        const float* __restrict__ xres) {
    __shared__ uint16_t Ahs[64 * AST], Als[64 * AST];
    __shared__ uint16_t Bhs[64 * AST], Bls[64 * AST];

    const int half = (blockIdx.x >= 128);
    const int lb = blockIdx.x & 127;
    const float* A = half ? A_b : A_a;
    const __nv_bfloat16* Bh = half ? Bh_b : Bh_a;
    const __nv_bfloat16* Bl = half ? Bl_b : Bl_a;
    const float* bias = half ? bias_b : bias_a;
    float* C = half ? C_b : C_a;
    float* sums_out = half ? sums_b : sums_a;

    const int tid = threadIdx.x;
    const int warp = tid >> 5, lane = tid & 31;
    const int gid = lane >> 2, tig = lane & 3;
    const int wm = warp >> 1, wn = warp & 1;
    const int bm = (lb >> 1) * 64, bn = (lb & 1) * 64;
    const int K = CC, N = CC;
    float acc[4][4] = {};

    const int j0 = tid * 2, j1 = tid * 2 + 1;
    const int ar0 = j0 >> 3, ac0 = j0 & 7;
    const int ar1 = j1 >> 3, ac1 = j1 & 7;
    const int brow = tid >> 2, bseg = tid & 3;

    float4 va0, va1;
    uint4 vbh, vbl;
    va0 = *(const float4*)&A[(long)(bm + ar0) * K + ac0 * 4];
    va1 = *(const float4*)&A[(long)(bm + ar1) * K + ac1 * 4];
    vbh = *(const uint4*)&Bh[(long)(bn + brow) * K + bseg * 8];
    vbl = *(const uint4*)&Bl[(long)(bn + brow) * K + bseg * 8];

#pragma unroll
    for (int c = 0; c < 4; c++) {
        {
            float4 v = va0;
            uint32_t h0, l0, h1, l1;
            split2(v.x, v.y, h0, l0);
            split2(v.z, v.w, h1, l1);
            uint32_t* ph = (uint32_t*)&Ahs[ar0 * AST + ac0 * 4];
            uint32_t* pl = (uint32_t*)&Als[ar0 * AST + ac0 * 4];
            ph[0] = h0; ph[1] = h1;
            pl[0] = l0; pl[1] = l1;
        }
        {
            float4 v = va1;
            uint32_t h0, l0, h1, l1;
            split2(v.x, v.y, h0, l0);
            split2(v.z, v.w, h1, l1);
            uint32_t* ph = (uint32_t*)&Ahs[ar1 * AST + ac1 * 4];
            uint32_t* pl = (uint32_t*)&Als[ar1 * AST + ac1 * 4];
            ph[0] = h0; ph[1] = h1;
            pl[0] = l0; pl[1] = l1;
        }
        *(uint4*)&Bhs[brow * AST + bseg * 8] = vbh;
        *(uint4*)&Bls[brow * AST + bseg * 8] = vbl;
        __syncthreads();

        if (c + 1 < 4) {
            const int kn = (c + 1) * 32;
            va0 = *(const float4*)&A[(long)(bm + ar0) * K + kn + ac0 * 4];
            va1 = *(const float4*)&A[(long)(bm + ar1) * K + kn + ac1 * 4];
            vbh = *(const uint4*)&Bh[(long)(bn + brow) * K + kn + bseg * 8];
            vbl = *(const uint4*)&Bl[(long)(bn + brow) * K + kn + bseg * 8];
        }

#pragma unroll
        for (int ks = 0; ks < 2; ks++) {
            int kk = ks * 16 + tig * 2;
            int r = wm * 16;
            uint32_t ah0 = *(const uint32_t*)&Ahs[(r + gid    ) * AST + kk    ];
            uint32_t ah1 = *(const uint32_t*)&Ahs[(r + gid + 8) * AST + kk    ];
            uint32_t ah2 = *(const uint32_t*)&Ahs[(r + gid    ) * AST + kk + 8];
            uint32_t ah3 = *(const uint32_t*)&Ahs[(r + gid + 8) * AST + kk + 8];
            uint32_t al0 = *(const uint32_t*)&Als[(r + gid    ) * AST + kk    ];
            uint32_t al1 = *(const uint32_t*)&Als[(r + gid + 8) * AST + kk    ];
            uint32_t al2 = *(const uint32_t*)&Als[(r + gid    ) * AST + kk + 8];
            uint32_t al3 = *(const uint32_t*)&Als[(r + gid + 8) * AST + kk + 8];
#pragma unroll
            for (int nb = 0; nb < 4; nb++) {
                int nr = wn * 32 + nb * 8 + gid;
                uint32_t bh0 = *(const uint32_t*)&Bhs[nr * AST + kk    ];
                uint32_t bh1 = *(const uint32_t*)&Bhs[nr * AST + kk + 8];
                uint32_t bl0 = *(const uint32_t*)&Bls[nr * AST + kk    ];
                uint32_t bl1 = *(const uint32_t*)&Bls[nr * AST + kk + 8];
                mma_bf16(acc[nb], ah0, ah1, ah2, ah3, bh0, bh1);
                mma_bf16(acc[nb], ah0, ah1, ah2, ah3, bl0, bl1);
                mma_bf16(acc[nb], al0, al1, al2, al3, bh0, bh1);
            }
        }
        __syncthreads();
    }

    const int rowA = bm + wm * 16 + gid, rowB = rowA + 8;
#pragma unroll
    for (int nb = 0; nb < 4; nb++) {
        int col = bn + wn * 32 + nb * 8 + tig * 2;
        float b0 = bias[col], b1v = bias[col + 1];
        float v0 = acc[nb][0] + b0, v1 = acc[nb][1] + b1v;
        float v2 = acc[nb][2] + b0, v3 = acc[nb][3] + b1v;
        float2 xA = *(const float2*)&xres[(long)rowA * N + col];
        float2 xB = *(const float2*)&xres[(long)rowB * N + col];
        float w0 = v0 + xA.x, w1 = v1 + xA.y;
        float w2 = v2 + xB.x, w3 = v3 + xB.y;
        *(float2*)&C[(long)rowA * N + col] = make_float2(w0, w1);
        *(float2*)&C[(long)rowB * N + col] = make_float2(w2, w3);
        float cs0 = w0 + w2, cs1 = w1 + w3;
        float cq0 = w0 * w0 + w2 * w2, cq1 = w1 * w1 + w3 * w3;
#pragma unroll
        for (int mk = 4; mk < 32; mk <<= 1) {
            cs0 += __shfl_xor_sync(0xFFFFFFFF, cs0, mk);
            cs1 += __shfl_xor_sync(0xFFFFFFFF, cs1, mk);
            cq0 += __shfl_xor_sync(0xFFFFFFFF, cq0, mk);
            cq1 += __shfl_xor_sync(0xFFFFFFFF, cq1, mk);
        }
        if (gid == 0) {
            atomicAdd(&sums_out[col], cs0);
            atomicAdd(&sums_out[CC + col], cq0);
            atomicAdd(&sums_out[col + 1], cs1);
            atomicAdd(&sums_out[CC + col + 1], cq1);
        }
    }
}

// ---------------- BN affine apply ----------------
__global__ __launch_bounds__(256) void bn_affine(const float* __restrict__ u,
        const float* __restrict__ sums, const float* __restrict__ g,
        const float* __restrict__ b, float* __restrict__ out) {
    int i = blockIdx.x * 256 + threadIdx.x;
    if (i >= NN * 32) return;
    int c4 = i & 31;
    float4 v = ((const float4*)u)[i];
    float o[4] = {v.x, v.y, v.z, v.w};
#pragma unroll
    for (int k = 0; k < 4; k++) {
        int c = c4 * 4 + k;
        float mean = sums[c] * (1.f / NN);
        float var  = sums[CC + c] * (1.f / NN) - mean * mean;
        float sc   = rsqrtf(var + BN_EPS) * g[c];
        o[k] = (o[k] - mean) * sc + b[c];
    }
    ((float4*)out)[i] = make_float4(o[0], o[1], o[2], o[3]);
}

// ---------------- mma.sync flash attention (BQ=128, cp.async double-buffered K/V) ----
#define EXP2_SCALE 0.25503480f
#define QK_STRIDE 40
#define VT_STRIDE 136

__global__ __launch_bounds__(256, 1) void mma_attn(const __nv_bfloat16* __restrict__ qb,
        const __nv_bfloat16* __restrict__ kb, const __nv_bfloat16* __restrict__ vtb,
        float* __restrict__ out) {
    __shared__ uint16_t Qs[128 * QK_STRIDE];
    __shared__ uint16_t Ks[2][128 * QK_STRIDE];
    __shared__ uint16_t Vts[2][32 * VT_STRIDE];

    const int tid = threadIdx.x;
    const int wid = tid >> 5, lane = tid & 31;
    const int gid = lane >> 2, tig = lane & 3;
    const int h = blockIdx.y;
    const int qbase = blockIdx.x * 128;
    const int r0 = wid * 16;

    const uint16_t* Qg = (const uint16_t*)(qb + ((long)h * NN + qbase) * 32);
#pragma unroll
    for (int it = 0; it < 2; it++) {
        int i = tid + it * 256;
        int row = i >> 2, seg = i & 3;
        *(uint4*)&Qs[row * QK_STRIDE + seg * 8] = *(const uint4*)&Qg[row * 32 + seg * 8];
    }

    auto pre_kv = [&](int st, int kb0) {
        const uint16_t* Kg = (const uint16_t*)(kb + ((long)h * NN + kb0) * 32);
#pragma unroll
        for (int it = 0; it < 2; it++) {
            int i = tid + it * 256;
            int row = i >> 2, seg = i & 3;
            CP16(smem_u32(&Ks[st][row * QK_STRIDE + seg * 8]), &Kg[row * 32 + seg * 8]);
        }
        const uint16_t* Vg = (const uint16_t*)(vtb + ((long)h * 32) * NN + kb0);
#pragma unroll
        for (int it = 0; it < 2; it++) {
            int i = tid + it * 256;
            int d = i >> 4, seg = i & 15;
            CP16(smem_u32(&Vts[st][d * VT_STRIDE + seg * 8]), &Vg[(long)d * NN + seg * 8]);
        }
    };

    pre_kv(0, 0);
    CP_COMMIT();
    __syncthreads();

    uint32_t aq[2][4];
#pragma unroll
    for (int t = 0; t < 2; t++) {
        int k = t * 16 + tig * 2;
        aq[t][0] = *(const uint32_t*)&Qs[(r0 + gid    ) * QK_STRIDE + k    ];
        aq[t][1] = *(const uint32_t*)&Qs[(r0 + gid + 8) * QK_STRIDE + k    ];
        aq[t][2] = *(const uint32_t*)&Qs[(r0 + gid    ) * QK_STRIDE + k + 8];
        aq[t][3] = *(const uint32_t*)&Qs[(r0 + gid + 8) * QK_STRIDE + k + 8];
    }

    float oacc[4][4] = {};
    float rs0 = 0.f, rs1 = 0.f;

    for (int kt = 0; kt < NN / 128; kt++) {
        const int st = kt & 1;
        if (kt + 1 < NN / 128) {
            pre_kv(st ^ 1, (kt + 1) * 128);
            CP_COMMIT();
            CP_WAIT1();
        } else {
            CP_WAIT0();
        }
        __syncthreads();

        float sacc[16][4];
#pragma unroll
        for (int j = 0; j < 16; j++) { sacc[j][0] = sacc[j][1] = sacc[j][2] = sacc[j][3] = 0.f; }
#pragma unroll
        for (int j = 0; j < 16; j++) {
#pragma unroll
            for (int t = 0; t < 2; t++) {
                int k = t * 16 + tig * 2;
                uint32_t b0 = *(const uint32_t*)&Ks[st][(8 * j + gid) * QK_STRIDE + k    ];
                uint32_t b1 = *(const uint32_t*)&Ks[st][(8 * j + gid) * QK_STRIDE + k + 8];
                mma_bf16(sacc[j], aq[t][0], aq[t][1], aq[t][2], aq[t][3], b0, b1);
            }
        }

        uint32_t pf[16][2];
#pragma unroll
        for (int j = 0; j < 16; j++) {
            float p0 = fast_exp2(sacc[j][0] * EXP2_SCALE);
            float p1 = fast_exp2(sacc[j][1] * EXP2_SCALE);
            float p2 = fast_exp2(sacc[j][2] * EXP2_SCALE);
            float p3 = fast_exp2(sacc[j][3] * EXP2_SCALE);
            rs0 += p0 + p1;
            rs1 += p2 + p3;
            pf[j][0] = pack_bf16(p0, p1);
            pf[j][1] = pack_bf16(p2, p3);
        }

#pragma unroll
        for (int t = 0; t < 8; t++) {
            uint32_t a0 = pf[2 * t][0], a1 = pf[2 * t][1];
            uint32_t a2 = pf[2 * t + 1][0], a3 = pf[2 * t + 1][1];
            int k = t * 16 + tig * 2;
#pragma unroll
            for (int n = 0; n < 4; n++) {
                uint32_t b0 = *(const uint32_t*)&Vts[st][(8 * n + gid) * VT_STRIDE + k    ];
                uint32_t b1 = *(const uint32_t*)&Vts[st][(8 * n + gid) * VT_STRIDE + k + 8];
                mma_bf16(oacc[n], a0, a1, a2, a3, b0, b1);
            }
        }
        __syncthreads();
    }

    rs0 += __shfl_xor_sync(0xFFFFFFFF, rs0, 1);
    rs0 += __shfl_xor_sync(0xFFFFFFFF, rs0, 2);
    rs1 += __shfl_xor_sync(0xFFFFFFFF, rs1, 1);
    rs1 += __shfl_xor_sync(0xFFFFFFFF, rs1, 2);
    float inv0 = 1.f / rs0, inv1 = 1.f / rs1;

    int rowA = qbase + r0 + gid, rowB = rowA + 8;
    float* poA = out + (long)rowA * CC + h * 32 + tig * 2;
    float* poB = out + (long)rowB * CC + h * 32 + tig * 2;
#pragma unroll
    for (int n = 0; n < 4; n++) {
        *(float2*)(poA + n * 8) = make_float2(oacc[n][0] * inv0, oacc[n][1] * inv0);
        *(float2*)(poB + n * 8) = make_float2(oacc[n][2] * inv1, oacc[n][3] * inv1);
    }
}

// ---------------- head MLP: warp-per-node, low smem ----------------
__global__ __launch_bounds__(256) void head_warp(const float* __restrict__ x,
        const float* __restrict__ w1, const float* __restrict__ b1,
        const float* __restrict__ w2, const float* __restrict__ b2,
        const float* __restrict__ w3, const float* __restrict__ b3,
        float* __restrict__ out) {
    __shared__ float y1s[8][64];
    __shared__ float y2s[8][32];
    int tid = threadIdx.x;
    int wid = tid >> 5, lane = tid & 31;
    int n = blockIdx.x * 8 + wid;

    float4 xv = *(const float4*)&x[(long)n * 128 + lane * 4];

    for (int o = 0; o < 64; o++) {
        float4 wv = *(const float4*)&w1[o * 128 + lane * 4];
        float p = xv.x * wv.x + xv.y * wv.y + xv.z * wv.z + xv.w * wv.w;
#pragma unroll
        for (int mk = 16; mk > 0; mk >>= 1) p += __shfl_xor_sync(0xFFFFFFFF, p, mk);
        if (lane == 0) y1s[wid][o] = fmaxf(p + b1[o], 0.f);
    }
    __syncwarp();
    float ya = y1s[wid][lane * 2], yb = y1s[wid][lane * 2 + 1];
    for (int o = 0; o < 32; o++) {
        float2 wv = *(const float2*)&w2[o * 64 + lane * 2];
        float p = ya * wv.x + yb * wv.y;
#pragma unroll
        for (int mk = 16; mk > 0; mk >>= 1) p += __shfl_xor_sync(0xFFFFFFFF, p, mk);
        if (lane == 0) y2s[wid][o] = fmaxf(p + b2[o], 0.f);
    }
    __syncwarp();
    float p = y2s[wid][lane] * w3[lane];
#pragma unroll
    for (int mk = 16; mk > 0; mk >>= 1) p += __shfl_xor_sync(0xFFFFFFFF, p, mk);
    if (lane == 0) out[n] = p + b3[0];
}

// ---------------- host orchestration ----------------
static __nv_bfloat16 *s_whi, *s_wlo;

extern "C" void kernel_launch(void* const* d_in, const int* in_sizes, int n_in,
                              void* d_out, int out_size) {
    const float* x_in      = (const float*)d_in[0];
    const int*   edge      = (const int*)  d_in[1];
    const float* gin_w1    = (const float*)d_in[2];
    const float* gin_b1    = (const float*)d_in[3];
    const float* gin_w2    = (const float*)d_in[4];
    const float* gin_b2    = (const float*)d_in[5];
    const float* attn_in_w = (const float*)d_in[6];
    const float* attn_in_b = (const float*)d_in[7];
    const float* attn_o_w  = (const float*)d_in[8];
    const float* attn_o_b  = (const float*)d_in[9];
    const float* n1_g = (const float*)d_in[10];
    const float* n1_b = (const float*)d_in[11];
    const float* n2_g = (const float*)d_in[12];
    const float* n2_b = (const float*)d_in[13];
    const float* n3_g = (const float*)d_in[14];
    const float* n3_b = (const float*)d_in[15];
    const float* mlp_w1 = (const float*)d_in[16];
    const float* mlp_b1 = (const float*)d_in[17];
    const float* mlp_w2 = (const float*)d_in[18];
    const float* mlp_b2 = (const float*)d_in[19];
    const float* hw1 = (const float*)d_in[20];
    const float* hb1 = (const float*)d_in[21];
    const float* hw2 = (const float*)d_in[22];
    const float* hb2 = (const float*)d_in[23];
    const float* hw3 = (const float*)d_in[24];
    const float* hb3 = (const float*)d_in[25];
    float* out = (float*)d_out;

    int E = in_sizes[1] / 2;

    float *p_x, *p_agg, *p_t1, *p_t2, *p_h1, *p_h2, *p_sums;
    int *p_deg;
    __nv_bfloat16 *p_qb, *p_kb, *p_vtb;
    cudaGetSymbolAddress((void**)&p_x,  g_x);
    cudaGetSymbolAddress((void**)&p_agg, g_agg);
    cudaGetSymbolAddress((void**)&p_t1, g_t1);
    cudaGetSymbolAddress((void**)&p_t2, g_t2);
    cudaGetSymbolAddress((void**)&p_h1, g_h1);
    cudaGetSymbolAddress((void**)&p_h2, g_h2);
    cudaGetSymbolAddress((void**)&p_sums, g_bnsums);
    cudaGetSymbolAddress((void**)&p_deg, g_deg);
    cudaGetSymbolAddress((void**)&p_qb, g_qb);
    cudaGetSymbolAddress((void**)&p_kb, g_kb);
    cudaGetSymbolAddress((void**)&p_vtb, g_vtb);
    cudaGetSymbolAddress((void**)&s_whi, g_whi);
    cudaGetSymbolAddress((void**)&s_wlo, g_wlo);

    conv_w<<<(WTOTAL + 255) / 256, 256>>>(gin_w1, gin_w2, attn_in_w, attn_o_w, mlp_w1, mlp_w2);
    cudaMemsetAsync(p_sums, 0, 12 * 2 * CC * sizeof(float));
    cudaMemsetAsync(p_deg, 0, (NN + 1) * sizeof(int));
    hist_kernel<<<(E + 255) / 256, 256>>>(edge, E);
    scan_kernel<<<1, 1024>>>();
    fill_kernel<<<(E + 255) / 256, 256>>>(edge, E);

    for (int i = 0; i < LL; i++) {
        const float* xcur = (i == 0) ? x_in : p_x;
        const float* gb1 = gin_b1 + (long)i * CC;
        const float* gb2 = gin_b2 + (long)i * CC;
        const float* aib = attn_in_b + (long)i * 3 * CC;
        const float* aob = attn_o_b + (long)i * CC;
        const float* mb1 = mlp_b1 + (long)i * 2 * CC;
        const float* mb2 = mlp_b2 + (long)i * CC;
        float* s1 = p_sums + (3 * i + 0) * 2 * CC;
        float* s2 = p_sums + (3 * i + 1) * 2 * CC;
        float* s3 = p_sums + (3 * i + 2) * 2 * CC;

        // ---- gather, then fused qkv||gin1, then attention ----
        gather_kernel<<<NN / 8, 256>>>(xcur, p_agg);
        gemm_qkv_gin1<<<512, 256>>>(xcur,
            s_whi + WOFF_AIN + i * 3 * CC * CC, s_wlo + WOFF_AIN + i * 3 * CC * CC, aib,
            p_qb, p_kb, p_vtb,
            p_agg, s_whi + WOFF_GIN1 + i * CC * CC, s_wlo + WOFF_GIN1 + i * CC * CC, gb1, p_t1);
        mma_attn<<<dim3(NN / 128, HEADS), 256>>>(p_qb, p_kb, p_vtb, p_agg);

        // ---- fused gin2 (t1->h1,s1) || aout (agg->h2,s2) ----
        gemm_dual_e3<<<256, 256>>>(
            p_t1, s_whi + WOFF_GIN2 + i * CC * CC, s_wlo + WOFF_GIN2 + i * CC * CC, gb2, p_h1, s1,
            p_agg, s_whi + WOFF_AOUT + i * CC * CC, s_wlo + WOFF_AOUT + i * CC * CC, aob, p_h2, s2,
            xcur);

        // ---- MLP ----
        gemm_tc<2, 1><<<dim3(4, 64), 256>>>(p_h1, p_h2,
            s_whi + WOFF_MW1 + i * 2 * CC * CC, s_wlo + WOFF_MW1 + i * 2 * CC * CC, mb1, p_t1,
            nullptr, nullptr, nullptr, nullptr, nullptr,
            s1, n1_g + i * CC, n1_b + i * CC, s2, n2_g + i * CC, n2_b + i * CC,
            p_t2, NN, 2 * CC, CC);
        gemm_tc<0, 3><<<dim3(2, 64), 256>>>(p_t1, nullptr,
            s_whi + WOFF_MW2 + i * 2 * CC * CC, s_wlo + WOFF_MW2 + i * 2 * CC * CC, mb2, p_agg,
            nullptr, nullptr, nullptr, p_t2, s3,
            nullptr, nullptr, nullptr, nullptr, nullptr, nullptr, nullptr, NN, CC, 2 * CC);
        bn_affine<<<NN * 32 / 256, 256>>>(p_agg, s3, n3_g + i * CC, n3_b + i * CC, p_x);
    }

    // ---- head ----
    head_warp<<<NN / 8, 256>>>(p_x, hw1, hb1, hw2, hb2, hw3, hb3, out);
}

// round 16
// speedup vs baseline: 1.3627x; 1.0083x over previous
#include <cuda_runtime.h>
#include <cuda_bf16.h>
#include <cstdint>

#define NN 4096
#define CC 128
#define LL 4
#define HEADS 4
#define BN_EPS 1e-5f
#define EMAX 262144

// ---------------- scratch (static device globals; no allocation) ----------------
__device__ float g_x  [NN * CC];
__device__ float g_agg[NN * CC];
__device__ float g_t1 [NN * 384];
__device__ float g_t2 [NN * CC];
__device__ float g_h1 [NN * CC];
__device__ float g_h2 [NN * CC];
__device__ float g_bnsums[12 * 2 * CC];
__device__ int   g_deg[NN + 1];
__device__ int   g_cur[NN];
__device__ int   g_csr[EMAX];
__device__ __nv_bfloat16 g_qb [HEADS * NN * 32];
__device__ __nv_bfloat16 g_kb [HEADS * NN * 32];
__device__ __nv_bfloat16 g_vtb[HEADS * 32 * NN];

// concatenated hi/lo bf16 weights
#define WOFF_GIN1 0
#define WOFF_GIN2 65536
#define WOFF_AIN  131072
#define WOFF_AOUT 327680
#define WOFF_MW1  393216
#define WOFF_MW2  524288
#define WTOTAL    655360
__device__ __nv_bfloat16 g_whi[WTOTAL];
__device__ __nv_bfloat16 g_wlo[WTOTAL];

// ---------------- mma.sync / ptx helpers ----------------
__device__ __forceinline__ void mma_bf16(float* d, uint32_t a0, uint32_t a1, uint32_t a2,
                                         uint32_t a3, uint32_t b0, uint32_t b1) {
    asm volatile(
        "mma.sync.aligned.m16n8k16.row.col.f32.bf16.bf16.f32 "
        "{%0,%1,%2,%3}, {%4,%5,%6,%7}, {%8,%9}, {%0,%1,%2,%3};"
        : "+f"(d[0]), "+f"(d[1]), "+f"(d[2]), "+f"(d[3])
        : "r"(a0), "r"(a1), "r"(a2), "r"(a3), "r"(b0), "r"(b1));
}
__device__ __forceinline__ float fast_exp2(float x) {
    float y; asm("ex2.approx.ftz.f32 %0, %1;" : "=f"(y) : "f"(x)); return y;
}
__device__ __forceinline__ uint32_t pack_bf16(float lo, float hi) {
    uint32_t r; asm("cvt.rn.bf16x2.f32 %0, %1, %2;" : "=r"(r) : "f"(hi), "f"(lo)); return r;
}
__device__ __forceinline__ void split2(float x, float y, uint32_t& hi, uint32_t& lo) {
    __nv_bfloat16 hx = __float2bfloat16(x), hy = __float2bfloat16(y);
    float lx = x - __bfloat162float(hx), ly = y - __bfloat162float(hy);
    hi = pack_bf16(__bfloat162float(hx), __bfloat162float(hy));
    lo = pack_bf16(lx, ly);
}
__device__ __forceinline__ uint32_t smem_u32(const void* p) {
    return (uint32_t)__cvta_generic_to_shared(p);
}
#define CP16(dst_u32, src) \
    asm volatile("cp.async.cg.shared.global [%0], [%1], 16;" :: "r"(dst_u32), "l"(src))
#define CP_COMMIT() asm volatile("cp.async.commit_group;")
#define CP_WAIT1()  asm volatile("cp.async.wait_group 1;")
#define CP_WAIT0()  asm volatile("cp.async.wait_group 0;")

// ---------------- weight hi/lo conversion ----------------
__global__ void conv_w(const float* __restrict__ w_gin1, const float* __restrict__ w_gin2,
                       const float* __restrict__ w_ain,  const float* __restrict__ w_aout,
                       const float* __restrict__ w_m1,   const float* __restrict__ w_m2) {
    int id = blockIdx.x * 256 + threadIdx.x;
    if (id >= WTOTAL) return;
    const float* src; int off;
    if      (id < WOFF_GIN2) { src = w_gin1; off = id; }
    else if (id < WOFF_AIN)  { src = w_gin2; off = id - WOFF_GIN2; }
    else if (id < WOFF_AOUT) { src = w_ain;  off = id - WOFF_AIN; }
    else if (id < WOFF_MW1)  { src = w_aout; off = id - WOFF_AOUT; }
    else if (id < WOFF_MW2)  { src = w_m1;   off = id - WOFF_MW1; }
    else                     { src = w_m2;   off = id - WOFF_MW2; }
    float v = src[off];
    __nv_bfloat16 h = __float2bfloat16(v);
    g_whi[id] = h;
    g_wlo[id] = __float2bfloat16(v - __bfloat162float(h));
}

// ---------------- CSR build ----------------
__global__ void hist_kernel(const int* __restrict__ ei, int E) {
    int e = blockIdx.x * blockDim.x + threadIdx.x;
    if (e < E) atomicAdd(&g_deg[ei[E + e] + 1], 1);
}

__global__ void scan_kernel() {
    __shared__ int part[1024];
    int t = threadIdx.x;
    int base = t * 4;
    int x0 = g_deg[base], x1 = g_deg[base + 1], x2 = g_deg[base + 2], x3 = g_deg[base + 3];
    x1 += x0; x2 += x1; x3 += x2;
    part[t] = x3;
    __syncthreads();
    for (int off = 1; off < 1024; off <<= 1) {
        int v = (t >= off) ? part[t - off] : 0;
        __syncthreads();
        part[t] += v;
        __syncthreads();
    }
    int add = (t > 0) ? part[t - 1] : 0;
    int v0 = x0 + add, v1 = x1 + add, v2 = x2 + add, v3 = x3 + add;
    g_deg[base] = v0; g_deg[base + 1] = v1; g_deg[base + 2] = v2; g_deg[base + 3] = v3;
    g_cur[base] = v0; g_cur[base + 1] = v1; g_cur[base + 2] = v2; g_cur[base + 3] = v3;
    __syncthreads();
    if (t == 0) g_deg[NN] += g_deg[NN - 1];
}

__global__ void fill_kernel(const int* __restrict__ ei, int E) {
    int e = blockIdx.x * blockDim.x + threadIdx.x;
    if (e >= E) return;
    int s = ei[e], d = ei[E + e];
    int pos = atomicAdd(&g_cur[d], 1);
    g_csr[pos] = s;
}

// ---------------- GIN gather (layer 0: plain) ----------------
__global__ __launch_bounds__(256) void gather_kernel(const float* __restrict__ x,
                                                     float* __restrict__ agg) {
    int wg = (blockIdx.x * 256 + threadIdx.x) >> 5;
    int lane = threadIdx.x & 31;
    if (wg >= NN) return;
    int beg = g_deg[wg], end = g_deg[wg + 1];
    float4 acc = *(const float4*)&x[(long)wg * CC + lane * 4];
    for (int j = beg; j < end; j++) {
        int s = g_csr[j];
        float4 v = *(const float4*)&x[(long)s * CC + lane * 4];
        acc.x += v.x; acc.y += v.y; acc.z += v.z; acc.w += v.w;
    }
    *(float4*)&agg[(long)wg * CC + lane * 4] = acc;
}

// ---------------- fused BN-affine + gather (layers 1..3) ----------------
// x = aff(u); agg = aff(u[self]) + sum aff(u[nbr])
__global__ __launch_bounds__(256) void bn_gather(const float* __restrict__ u,
        const float* __restrict__ sums, const float* __restrict__ g,
        const float* __restrict__ b, float* __restrict__ x, float* __restrict__ agg) {
    int wg = (blockIdx.x * 256 + threadIdx.x) >> 5;
    int lane = threadIdx.x & 31;
    if (wg >= NN) return;
    float mean[4], sc[4], bb[4];
#pragma unroll
    for (int k = 0; k < 4; k++) {
        int c = lane * 4 + k;
        float m = sums[c] * (1.f / NN);
        float var = sums[CC + c] * (1.f / NN) - m * m;
        mean[k] = m;
        sc[k] = rsqrtf(var + BN_EPS) * g[c];
        bb[k] = b[c];
    }
    float4 uv = *(const float4*)&u[(long)wg * CC + lane * 4];
    float4 xv = make_float4((uv.x - mean[0]) * sc[0] + bb[0],
                            (uv.y - mean[1]) * sc[1] + bb[1],
                            (uv.z - mean[2]) * sc[2] + bb[2],
                            (uv.w - mean[3]) * sc[3] + bb[3]);
    *(float4*)&x[(long)wg * CC + lane * 4] = xv;
    float4 acc = xv;
    int beg = g_deg[wg], end = g_deg[wg + 1];
    for (int j = beg; j < end; j++) {
        int s = g_csr[j];
        float4 v = *(const float4*)&u[(long)s * CC + lane * 4];
        acc.x += (v.x - mean[0]) * sc[0] + bb[0];
        acc.y += (v.y - mean[1]) * sc[1] + bb[1];
        acc.z += (v.z - mean[2]) * sc[2] + bb[2];
        acc.w += (v.w - mean[3]) * sc[3] + bb[3];
    }
    *(float4*)&agg[(long)wg * CC + lane * 4] = acc;
}

// ---------------- tensor-core GEMM (hi/lo split, register-prefetch) — R13 proven ------
#define AST 40
template <int LMODE, int EMODE>
__global__ __launch_bounds__(256) void gemm_tc(const float* __restrict__ A,
        const float* __restrict__ A2,
        const __nv_bfloat16* __restrict__ Bh, const __nv_bfloat16* __restrict__ Bl,
        const float* __restrict__ bias, float* __restrict__ C,
        __nv_bfloat16* __restrict__ qb, __nv_bfloat16* __restrict__ kbuf,
        __nv_bfloat16* __restrict__ vtb,
        const float* __restrict__ xres, float* __restrict__ sums_out,
        const float* __restrict__ s1, const float* __restrict__ g1, const float* __restrict__ b1,
        const float* __restrict__ s2, const float* __restrict__ g2, const float* __restrict__ b2,
        float* __restrict__ hout, int M, int N, int K) {
    __shared__ uint16_t Ahs[64 * AST], Als[64 * AST];
    __shared__ uint16_t Bhs[64 * AST], Bls[64 * AST];
    __shared__ float csc1[128], cof1[128], csc2[128], cof2[128];
    const int tid = threadIdx.x;
    const int warp = tid >> 5, lane = tid & 31;
    const int gid = lane >> 2, tig = lane & 3;
    const int wm = warp >> 1, wn = warp & 1;
    const int bm = blockIdx.y * 64, bn = blockIdx.x * 64;
    float acc[4][4] = {};

    if (LMODE == 2) {
        int c = tid & 127;
        const float* ss = (tid < 128) ? s1 : s2;
        const float* gg = (tid < 128) ? g1 : g2;
        const float* bb2 = (tid < 128) ? b1 : b2;
        float mean = ss[c] * (1.f / NN);
        float var  = ss[CC + c] * (1.f / NN) - mean * mean;
        float sc   = rsqrtf(var + BN_EPS) * gg[c];
        float off  = bb2[c] - mean * sc;
        if (tid < 128) { csc1[c] = sc; cof1[c] = off; }
        else           { csc2[c] = sc; cof2[c] = off; }
        __syncthreads();
    }

    const int nch = K >> 5;
    const int j0 = tid * 2, j1 = tid * 2 + 1;
    const int ar0 = j0 >> 3, ac0 = j0 & 7;
    const int ar1 = j1 >> 3, ac1 = j1 & 7;
    const int brow = tid >> 2, bseg = tid & 3;

    float4 va0, va1, wa0, wa1;
    uint4 vbh, vbl;

    va0 = *(const float4*)&A[(long)(bm + ar0) * K + ac0 * 4];
    va1 = *(const float4*)&A[(long)(bm + ar1) * K + ac1 * 4];
    if (LMODE == 2) {
        wa0 = *(const float4*)&A2[(long)(bm + ar0) * K + ac0 * 4];
        wa1 = *(const float4*)&A2[(long)(bm + ar1) * K + ac1 * 4];
    }
    vbh = *(const uint4*)&Bh[(long)(bn + brow) * K + bseg * 8];
    vbl = *(const uint4*)&Bl[(long)(bn + brow) * K + bseg * 8];

    for (int c = 0; c < nch; c++) {
        const int k0 = c * 32;
        {
            float4 v = va0;
            int cbase = k0 + ac0 * 4;
            if (LMODE == 2) {
                v.x = v.x * csc1[cbase]     + cof1[cbase]     + wa0.x * csc2[cbase]     + cof2[cbase];
                v.y = v.y * csc1[cbase + 1] + cof1[cbase + 1] + wa0.y * csc2[cbase + 1] + cof2[cbase + 1];
                v.z = v.z * csc1[cbase + 2] + cof1[cbase + 2] + wa0.z * csc2[cbase + 2] + cof2[cbase + 2];
                v.w = v.w * csc1[cbase + 3] + cof1[cbase + 3] + wa0.w * csc2[cbase + 3] + cof2[cbase + 3];
                if (blockIdx.x == 0)
                    *(float4*)&hout[(long)(bm + ar0) * K + cbase] = v;
            }
            uint32_t h0, l0, h1, l1;
            split2(v.x, v.y, h0, l0);
            split2(v.z, v.w, h1, l1);
            uint32_t* ph = (uint32_t*)&Ahs[ar0 * AST + ac0 * 4];
            uint32_t* pl = (uint32_t*)&Als[ar0 * AST + ac0 * 4];
            ph[0] = h0; ph[1] = h1;
            pl[0] = l0; pl[1] = l1;
        }
        {
            float4 v = va1;
            int cbase = k0 + ac1 * 4;
            if (LMODE == 2) {
                v.x = v.x * csc1[cbase]     + cof1[cbase]     + wa1.x * csc2[cbase]     + cof2[cbase];
                v.y = v.y * csc1[cbase + 1] + cof1[cbase + 1] + wa1.y * csc2[cbase + 1] + cof2[cbase + 1];
                v.z = v.z * csc1[cbase + 2] + cof1[cbase + 2] + wa1.z * csc2[cbase + 2] + cof2[cbase + 2];
                v.w = v.w * csc1[cbase + 3] + cof1[cbase + 3] + wa1.w * csc2[cbase + 3] + cof2[cbase + 3];
                if (blockIdx.x == 0)
                    *(float4*)&hout[(long)(bm + ar1) * K + cbase] = v;
            }
            uint32_t h0, l0, h1, l1;
            split2(v.x, v.y, h0, l0);
            split2(v.z, v.w, h1, l1);
            uint32_t* ph = (uint32_t*)&Ahs[ar1 * AST + ac1 * 4];
            uint32_t* pl = (uint32_t*)&Als[ar1 * AST + ac1 * 4];
            ph[0] = h0; ph[1] = h1;
            pl[0] = l0; pl[1] = l1;
        }
        *(uint4*)&Bhs[brow * AST + bseg * 8] = vbh;
        *(uint4*)&Bls[brow * AST + bseg * 8] = vbl;
        __syncthreads();

        if (c + 1 < nch) {
            const int kn = (c + 1) * 32;
            va0 = *(const float4*)&A[(long)(bm + ar0) * K + kn + ac0 * 4];
            va1 = *(const float4*)&A[(long)(bm + ar1) * K + kn + ac1 * 4];
            if (LMODE == 2) {
                wa0 = *(const float4*)&A2[(long)(bm + ar0) * K + kn + ac0 * 4];
                wa1 = *(const float4*)&A2[(long)(bm + ar1) * K + kn + ac1 * 4];
            }
            vbh = *(const uint4*)&Bh[(long)(bn + brow) * K + kn + bseg * 8];
            vbl = *(const uint4*)&Bl[(long)(bn + brow) * K + kn + bseg * 8];
        }

#pragma unroll
        for (int ks = 0; ks < 2; ks++) {
            int kk = ks * 16 + tig * 2;
            int r = wm * 16;
            uint32_t ah0 = *(const uint32_t*)&Ahs[(r + gid    ) * AST + kk    ];
            uint32_t ah1 = *(const uint32_t*)&Ahs[(r + gid + 8) * AST + kk    ];
            uint32_t ah2 = *(const uint32_t*)&Ahs[(r + gid    ) * AST + kk + 8];
            uint32_t ah3 = *(const uint32_t*)&Ahs[(r + gid + 8) * AST + kk + 8];
            uint32_t al0 = *(const uint32_t*)&Als[(r + gid    ) * AST + kk    ];
            uint32_t al1 = *(const uint32_t*)&Als[(r + gid + 8) * AST + kk    ];
            uint32_t al2 = *(const uint32_t*)&Als[(r + gid    ) * AST + kk + 8];
            uint32_t al3 = *(const uint32_t*)&Als[(r + gid + 8) * AST + kk + 8];
#pragma unroll
            for (int nb = 0; nb < 4; nb++) {
                int nr = wn * 32 + nb * 8 + gid;
                uint32_t bh0 = *(const uint32_t*)&Bhs[nr * AST + kk    ];
                uint32_t bh1 = *(const uint32_t*)&Bhs[nr * AST + kk + 8];
                uint32_t bl0 = *(const uint32_t*)&Bls[nr * AST + kk    ];
                uint32_t bl1 = *(const uint32_t*)&Bls[nr * AST + kk + 8];
                mma_bf16(acc[nb], ah0, ah1, ah2, ah3, bh0, bh1);
                mma_bf16(acc[nb], ah0, ah1, ah2, ah3, bl0, bl1);
                mma_bf16(acc[nb], al0, al1, al2, al3, bh0, bh1);
            }
        }
        __syncthreads();
    }

    const int rowA = bm + wm * 16 + gid, rowB = rowA + 8;
#pragma unroll
    for (int nb = 0; nb < 4; nb++) {
        int col = bn + wn * 32 + nb * 8 + tig * 2;
        if (col >= N) continue;
        float b0 = bias[col], b1v = bias[col + 1];
        float v0 = acc[nb][0] + b0, v1 = acc[nb][1] + b1v;
        float v2 = acc[nb][2] + b0, v3 = acc[nb][3] + b1v;
        if (EMODE == 1) {
            v0 = fmaxf(v0, 0.f); v1 = fmaxf(v1, 0.f);
            v2 = fmaxf(v2, 0.f); v3 = fmaxf(v3, 0.f);
        }
        if (EMODE == 2) {
            int sec = col >> 7, hh = (col & 127) >> 5, d = col & 31;
            if (sec == 0) {
                *(uint32_t*)&qb[((hh << 12) + rowA) * 32 + d] = pack_bf16(v0, v1);
                *(uint32_t*)&qb[((hh << 12) + rowB) * 32 + d] = pack_bf16(v2, v3);
            } else if (sec == 1) {
                *(uint32_t*)&kbuf[((hh << 12) + rowA) * 32 + d] = pack_bf16(v0, v1);
                *(uint32_t*)&kbuf[((hh << 12) + rowB) * 32 + d] = pack_bf16(v2, v3);
            } else {
                vtb[((hh * 32 + d    ) << 12) + rowA] = __float2bfloat16(v0);
                vtb[((hh * 32 + d + 1) << 12) + rowA] = __float2bfloat16(v1);
                vtb[((hh * 32 + d    ) << 12) + rowB] = __float2bfloat16(v2);
                vtb[((hh * 32 + d + 1) << 12) + rowB] = __float2bfloat16(v3);
            }
        } else if (EMODE == 3) {
            float2 xA = *(const float2*)&xres[(long)rowA * N + col];
            float2 xB = *(const float2*)&xres[(long)rowB * N + col];
            float w0 = v0 + xA.x, w1 = v1 + xA.y;
            float w2 = v2 + xB.x, w3 = v3 + xB.y;
            *(float2*)&C[(long)rowA * N + col] = make_float2(w0, w1);
            *(float2*)&C[(long)rowB * N + col] = make_float2(w2, w3);
            float cs0 = w0 + w2, cs1 = w1 + w3;
            float cq0 = w0 * w0 + w2 * w2, cq1 = w1 * w1 + w3 * w3;
#pragma unroll
            for (int mk = 4; mk < 32; mk <<= 1) {
                cs0 += __shfl_xor_sync(0xFFFFFFFF, cs0, mk);
                cs1 += __shfl_xor_sync(0xFFFFFFFF, cs1, mk);
                cq0 += __shfl_xor_sync(0xFFFFFFFF, cq0, mk);
                cq1 += __shfl_xor_sync(0xFFFFFFFF, cq1, mk);
            }
            if (gid == 0) {
                atomicAdd(&sums_out[col], cs0);
                atomicAdd(&sums_out[CC + col], cq0);
                atomicAdd(&sums_out[col + 1], cs1);
                atomicAdd(&sums_out[CC + col + 1], cq1);
            }
        } else {
            *(float2*)&C[(long)rowA * N + col] = make_float2(v0, v1);
            *(float2*)&C[(long)rowB * N + col] = make_float2(v2, v3);
        }
    }
}

// ---------------- fused qkv (blocks 0..383, EMODE2) || gin1 (blocks 384..511, EMODE1) --
__global__ __launch_bounds__(256) void gemm_qkv_gin1(
        const float* __restrict__ xcur,
        const __nv_bfloat16* __restrict__ Bh_q, const __nv_bfloat16* __restrict__ Bl_q,
        const float* __restrict__ aib,
        __nv_bfloat16* __restrict__ qb, __nv_bfloat16* __restrict__ kbuf,
        __nv_bfloat16* __restrict__ vtb,
        const float* __restrict__ agg,
        const __nv_bfloat16* __restrict__ Bh_g, const __nv_bfloat16* __restrict__ Bl_g,
        const float* __restrict__ gb1, float* __restrict__ t1) {
    __shared__ uint16_t Ahs[64 * AST], Als[64 * AST];
    __shared__ uint16_t Bhs[64 * AST], Bls[64 * AST];

    const bool isq = (blockIdx.x < 384);
    int bx, by;
    const float* A;
    const __nv_bfloat16 *Bh, *Bl;
    const float* bias;
    if (isq) {
        bx = blockIdx.x % 6; by = blockIdx.x / 6;
        A = xcur; Bh = Bh_q; Bl = Bl_q; bias = aib;
    } else {
        int lb = blockIdx.x - 384;
        bx = lb & 1; by = lb >> 1;
        A = agg; Bh = Bh_g; Bl = Bl_g; bias = gb1;
    }
    const int K = CC;
    const int tid = threadIdx.x;
    const int warp = tid >> 5, lane = tid & 31;
    const int gid = lane >> 2, tig = lane & 3;
    const int wm = warp >> 1, wn = warp & 1;
    const int bm = by * 64, bn = bx * 64;
    float acc[4][4] = {};

    const int j0 = tid * 2, j1 = tid * 2 + 1;
    const int ar0 = j0 >> 3, ac0 = j0 & 7;
    const int ar1 = j1 >> 3, ac1 = j1 & 7;
    const int brow = tid >> 2, bseg = tid & 3;

    float4 va0, va1;
    uint4 vbh, vbl;
    va0 = *(const float4*)&A[(long)(bm + ar0) * K + ac0 * 4];
    va1 = *(const float4*)&A[(long)(bm + ar1) * K + ac1 * 4];
    vbh = *(const uint4*)&Bh[(long)(bn + brow) * K + bseg * 8];
    vbl = *(const uint4*)&Bl[(long)(bn + brow) * K + bseg * 8];

#pragma unroll
    for (int c = 0; c < 4; c++) {
        {
            float4 v = va0;
            uint32_t h0, l0, h1, l1;
            split2(v.x, v.y, h0, l0);
            split2(v.z, v.w, h1, l1);
            uint32_t* ph = (uint32_t*)&Ahs[ar0 * AST + ac0 * 4];
            uint32_t* pl = (uint32_t*)&Als[ar0 * AST + ac0 * 4];
            ph[0] = h0; ph[1] = h1;
            pl[0] = l0; pl[1] = l1;
        }
        {
            float4 v = va1;
            uint32_t h0, l0, h1, l1;
            split2(v.x, v.y, h0, l0);
            split2(v.z, v.w, h1, l1);
            uint32_t* ph = (uint32_t*)&Ahs[ar1 * AST + ac1 * 4];
            uint32_t* pl = (uint32_t*)&Als[ar1 * AST + ac1 * 4];
            ph[0] = h0; ph[1] = h1;
            pl[0] = l0; pl[1] = l1;
        }
        *(uint4*)&Bhs[brow * AST + bseg * 8] = vbh;
        *(uint4*)&Bls[brow * AST + bseg * 8] = vbl;
        __syncthreads();

        if (c + 1 < 4) {
            const int kn = (c + 1) * 32;
            va0 = *(const float4*)&A[(long)(bm + ar0) * K + kn + ac0 * 4];
            va1 = *(const float4*)&A[(long)(bm + ar1) * K + kn + ac1 * 4];
            vbh = *(const uint4*)&Bh[(long)(bn + brow) * K + kn + bseg * 8];
            vbl = *(const uint4*)&Bl[(long)(bn + brow) * K + kn + bseg * 8];
        }

#pragma unroll
        for (int ks = 0; ks < 2; ks++) {
            int kk = ks * 16 + tig * 2;
            int r = wm * 16;
            uint32_t ah0 = *(const uint32_t*)&Ahs[(r + gid    ) * AST + kk    ];
            uint32_t ah1 = *(const uint32_t*)&Ahs[(r + gid + 8) * AST + kk    ];
            uint32_t ah2 = *(const uint32_t*)&Ahs[(r + gid    ) * AST + kk + 8];
            uint32_t ah3 = *(const uint32_t*)&Ahs[(r + gid + 8) * AST + kk + 8];
            uint32_t al0 = *(const uint32_t*)&Als[(r + gid    ) * AST + kk    ];
            uint32_t al1 = *(const uint32_t*)&Als[(r + gid + 8) * AST + kk    ];
            uint32_t al2 = *(const uint32_t*)&Als[(r + gid    ) * AST + kk + 8];
            uint32_t al3 = *(const uint32_t*)&Als[(r + gid + 8) * AST + kk + 8];
#pragma unroll
            for (int nb = 0; nb < 4; nb++) {
                int nr = wn * 32 + nb * 8 + gid;
                uint32_t bh0 = *(const uint32_t*)&Bhs[nr * AST + kk    ];
                uint32_t bh1 = *(const uint32_t*)&Bhs[nr * AST + kk + 8];
                uint32_t bl0 = *(const uint32_t*)&Bls[nr * AST + kk    ];
                uint32_t bl1 = *(const uint32_t*)&Bls[nr * AST + kk + 8];
                mma_bf16(acc[nb], ah0, ah1, ah2, ah3, bh0, bh1);
                mma_bf16(acc[nb], ah0, ah1, ah2, ah3, bl0, bl1);
                mma_bf16(acc[nb], al0, al1, al2, al3, bh0, bh1);
            }
        }
        __syncthreads();
    }

    const int rowA = bm + wm * 16 + gid, rowB = rowA + 8;
#pragma unroll
    for (int nb = 0; nb < 4; nb++) {
        int col = bn + wn * 32 + nb * 8 + tig * 2;
        float b0 = bias[col], b1v = bias[col + 1];
        float v0 = acc[nb][0] + b0, v1 = acc[nb][1] + b1v;
        float v2 = acc[nb][2] + b0, v3 = acc[nb][3] + b1v;
        if (isq) {
            int sec = col >> 7, hh = (col & 127) >> 5, d = col & 31;
            if (sec == 0) {
                *(uint32_t*)&qb[((hh << 12) + rowA) * 32 + d] = pack_bf16(v0, v1);
                *(uint32_t*)&qb[((hh << 12) + rowB) * 32 + d] = pack_bf16(v2, v3);
            } else if (sec == 1) {
                *(uint32_t*)&kbuf[((hh << 12) + rowA) * 32 + d] = pack_bf16(v0, v1);
                *(uint32_t*)&kbuf[((hh << 12) + rowB) * 32 + d] = pack_bf16(v2, v3);
            } else {
                vtb[((hh * 32 + d    ) << 12) + rowA] = __float2bfloat16(v0);
                vtb[((hh * 32 + d + 1) << 12) + rowA] = __float2bfloat16(v1);
                vtb[((hh * 32 + d    ) << 12) + rowB] = __float2bfloat16(v2);
                vtb[((hh * 32 + d + 1) << 12) + rowB] = __float2bfloat16(v3);
            }
        } else {
            v0 = fmaxf(v0, 0.f); v1 = fmaxf(v1, 0.f);
            v2 = fmaxf(v2, 0.f); v3 = fmaxf(v3, 0.f);
            *(float2*)&t1[(long)rowA * 128 + col] = make_float2(v0, v1);
            *(float2*)&t1[(long)rowB * 128 + col] = make_float2(v2, v3);
        }
    }
}

// ---------------- dual EMODE-3 GEMM (R14 proven) ----------------
__global__ __launch_bounds__(256) void gemm_dual_e3(
        const float* __restrict__ A_a, const __nv_bfloat16* __restrict__ Bh_a,
        const __nv_bfloat16* __restrict__ Bl_a, const float* __restrict__ bias_a,
        float* __restrict__ C_a, float* __restrict__ sums_a,
        const float* __restrict__ A_b, const __nv_bfloat16* __restrict__ Bh_b,
        const __nv_bfloat16* __restrict__ Bl_b, const float* __restrict__ bias_b,
        float* __restrict__ C_b, float* __restrict__ sums_b,
        const float* __restrict__ xres) {
    __shared__ uint16_t Ahs[64 * AST], Als[64 * AST];
    __shared__ uint16_t Bhs[64 * AST], Bls[64 * AST];

    const int half = (blockIdx.x >= 128);
    const int lb = blockIdx.x & 127;
    const float* A = half ? A_b : A_a;
    const __nv_bfloat16* Bh = half ? Bh_b : Bh_a;
    const __nv_bfloat16* Bl = half ? Bl_b : Bl_a;
    const float* bias = half ? bias_b : bias_a;
    float* C = half ? C_b : C_a;
    float* sums_out = half ? sums_b : sums_a;

    const int tid = threadIdx.x;
    const int warp = tid >> 5, lane = tid & 31;
    const int gid = lane >> 2, tig = lane & 3;
    const int wm = warp >> 1, wn = warp & 1;
    const int bm = (lb >> 1) * 64, bn = (lb & 1) * 64;
    const int K = CC, N = CC;
    float acc[4][4] = {};

    const int j0 = tid * 2, j1 = tid * 2 + 1;
    const int ar0 = j0 >> 3, ac0 = j0 & 7;
    const int ar1 = j1 >> 3, ac1 = j1 & 7;
    const int brow = tid >> 2, bseg = tid & 3;

    float4 va0, va1;
    uint4 vbh, vbl;
    va0 = *(const float4*)&A[(long)(bm + ar0) * K + ac0 * 4];
    va1 = *(const float4*)&A[(long)(bm + ar1) * K + ac1 * 4];
    vbh = *(const uint4*)&Bh[(long)(bn + brow) * K + bseg * 8];
    vbl = *(const uint4*)&Bl[(long)(bn + brow) * K + bseg * 8];

#pragma unroll
    for (int c = 0; c < 4; c++) {
        {
            float4 v = va0;
            uint32_t h0, l0, h1, l1;
            split2(v.x, v.y, h0, l0);
            split2(v.z, v.w, h1, l1);
            uint32_t* ph = (uint32_t*)&Ahs[ar0 * AST + ac0 * 4];
            uint32_t* pl = (uint32_t*)&Als[ar0 * AST + ac0 * 4];
            ph[0] = h0; ph[1] = h1;
            pl[0] = l0; pl[1] = l1;
        }
        {
            float4 v = va1;
            uint32_t h0, l0, h1, l1;
            split2(v.x, v.y, h0, l0);
            split2(v.z, v.w, h1, l1);
            uint32_t* ph = (uint32_t*)&Ahs[ar1 * AST + ac1 * 4];
            uint32_t* pl = (uint32_t*)&Als[ar1 * AST + ac1 * 4];
            ph[0] = h0; ph[1] = h1;
            pl[0] = l0; pl[1] = l1;
        }
        *(uint4*)&Bhs[brow * AST + bseg * 8] = vbh;
        *(uint4*)&Bls[brow * AST + bseg * 8] = vbl;
        __syncthreads();

        if (c + 1 < 4) {
            const int kn = (c + 1) * 32;
            va0 = *(const float4*)&A[(long)(bm + ar0) * K + kn + ac0 * 4];
            va1 = *(const float4*)&A[(long)(bm + ar1) * K + kn + ac1 * 4];
            vbh = *(const uint4*)&Bh[(long)(bn + brow) * K + kn + bseg * 8];
            vbl = *(const uint4*)&Bl[(long)(bn + brow) * K + kn + bseg * 8];
        }

#pragma unroll
        for (int ks = 0; ks < 2; ks++) {
            int kk = ks * 16 + tig * 2;
            int r = wm * 16;
            uint32_t ah0 = *(const uint32_t*)&Ahs[(r + gid    ) * AST + kk    ];
            uint32_t ah1 = *(const uint32_t*)&Ahs[(r + gid + 8) * AST + kk    ];
            uint32_t ah2 = *(const uint32_t*)&Ahs[(r + gid    ) * AST + kk + 8];
            uint32_t ah3 = *(const uint32_t*)&Ahs[(r + gid + 8) * AST + kk + 8];
            uint32_t al0 = *(const uint32_t*)&Als[(r + gid    ) * AST + kk    ];
            uint32_t al1 = *(const uint32_t*)&Als[(r + gid + 8) * AST + kk    ];
            uint32_t al2 = *(const uint32_t*)&Als[(r + gid    ) * AST + kk + 8];
            uint32_t al3 = *(const uint32_t*)&Als[(r + gid + 8) * AST + kk + 8];
#pragma unroll
            for (int nb = 0; nb < 4; nb++) {
                int nr = wn * 32 + nb * 8 + gid;
                uint32_t bh0 = *(const uint32_t*)&Bhs[nr * AST + kk    ];
                uint32_t bh1 = *(const uint32_t*)&Bhs[nr * AST + kk + 8];
                uint32_t bl0 = *(const uint32_t*)&Bls[nr * AST + kk    ];
                uint32_t bl1 = *(const uint32_t*)&Bls[nr * AST + kk + 8];
                mma_bf16(acc[nb], ah0, ah1, ah2, ah3, bh0, bh1);
                mma_bf16(acc[nb], ah0, ah1, ah2, ah3, bl0, bl1);
                mma_bf16(acc[nb], al0, al1, al2, al3, bh0, bh1);
            }
        }
        __syncthreads();
    }

    const int rowA = bm + wm * 16 + gid, rowB = rowA + 8;
#pragma unroll
    for (int nb = 0; nb < 4; nb++) {
        int col = bn + wn * 32 + nb * 8 + tig * 2;
        float b0 = bias[col], b1v = bias[col + 1];
        float v0 = acc[nb][0] + b0, v1 = acc[nb][1] + b1v;
        float v2 = acc[nb][2] + b0, v3 = acc[nb][3] + b1v;
        float2 xA = *(const float2*)&xres[(long)rowA * N + col];
        float2 xB = *(const float2*)&xres[(long)rowB * N + col];
        float w0 = v0 + xA.x, w1 = v1 + xA.y;
        float w2 = v2 + xB.x, w3 = v3 + xB.y;
        *(float2*)&C[(long)rowA * N + col] = make_float2(w0, w1);
        *(float2*)&C[(long)rowB * N + col] = make_float2(w2, w3);
        float cs0 = w0 + w2, cs1 = w1 + w3;
        float cq0 = w0 * w0 + w2 * w2, cq1 = w1 * w1 + w3 * w3;
#pragma unroll
        for (int mk = 4; mk < 32; mk <<= 1) {
            cs0 += __shfl_xor_sync(0xFFFFFFFF, cs0, mk);
            cs1 += __shfl_xor_sync(0xFFFFFFFF, cs1, mk);
            cq0 += __shfl_xor_sync(0xFFFFFFFF, cq0, mk);
            cq1 += __shfl_xor_sync(0xFFFFFFFF, cq1, mk);
        }
        if (gid == 0) {
            atomicAdd(&sums_out[col], cs0);
            atomicAdd(&sums_out[CC + col], cq0);
            atomicAdd(&sums_out[col + 1], cs1);
            atomicAdd(&sums_out[CC + col + 1], cq1);
        }
    }
}

// ---------------- mma.sync flash attention (BQ=128, cp.async double-buffered K/V) ----
#define EXP2_SCALE 0.25503480f
#define QK_STRIDE 40
#define VT_STRIDE 136

__global__ __launch_bounds__(256, 1) void mma_attn(const __nv_bfloat16* __restrict__ qb,
        const __nv_bfloat16* __restrict__ kb, const __nv_bfloat16* __restrict__ vtb,
        float* __restrict__ out) {
    __shared__ uint16_t Qs[128 * QK_STRIDE];
    __shared__ uint16_t Ks[2][128 * QK_STRIDE];
    __shared__ uint16_t Vts[2][32 * VT_STRIDE];

    const int tid = threadIdx.x;
    const int wid = tid >> 5, lane = tid & 31;
    const int gid = lane >> 2, tig = lane & 3;
    const int h = blockIdx.y;
    const int qbase = blockIdx.x * 128;
    const int r0 = wid * 16;

    const uint16_t* Qg = (const uint16_t*)(qb + ((long)h * NN + qbase) * 32);
#pragma unroll
    for (int it = 0; it < 2; it++) {
        int i = tid + it * 256;
        int row = i >> 2, seg = i & 3;
        *(uint4*)&Qs[row * QK_STRIDE + seg * 8] = *(const uint4*)&Qg[row * 32 + seg * 8];
    }

    auto pre_kv = [&](int st, int kb0) {
        const uint16_t* Kg = (const uint16_t*)(kb + ((long)h * NN + kb0) * 32);
#pragma unroll
        for (int it = 0; it < 2; it++) {
            int i = tid + it * 256;
            int row = i >> 2, seg = i & 3;
            CP16(smem_u32(&Ks[st][row * QK_STRIDE + seg * 8]), &Kg[row * 32 + seg * 8]);
        }
        const uint16_t* Vg = (const uint16_t*)(vtb + ((long)h * 32) * NN + kb0);
#pragma unroll
        for (int it = 0; it < 2; it++) {
            int i = tid + it * 256;
            int d = i >> 4, seg = i & 15;
            CP16(smem_u32(&Vts[st][d * VT_STRIDE + seg * 8]), &Vg[(long)d * NN + seg * 8]);
        }
    };

    pre_kv(0, 0);
    CP_COMMIT();
    __syncthreads();

    uint32_t aq[2][4];
#pragma unroll
    for (int t = 0; t < 2; t++) {
        int k = t * 16 + tig * 2;
        aq[t][0] = *(const uint32_t*)&Qs[(r0 + gid    ) * QK_STRIDE + k    ];
        aq[t][1] = *(const uint32_t*)&Qs[(r0 + gid + 8) * QK_STRIDE + k    ];
        aq[t][2] = *(const uint32_t*)&Qs[(r0 + gid    ) * QK_STRIDE + k + 8];
        aq[t][3] = *(const uint32_t*)&Qs[(r0 + gid + 8) * QK_STRIDE + k + 8];
    }

    float oacc[4][4] = {};
    float rs0 = 0.f, rs1 = 0.f;

    for (int kt = 0; kt < NN / 128; kt++) {
        const int st = kt & 1;
        if (kt + 1 < NN / 128) {
            pre_kv(st ^ 1, (kt + 1) * 128);
            CP_COMMIT();
            CP_WAIT1();
        } else {
            CP_WAIT0();
        }
        __syncthreads();

        float sacc[16][4];
#pragma unroll
        for (int j = 0; j < 16; j++) { sacc[j][0] = sacc[j][1] = sacc[j][2] = sacc[j][3] = 0.f; }
#pragma unroll
        for (int j = 0; j < 16; j++) {
#pragma unroll
            for (int t = 0; t < 2; t++) {
                int k = t * 16 + tig * 2;
                uint32_t b0 = *(const uint32_t*)&Ks[st][(8 * j + gid) * QK_STRIDE + k    ];
                uint32_t b1 = *(const uint32_t*)&Ks[st][(8 * j + gid) * QK_STRIDE + k + 8];
                mma_bf16(sacc[j], aq[t][0], aq[t][1], aq[t][2], aq[t][3], b0, b1);
            }
        }

        uint32_t pf[16][2];
#pragma unroll
        for (int j = 0; j < 16; j++) {
            float p0 = fast_exp2(sacc[j][0] * EXP2_SCALE);
            float p1 = fast_exp2(sacc[j][1] * EXP2_SCALE);
            float p2 = fast_exp2(sacc[j][2] * EXP2_SCALE);
            float p3 = fast_exp2(sacc[j][3] * EXP2_SCALE);
            rs0 += p0 + p1;
            rs1 += p2 + p3;
            pf[j][0] = pack_bf16(p0, p1);
            pf[j][1] = pack_bf16(p2, p3);
        }

#pragma unroll
        for (int t = 0; t < 8; t++) {
            uint32_t a0 = pf[2 * t][0], a1 = pf[2 * t][1];
            uint32_t a2 = pf[2 * t + 1][0], a3 = pf[2 * t + 1][1];
            int k = t * 16 + tig * 2;
#pragma unroll
            for (int n = 0; n < 4; n++) {
                uint32_t b0 = *(const uint32_t*)&Vts[st][(8 * n + gid) * VT_STRIDE + k    ];
                uint32_t b1 = *(const uint32_t*)&Vts[st][(8 * n + gid) * VT_STRIDE + k + 8];
                mma_bf16(oacc[n], a0, a1, a2, a3, b0, b1);
            }
        }
        __syncthreads();
    }

    rs0 += __shfl_xor_sync(0xFFFFFFFF, rs0, 1);
    rs0 += __shfl_xor_sync(0xFFFFFFFF, rs0, 2);
    rs1 += __shfl_xor_sync(0xFFFFFFFF, rs1, 1);
    rs1 += __shfl_xor_sync(0xFFFFFFFF, rs1, 2);
    float inv0 = 1.f / rs0, inv1 = 1.f / rs1;

    int rowA = qbase + r0 + gid, rowB = rowA + 8;
    float* poA = out + (long)rowA * CC + h * 32 + tig * 2;
    float* poB = out + (long)rowB * CC + h * 32 + tig * 2;
#pragma unroll
    for (int n = 0; n < 4; n++) {
        *(float2*)(poA + n * 8) = make_float2(oacc[n][0] * inv0, oacc[n][1] * inv0);
        *(float2*)(poB + n * 8) = make_float2(oacc[n][2] * inv1, oacc[n][3] * inv1);
    }
}

// ---------------- head MLP with inline final BN affine ----------------
__global__ __launch_bounds__(256) void head_warp(const float* __restrict__ u,
        const float* __restrict__ sums, const float* __restrict__ gw,
        const float* __restrict__ bw,
        const float* __restrict__ w1, const float* __restrict__ b1,
        const float* __restrict__ w2, const float* __restrict__ b2,
        const float* __restrict__ w3, const float* __restrict__ b3,
        float* __restrict__ out) {
    __shared__ float y1s[8][64];
    __shared__ float y2s[8][32];
    int tid = threadIdx.x;
    int wid = tid >> 5, lane = tid & 31;
    int n = blockIdx.x * 8 + wid;

    float4 uv = *(const float4*)&u[(long)n * 128 + lane * 4];
    float xv4[4] = {uv.x, uv.y, uv.z, uv.w};
#pragma unroll
    for (int k = 0; k < 4; k++) {
        int c = lane * 4 + k;
        float m = sums[c] * (1.f / NN);
        float var = sums[CC + c] * (1.f / NN) - m * m;
        float sc = rsqrtf(var + BN_EPS) * gw[c];
        xv4[k] = (xv4[k] - m) * sc + bw[c];
    }
    float4 xv = make_float4(xv4[0], xv4[1], xv4[2], xv4[3]);

    for (int o = 0; o < 64; o++) {
        float4 wv = *(const float4*)&w1[o * 128 + lane * 4];
        float p = xv.x * wv.x + xv.y * wv.y + xv.z * wv.z + xv.w * wv.w;
#pragma unroll
        for (int mk = 16; mk > 0; mk >>= 1) p += __shfl_xor_sync(0xFFFFFFFF, p, mk);
        if (lane == 0) y1s[wid][o] = fmaxf(p + b1[o], 0.f);
    }
    __syncwarp();
    float ya = y1s[wid][lane * 2], yb = y1s[wid][lane * 2 + 1];
    for (int o = 0; o < 32; o++) {
        float2 wv = *(const float2*)&w2[o * 64 + lane * 2];
        float p = ya * wv.x + yb * wv.y;
#pragma unroll
        for (int mk = 16; mk > 0; mk >>= 1) p += __shfl_xor_sync(0xFFFFFFFF, p, mk);
        if (lane == 0) y2s[wid][o] = fmaxf(p + b2[o], 0.f);
    }
    __syncwarp();
    float p = y2s[wid][lane] * w3[lane];
#pragma unroll
    for (int mk = 16; mk > 0; mk >>= 1) p += __shfl_xor_sync(0xFFFFFFFF, p, mk);
    if (lane == 0) out[n] = p + b3[0];
}

// ---------------- host orchestration ----------------
static __nv_bfloat16 *s_whi, *s_wlo;

extern "C" void kernel_launch(void* const* d_in, const int* in_sizes, int n_in,
                              void* d_out, int out_size) {
    const float* x_in      = (const float*)d_in[0];
    const int*   edge      = (const int*)  d_in[1];
    const float* gin_w1    = (const float*)d_in[2];
    const float* gin_b1    = (const float*)d_in[3];
    const float* gin_w2    = (const float*)d_in[4];
    const float* gin_b2    = (const float*)d_in[5];
    const float* attn_in_w = (const float*)d_in[6];
    const float* attn_in_b = (const float*)d_in[7];
    const float* attn_o_w  = (const float*)d_in[8];
    const float* attn_o_b  = (const float*)d_in[9];
    const float* n1_g = (const float*)d_in[10];
    const float* n1_b = (const float*)d_in[11];
    const float* n2_g = (const float*)d_in[12];
    const float* n2_b = (const float*)d_in[13];
    const float* n3_g = (const float*)d_in[14];
    const float* n3_b = (const float*)d_in[15];
    const float* mlp_w1 = (const float*)d_in[16];
    const float* mlp_b1 = (const float*)d_in[17];
    const float* mlp_w2 = (const float*)d_in[18];
    const float* mlp_b2 = (const float*)d_in[19];
    const float* hw1 = (const float*)d_in[20];
    const float* hb1 = (const float*)d_in[21];
    const float* hw2 = (const float*)d_in[22];
    const float* hb2 = (const float*)d_in[23];
    const float* hw3 = (const float*)d_in[24];
    const float* hb3 = (const float*)d_in[25];
    float* out = (float*)d_out;

    int E = in_sizes[1] / 2;

    float *p_x, *p_agg, *p_t1, *p_t2, *p_h1, *p_h2, *p_sums;
    int *p_deg;
    __nv_bfloat16 *p_qb, *p_kb, *p_vtb;
    cudaGetSymbolAddress((void**)&p_x,  g_x);
    cudaGetSymbolAddress((void**)&p_agg, g_agg);
    cudaGetSymbolAddress((void**)&p_t1, g_t1);
    cudaGetSymbolAddress((void**)&p_t2, g_t2);
    cudaGetSymbolAddress((void**)&p_h1, g_h1);
    cudaGetSymbolAddress((void**)&p_h2, g_h2);
    cudaGetSymbolAddress((void**)&p_sums, g_bnsums);
    cudaGetSymbolAddress((void**)&p_deg, g_deg);
    cudaGetSymbolAddress((void**)&p_qb, g_qb);
    cudaGetSymbolAddress((void**)&p_kb, g_kb);
    cudaGetSymbolAddress((void**)&p_vtb, g_vtb);
    cudaGetSymbolAddress((void**)&s_whi, g_whi);
    cudaGetSymbolAddress((void**)&s_wlo, g_wlo);

    conv_w<<<(WTOTAL + 255) / 256, 256>>>(gin_w1, gin_w2, attn_in_w, attn_o_w, mlp_w1, mlp_w2);
    cudaMemsetAsync(p_sums, 0, 12 * 2 * CC * sizeof(float));
    cudaMemsetAsync(p_deg, 0, (NN + 1) * sizeof(int));
    hist_kernel<<<(E + 255) / 256, 256>>>(edge, E);
    scan_kernel<<<1, 1024>>>();
    fill_kernel<<<(E + 255) / 256, 256>>>(edge, E);

    for (int i = 0; i < LL; i++) {
        const float* xcur = (i == 0) ? x_in : p_x;
        const float* gb1 = gin_b1 + (long)i * CC;
        const float* gb2 = gin_b2 + (long)i * CC;
        const float* aib = attn_in_b + (long)i * 3 * CC;
        const float* aob = attn_o_b + (long)i * CC;
        const float* mb1 = mlp_b1 + (long)i * 2 * CC;
        const float* mb2 = mlp_b2 + (long)i * CC;
        float* s1 = p_sums + (3 * i + 0) * 2 * CC;
        float* s2 = p_sums + (3 * i + 1) * 2 * CC;
        float* s3 = p_sums + (3 * i + 2) * 2 * CC;

        // ---- layer entry: gather (layer 0) or fused BN+gather (layers 1..3) ----
        if (i == 0) {
            gather_kernel<<<NN / 8, 256>>>(x_in, p_t2);
        } else {
            float* s3p = p_sums + (3 * (i - 1) + 2) * 2 * CC;
            bn_gather<<<NN / 8, 256>>>(p_agg, s3p, n3_g + (i - 1) * CC, n3_b + (i - 1) * CC,
                                       p_x, p_t2);
        }

        // ---- fused qkv || gin1 (agg in p_t2) ----
        gemm_qkv_gin1<<<512, 256>>>(xcur,
            s_whi + WOFF_AIN + i * 3 * CC * CC, s_wlo + WOFF_AIN + i * 3 * CC * CC, aib,
            p_qb, p_kb, p_vtb,
            p_t2, s_whi + WOFF_GIN1 + i * CC * CC, s_wlo + WOFF_GIN1 + i * CC * CC, gb1, p_t1);
        mma_attn<<<dim3(NN / 128, HEADS), 256>>>(p_qb, p_kb, p_vtb, p_agg);

        // ---- fused gin2 (t1->h1,s1) || aout (agg->h2,s2) ----
        gemm_dual_e3<<<256, 256>>>(
            p_t1, s_whi + WOFF_GIN2 + i * CC * CC, s_wlo + WOFF_GIN2 + i * CC * CC, gb2, p_h1, s1,
            p_agg, s_whi + WOFF_AOUT + i * CC * CC, s_wlo + WOFF_AOUT + i * CC * CC, aob, p_h2, s2,
            xcur);

        // ---- MLP ----
        gemm_tc<2, 1><<<dim3(4, 64), 256>>>(p_h1, p_h2,
            s_whi + WOFF_MW1 + i * 2 * CC * CC, s_wlo + WOFF_MW1 + i * 2 * CC * CC, mb1, p_t1,
            nullptr, nullptr, nullptr, nullptr, nullptr,
            s1, n1_g + i * CC, n1_b + i * CC, s2, n2_g + i * CC, n2_b + i * CC,
            p_t2, NN, 2 * CC, CC);
        gemm_tc<0, 3><<<dim3(2, 64), 256>>>(p_t1, nullptr,
            s_whi + WOFF_MW2 + i * 2 * CC * CC, s_wlo + WOFF_MW2 + i * 2 * CC * CC, mb2, p_agg,
            nullptr, nullptr, nullptr, p_t2, s3,
            nullptr, nullptr, nullptr, nullptr, nullptr, nullptr, nullptr, NN, CC, 2 * CC);
    }

    // ---- head with inline final BN affine ----
    head_warp<<<NN / 8, 256>>>(p_agg, p_sums + 11 * 2 * CC, n3_g + 3 * CC, n3_b + 3 * CC,
                               hw1, hb1, hw2, hb2, hw3, hb3, out);
}